// round 2
// baseline (speedup 1.0000x reference)
#include <cuda_runtime.h>
#include <cuda_bf16.h>
#include <math.h>

// Problem constants
#define B_  2
#define S_  2048
#define E_  1024
#define H_  1024
#define NH_ 8
#define HD_ 128
#define L_  2
#define V_  32000
#define CS_ 128
#define NC_ 16
#define TOPK_ 8
#define R_  (B_ * S_)       // 4096 rows
#define FF_ (4 * H_)        // 4096
#define HH_ (H_ / 2)        // 512
#define SCALE_ 0.08838834764831843f  // 1/sqrt(128)

// ---------------- scratch (device globals; no allocations allowed) ----------------
__device__ float g_h  [R_ * H_];      // hidden state
__device__ float g_x  [R_ * H_];      // emb / qe / ln output (reused)
__device__ float g_q  [R_ * H_];
__device__ float g_k  [R_ * H_];
__device__ float g_v  [R_ * H_];
__device__ float g_ao [R_ * H_];
__device__ float g_mid[R_ * FF_];     // 64MB: qe1 / ffn mid
__device__ float g_avg [B_ * NC_ * H_];
__device__ float g_cmid[B_ * NC_ * HH_];
__device__ float g_cenc[B_ * NC_ * H_];
__device__ unsigned g_sel[R_];

// ---------------- helpers ----------------
__device__ __forceinline__ float warpSum(float v) {
    #pragma unroll
    for (int o = 16; o > 0; o >>= 1) v += __shfl_xor_sync(0xffffffffu, v, o);
    return v;
}
__device__ __forceinline__ float warpMax(float v) {
    #pragma unroll
    for (int o = 16; o > 0; o >>= 1) v = fmaxf(v, __shfl_xor_sync(0xffffffffu, v, o));
    return v;
}

// ---------------- embedding ----------------
__global__ void embed_kernel(const int* __restrict__ ids, const float* __restrict__ tok,
                             const float* __restrict__ pos, float* __restrict__ out) {
    int r = blockIdx.x;
    int sp = r % S_;
    int id = ids[r];
    const float* t = tok + (size_t)id * E_;
    const float* p = pos + (size_t)sp * E_;
    float* o = out + (size_t)r * E_;
    for (int e = threadIdx.x; e < E_; e += blockDim.x) o[e] = t[e] + p[e];
}

// ---------------- generic SGEMM: C = act(A@W + bias) [+ res] ----------------
// A:[M,K] row-major, W:[K,N] row-major. Requires K%16==0, N%128==0. M guarded.
// act: 0=none, 1=relu, 2=gelu(exact)
__global__ void __launch_bounds__(256)
gemm_kernel(const float* __restrict__ A, const float* __restrict__ W,
            const float* __restrict__ bias, const float* __restrict__ res,
            float* __restrict__ C, int M, int K, int N, int act) {
    __shared__ float As[16][128];
    __shared__ float Bs[16][128];
    const int tid = threadIdx.x;
    const int tx = tid & 15, ty = tid >> 4;
    const int m0 = blockIdx.y * 128, n0 = blockIdx.x * 128;

    const int ar = tid >> 1;           // 0..127 (A row within tile)
    const int aseg = (tid & 1) * 8;    // 0 or 8 (k segment)
    const int br = tid >> 4;           // 0..15 (B row = k)
    const int bc = (tid & 15) * 4;     // 0..60

    float acc[8][8];
    #pragma unroll
    for (int i = 0; i < 8; i++)
        #pragma unroll
        for (int j = 0; j < 8; j++) acc[i][j] = 0.f;

    for (int k0 = 0; k0 < K; k0 += 16) {
        float4 a0, a1;
        if (m0 + ar < M) {
            const float* ap = A + (size_t)(m0 + ar) * K + k0 + aseg;
            a0 = *(const float4*)ap;
            a1 = *(const float4*)(ap + 4);
        } else {
            a0 = make_float4(0.f, 0.f, 0.f, 0.f);
            a1 = a0;
        }
        As[aseg + 0][ar] = a0.x; As[aseg + 1][ar] = a0.y;
        As[aseg + 2][ar] = a0.z; As[aseg + 3][ar] = a0.w;
        As[aseg + 4][ar] = a1.x; As[aseg + 5][ar] = a1.y;
        As[aseg + 6][ar] = a1.z; As[aseg + 7][ar] = a1.w;

        const float* bp = W + (size_t)(k0 + br) * N + n0;
        *(float4*)&Bs[br][bc]      = *(const float4*)(bp + bc);
        *(float4*)&Bs[br][bc + 64] = *(const float4*)(bp + bc + 64);
        __syncthreads();

        #pragma unroll
        for (int kk = 0; kk < 16; kk++) {
            float a[8], b[8];
            *(float4*)&a[0] = *(float4*)&As[kk][ty * 8];
            *(float4*)&a[4] = *(float4*)&As[kk][ty * 8 + 4];
            *(float4*)&b[0] = *(float4*)&Bs[kk][tx * 8];
            *(float4*)&b[4] = *(float4*)&Bs[kk][tx * 8 + 4];
            #pragma unroll
            for (int i = 0; i < 8; i++)
                #pragma unroll
                for (int j = 0; j < 8; j++) acc[i][j] += a[i] * b[j];
        }
        __syncthreads();
    }

    #pragma unroll
    for (int i = 0; i < 8; i++) {
        int row = m0 + ty * 8 + i;
        if (row >= M) break;
        size_t off = (size_t)row * N + n0 + tx * 8;
        #pragma unroll
        for (int j = 0; j < 8; j++) {
            float v = acc[i][j] + bias[n0 + tx * 8 + j];
            if (act == 1) v = fmaxf(v, 0.f);
            else if (act == 2) v = 0.5f * v * (1.f + erff(v * 0.7071067811865475f));
            if (res) v += res[off + j];
            C[off + j] = v;
        }
    }
}

// ---------------- chunk mean ----------------
__global__ void chunk_avg_kernel(const float* __restrict__ h, const int* __restrict__ ids,
                                 float* __restrict__ avg) {
    int c = blockIdx.x, b = blockIdx.y;
    __shared__ float msk[CS_];
    __shared__ float s_cnt;
    int tid = threadIdx.x;
    if (tid < CS_) msk[tid] = (ids[b * S_ + c * CS_ + tid] != 0) ? 1.f : 0.f;
    __syncthreads();
    if (tid == 0) {
        float cn = 0.f;
        for (int p = 0; p < CS_; p++) cn += msk[p];
        s_cnt = cn;
    }
    __syncthreads();
    float inv = 1.f / (s_cnt + 1e-10f);
    for (int d = tid; d < H_; d += blockDim.x) {
        float s = 0.f;
        for (int p = 0; p < CS_; p++)
            s += h[(size_t)(b * S_ + c * CS_ + p) * H_ + d] * msk[p];
        avg[(size_t)(b * NC_ + c) * H_ + d] = s * inv;
    }
}

// ---------------- cscores + top-k chunk selection ----------------
__global__ void __launch_bounds__(512)
topk_kernel(const float* __restrict__ qe, const float* __restrict__ cenc,
            unsigned* __restrict__ sel) {
    int s = blockIdx.x, b = blockIdx.y;
    int tid = threadIdx.x, warp = tid >> 5, lane = tid & 31;
    __shared__ float sc[NC_];
    const float* q = qe + (size_t)(b * S_ + s) * H_;
    const float* c = cenc + (size_t)(b * NC_ + warp) * H_;
    float d = 0.f;
    for (int e = lane; e < H_; e += 32) d += q[e] * c[e];
    d = warpSum(d);
    if (lane == 0) sc[warp] = d;
    __syncthreads();
    if (tid == 0) {
        unsigned chosen = 0;
        for (int t = 0; t < TOPK_; t++) {
            float best = -INFINITY;
            int bi = 0;
            for (int cc = 0; cc < NC_; cc++)
                if (!((chosen >> cc) & 1u) && sc[cc] > best) { best = sc[cc]; bi = cc; }
            chosen |= 1u << bi;
        }
        sel[b * S_ + s] = chosen;
    }
}

// ---------------- LayerNorm ----------------
__global__ void ln_kernel(const float* __restrict__ x, const float* __restrict__ g,
                          const float* __restrict__ bt, float* __restrict__ y) {
    int r = blockIdx.x;
    int tid = threadIdx.x, warp = tid >> 5, lane = tid & 31;
    const float* xr = x + (size_t)r * H_;
    float s = 0.f, sq = 0.f;
    for (int e = tid; e < H_; e += 256) {
        float v = xr[e];
        s += v; sq += v * v;
    }
    __shared__ float rs[8], rq[8];
    __shared__ float s_mean, s_rstd;
    s = warpSum(s); sq = warpSum(sq);
    if (lane == 0) { rs[warp] = s; rq[warp] = sq; }
    __syncthreads();
    if (tid == 0) {
        float S = 0.f, Q = 0.f;
        for (int w = 0; w < 8; w++) { S += rs[w]; Q += rq[w]; }
        float mean = S / (float)H_;
        float var = Q / (float)H_ - mean * mean;
        s_mean = mean;
        s_rstd = rsqrtf(var + 1e-5f);
    }
    __syncthreads();
    float mean = s_mean, rstd = s_rstd;
    float* yr = y + (size_t)r * H_;
    for (int e = tid; e < H_; e += 256)
        yr[e] = (xr[e] - mean) * rstd * g[e] + bt[e];
}

// ---------------- sparse chunk attention (one block per (b, head, query)) ----------------
__global__ void __launch_bounds__(128)
attn_kernel(const float* __restrict__ q, const float* __restrict__ k,
            const float* __restrict__ v, const unsigned* __restrict__ sel,
            const int* __restrict__ ids, float* __restrict__ out) {
    int s = blockIdx.x, head = blockIdx.y, b = blockIdx.z;
    int tid = threadIdx.x, warp = tid >> 5, lane = tid & 31;
    __shared__ float qv[HD_];
    __shared__ float sc[CS_];
    __shared__ float red[4];
    __shared__ float bcast[2];

    size_t qoff = (size_t)(b * S_ + s) * H_ + head * HD_;
    qv[tid] = q[qoff + tid];
    __syncthreads();
    float4 q4 = *(const float4*)&qv[lane * 4];

    unsigned msk = sel[b * S_ + s];
    float m = -INFINITY, l = 0.f, acc = 0.f;

    for (int c = 0; c < NC_; c++) {
        if (!((msk >> c) & 1u)) continue;
        int j0 = c * CS_;
        // scores: 4 warps x 32 keys each
        for (int kk = 0; kk < 32; kk++) {
            int j = j0 + warp * 32 + kk;
            const float4 kv = *(const float4*)&k[(size_t)(b * S_ + j) * H_ + head * HD_ + lane * 4];
            float d = q4.x * kv.x + q4.y * kv.y + q4.z * kv.z + q4.w * kv.w;
            d = warpSum(d);
            if (lane == 0) sc[warp * 32 + kk] = d;
        }
        __syncthreads();
        float scv = sc[tid] * SCALE_;
        if (ids[b * S_ + j0 + tid] == 0) scv = -INFINITY;
        float wm = warpMax(scv);
        if (lane == 0) red[warp] = wm;
        __syncthreads();
        if (tid == 0) {
            float mm = red[0];
            mm = fmaxf(mm, red[1]); mm = fmaxf(mm, red[2]); mm = fmaxf(mm, red[3]);
            bcast[0] = mm;
        }
        __syncthreads();
        float cmax = bcast[0];
        float newm = fmaxf(m, cmax);
        float p = expf(scv - newm);
        sc[tid] = p;
        float ws = warpSum(p);
        if (lane == 0) red[warp] = ws;
        __syncthreads();
        if (tid == 0) bcast[1] = red[0] + red[1] + red[2] + red[3];
        __syncthreads();
        float csum = bcast[1];
        float f = expf(m - newm);
        l = l * f + csum;
        acc *= f;
        const float* vb = v + (size_t)(b * S_ + j0) * H_ + head * HD_ + tid;
        for (int j = 0; j < CS_; j++) acc += sc[j] * vb[(size_t)j * H_];
        m = newm;
        __syncthreads();
    }
    out[qoff + tid] = acc / l;
}

// ---------------- host-side orchestration ----------------
static inline void launch_gemm(const float* A, const float* W, const float* bias,
                               const float* res, float* C, int M, int K, int N, int act) {
    dim3 grid(N / 128, (M + 127) / 128);
    gemm_kernel<<<grid, 256>>>(A, W, bias, res, C, M, K, N, act);
}

extern "C" void kernel_launch(void* const* d_in, const int* in_sizes, int n_in,
                              void* d_out, int out_size) {
    const int*   ids     = (const int*)  d_in[0];
    const float* tok_emb = (const float*)d_in[1];
    const float* pos_emb = (const float*)d_in[2];
    const float* in_w    = (const float*)d_in[3];
    const float* in_b    = (const float*)d_in[4];
    const float* ch_w1   = (const float*)d_in[5];
    const float* ch_b1   = (const float*)d_in[6];
    const float* ch_w2   = (const float*)d_in[7];
    const float* ch_b2   = (const float*)d_in[8];
    const float* qe_w1   = (const float*)d_in[9];
    const float* qe_b1   = (const float*)d_in[10];
    const float* qe_w2   = (const float*)d_in[11];
    const float* qe_b2   = (const float*)d_in[12];
    const float* q_w     = (const float*)d_in[13];
    const float* q_b     = (const float*)d_in[14];
    const float* k_w     = (const float*)d_in[15];
    const float* k_b     = (const float*)d_in[16];
    const float* v_w     = (const float*)d_in[17];
    const float* v_b     = (const float*)d_in[18];
    const float* o_w     = (const float*)d_in[19];
    const float* o_b     = (const float*)d_in[20];
    const float* f_w1    = (const float*)d_in[21];
    const float* f_b1    = (const float*)d_in[22];
    const float* f_w2    = (const float*)d_in[23];
    const float* f_b2    = (const float*)d_in[24];
    const float* ln1_g   = (const float*)d_in[25];
    const float* ln1_b   = (const float*)d_in[26];
    const float* ln2_g   = (const float*)d_in[27];
    const float* ln2_b   = (const float*)d_in[28];
    const float* out_w   = (const float*)d_in[29];
    const float* out_b   = (const float*)d_in[30];
    float* logits = (float*)d_out;

    float *h, *x, *q, *k, *v, *ao, *mid, *avg, *cmid, *cenc;
    unsigned* sel;
    cudaGetSymbolAddress((void**)&h,   g_h);
    cudaGetSymbolAddress((void**)&x,   g_x);
    cudaGetSymbolAddress((void**)&q,   g_q);
    cudaGetSymbolAddress((void**)&k,   g_k);
    cudaGetSymbolAddress((void**)&v,   g_v);
    cudaGetSymbolAddress((void**)&ao,  g_ao);
    cudaGetSymbolAddress((void**)&mid, g_mid);
    cudaGetSymbolAddress((void**)&avg, g_avg);
    cudaGetSymbolAddress((void**)&cmid,g_cmid);
    cudaGetSymbolAddress((void**)&cenc,g_cenc);
    cudaGetSymbolAddress((void**)&sel, g_sel);

    // embeddings -> x; input projection -> h
    embed_kernel<<<R_, 256>>>(ids, tok_emb, pos_emb, x);
    launch_gemm(x, in_w, in_b, nullptr, h, R_, E_, H_, 0);

    // chunk encodings
    chunk_avg_kernel<<<dim3(NC_, B_), 256>>>(h, ids, avg);
    launch_gemm(avg,  ch_w1, ch_b1, nullptr, cmid, B_ * NC_, H_,  HH_, 1);
    launch_gemm(cmid, ch_w2, ch_b2, nullptr, cenc, B_ * NC_, HH_, H_,  0);

    for (int i = 0; i < L_; i++) {
        // query encodings + chunk selection
        launch_gemm(h,   qe_w1, qe_b1, nullptr, mid, R_, H_,  HH_, 1);
        launch_gemm(mid, qe_w2, qe_b2, nullptr, x,   R_, HH_, H_,  0);
        topk_kernel<<<dim3(S_, B_), 512>>>(x, cenc, sel);

        // attention block
        ln_kernel<<<R_, 256>>>(h, ln1_g + i * H_, ln1_b + i * H_, x);
        launch_gemm(x, q_w + (size_t)i * H_ * H_, q_b + i * H_, nullptr, q, R_, H_, H_, 0);
        launch_gemm(x, k_w + (size_t)i * H_ * H_, k_b + i * H_, nullptr, k, R_, H_, H_, 0);
        launch_gemm(x, v_w + (size_t)i * H_ * H_, v_b + i * H_, nullptr, v, R_, H_, H_, 0);
        attn_kernel<<<dim3(S_, NH_, B_), 128>>>(q, k, v, sel, ids, ao);
        launch_gemm(ao, o_w + (size_t)i * H_ * H_, o_b + i * H_, h, h, R_, H_, H_, 0);

        // FFN block
        ln_kernel<<<R_, 256>>>(h, ln2_g + i * H_, ln2_b + i * H_, x);
        launch_gemm(x,   f_w1 + (size_t)i * H_ * FF_, f_b1 + i * FF_, nullptr, mid, R_, H_,  FF_, 2);
        launch_gemm(mid, f_w2 + (size_t)i * FF_ * H_, f_b2 + i * H_,  h,       h,   R_, FF_, H_,  0);
    }

    // output logits
    launch_gemm(h, out_w, out_b, nullptr, logits, R_, H_, V_, 0);
}

// round 5
// speedup vs baseline: 1.4333x; 1.4333x over previous
#include <cuda_runtime.h>
#include <cuda_bf16.h>
#include <math.h>
#include <stdint.h>

#define B_  2
#define S_  2048
#define E_  1024
#define H_  1024
#define NH_ 8
#define HD_ 128
#define L_  2
#define V_  32000
#define CS_ 128
#define NC_ 16
#define TOPK_ 8
#define R_  (B_ * S_)
#define FF_ (4 * H_)
#define HH_ (H_ / 2)
#define SCALE_ 0.08838834764831843f

// ---- scratch ----
__device__ __align__(16) float g_h  [R_ * H_];
__device__ __align__(16) float g_x  [R_ * H_];
__device__ __align__(16) float g_q  [R_ * H_];
__device__ __align__(16) float g_k  [R_ * H_];
__device__ __align__(16) float g_v  [R_ * H_];
__device__ __align__(16) float g_ao [R_ * H_];
__device__ __align__(16) float g_mid[R_ * FF_];
__device__ __align__(16) float g_avg [B_ * NC_ * H_];
__device__ __align__(16) float g_cmid[B_ * NC_ * HH_];
__device__ __align__(16) float g_cenc[B_ * NC_ * H_];
__device__ unsigned g_sel[R_];
// bf16x3 splits: A (activations) and W^T (weights)
__device__ __align__(16) __nv_bfloat16 g_A0[4096 * 4096];
__device__ __align__(16) __nv_bfloat16 g_A1[4096 * 4096];
__device__ __align__(16) __nv_bfloat16 g_A2[4096 * 4096];
__device__ __align__(16) __nv_bfloat16 g_W0[32000 * 1024];
__device__ __align__(16) __nv_bfloat16 g_W1[32000 * 1024];
__device__ __align__(16) __nv_bfloat16 g_W2[32000 * 1024];

// ---- helpers ----
__device__ __forceinline__ float warpSum(float v) {
    #pragma unroll
    for (int o = 16; o > 0; o >>= 1) v += __shfl_xor_sync(0xffffffffu, v, o);
    return v;
}
__device__ __forceinline__ float warpMax(float v) {
    #pragma unroll
    for (int o = 16; o > 0; o >>= 1) v = fmaxf(v, __shfl_xor_sync(0xffffffffu, v, o));
    return v;
}
__device__ __forceinline__ uint32_t smem_u32(const void* p) {
    uint32_t a;
    asm("{ .reg .u64 t; cvta.to.shared.u64 t, %1; cvt.u32.u64 %0, t; }" : "=r"(a) : "l"(p));
    return a;
}
#define CPA(d, s) asm volatile("cp.async.cg.shared.global [%0], [%1], 16;" :: "r"(d), "l"(s))
#define CPA_COMMIT() asm volatile("cp.async.commit_group;" ::: "memory")
#define CPA_WAIT0()  asm volatile("cp.async.wait_group 0;" ::: "memory")

#define LDSM_X4(r0, r1, r2, r3, a) \
    asm volatile("ldmatrix.sync.aligned.m8n8.x4.shared.b16 {%0,%1,%2,%3}, [%4];" \
        : "=r"(r0), "=r"(r1), "=r"(r2), "=r"(r3) : "r"(a))

#define MMA_BF16(c, a, b) \
    asm volatile("mma.sync.aligned.m16n8k16.row.col.f32.bf16.bf16.f32 " \
        "{%0,%1,%2,%3}, {%4,%5,%6,%7}, {%8,%9}, {%0,%1,%2,%3};" \
        : "+f"((c)[0]), "+f"((c)[1]), "+f"((c)[2]), "+f"((c)[3]) \
        : "r"((a)[0]), "r"((a)[1]), "r"((a)[2]), "r"((a)[3]), "r"((b)[0]), "r"((b)[1]))

// ---- embedding ----
__global__ void embed_kernel(const int* __restrict__ ids, const float* __restrict__ tok,
                             const float* __restrict__ pos, float* __restrict__ out) {
    int r = blockIdx.x;
    int id = ids[r];
    const float* t = tok + (size_t)id * E_;
    const float* p = pos + (size_t)(r % S_) * E_;
    float* o = out + (size_t)r * E_;
    for (int e = threadIdx.x; e < E_; e += blockDim.x) o[e] = t[e] + p[e];
}

// ---- fp32 -> 3-way bf16 split ----
__global__ void cvt_split3_kernel(const float* __restrict__ a, __nv_bfloat16* __restrict__ o0,
                                  __nv_bfloat16* __restrict__ o1, __nv_bfloat16* __restrict__ o2,
                                  int n) {
    int i = (blockIdx.x * blockDim.x + threadIdx.x) * 4;
    if (i >= n) return;
    float4 v = *(const float4*)(a + i);
    union { __nv_bfloat16 b[4]; uint2 u; } U0, U1, U2;
    float f[4] = {v.x, v.y, v.z, v.w};
    #pragma unroll
    for (int j = 0; j < 4; j++) {
        __nv_bfloat16 b0 = __float2bfloat16_rn(f[j]);
        float r1 = f[j] - __bfloat162float(b0);
        __nv_bfloat16 b1 = __float2bfloat16_rn(r1);
        float r2 = r1 - __bfloat162float(b1);
        U0.b[j] = b0; U1.b[j] = b1; U2.b[j] = __float2bfloat16_rn(r2);
    }
    *(uint2*)(o0 + i) = U0.u;
    *(uint2*)(o1 + i) = U1.u;
    *(uint2*)(o2 + i) = U2.u;
}

// ---- fp32 W[K,N] -> 3-way split W^T[N,K] ----
__global__ void cvt_t3_kernel(const float* __restrict__ w, __nv_bfloat16* __restrict__ o0,
                              __nv_bfloat16* __restrict__ o1, __nv_bfloat16* __restrict__ o2,
                              int Kd, int Nd) {
    __shared__ float t[32][33];
    int n0 = blockIdx.x * 32, k0 = blockIdx.y * 32;
    int tx = threadIdx.x, ty = threadIdx.y;
    #pragma unroll
    for (int i = 0; i < 32; i += 8)
        t[ty + i][tx] = w[(size_t)(k0 + ty + i) * Nd + n0 + tx];
    __syncthreads();
    #pragma unroll
    for (int i = 0; i < 32; i += 8) {
        float v = t[tx][ty + i];
        __nv_bfloat16 b0 = __float2bfloat16_rn(v);
        float r1 = v - __bfloat162float(b0);
        __nv_bfloat16 b1 = __float2bfloat16_rn(r1);
        float r2 = r1 - __bfloat162float(b1);
        size_t o = (size_t)(n0 + ty + i) * Kd + k0 + tx;
        o0[o] = b0; o1[o] = b1; o2[o] = __float2bfloat16_rn(r2);
    }
}

// ---- HMMA bf16x3 GEMM: C = act(A@W + bias) [+res] ----
// NB=6: full fp32 emulation (6 products). NB=4: 3 products (~1e-5, output-only GEMMs).
// CTA 128x128, BK=32, 8 warps 32x64. A buffers at 0..(NA-1), B at NA..(NB-1).
#define SK 40
#define MAT_B (128 * SK * 2)        // 10240 B

template<int NB>
__global__ void __launch_bounds__(256)
gemm_tc_kernel(const __nv_bfloat16* __restrict__ A0, const __nv_bfloat16* __restrict__ A1,
               const __nv_bfloat16* __restrict__ A2,
               const __nv_bfloat16* __restrict__ B0, const __nv_bfloat16* __restrict__ B1,
               const __nv_bfloat16* __restrict__ B2,
               const float* __restrict__ bias, const float* __restrict__ res,
               float* __restrict__ C, int M, int K, int N, int act) {
    constexpr int NA = (NB == 6) ? 3 : 2;     // # A buffers
    constexpr int STG = NB * MAT_B;
    extern __shared__ char smem[];
    const uint32_t sb = smem_u32(smem);
    const int tid = threadIdx.x, lane = tid & 31;
    const int w = tid >> 5, wm = w & 3, wn = w >> 2;
    const int m0 = blockIdx.y * 128, n0 = blockIdx.x * 128;

    float c[2][8][4];
    #pragma unroll
    for (int i = 0; i < 2; i++)
        #pragma unroll
        for (int j = 0; j < 8; j++)
            #pragma unroll
            for (int e = 0; e < 4; e++) c[i][j][e] = 0.f;

    int rowi[2], segi[2], arowi[2];
    #pragma unroll
    for (int i = 0; i < 2; i++) {
        int idx = tid + i * 256;
        rowi[i] = idx >> 2;
        segi[i] = idx & 3;
        int ar = m0 + rowi[i];
        arowi[i] = ar < M ? ar : (M - 1);
    }

    auto issue_stage = [&](int kb, int st) {
        size_t gk = (size_t)kb * 32;
        #pragma unroll
        for (int i = 0; i < 2; i++) {
            uint32_t ds = sb + st * STG + (rowi[i] * SK + segi[i] * 8) * 2;
            size_t aoff = (size_t)arowi[i] * K + gk + segi[i] * 8;
            size_t boff = (size_t)(n0 + rowi[i]) * K + gk + segi[i] * 8;
            CPA(ds,              A0 + aoff);
            CPA(ds + MAT_B,      A1 + aoff);
            if (NB == 6) CPA(ds + 2 * MAT_B, A2 + aoff);
            CPA(ds + NA * MAT_B,       B0 + boff);
            CPA(ds + (NA + 1) * MAT_B, B1 + boff);
            if (NB == 6) CPA(ds + 5 * MAT_B, B2 + boff);
        }
        CPA_COMMIT();
    };

    const int nkb = K >> 5;
    issue_stage(0, 0);
    CPA_WAIT0();
    __syncthreads();

    const uint32_t a_off = ((wm * 32 + (lane & 15)) * SK + ((lane >> 4) << 3)) * 2;
    const uint32_t b_off = ((wn * 64 + (lane & 7) + ((lane >> 4) << 3)) * SK + (((lane >> 3) & 1) << 3)) * 2;

    for (int kb = 0; kb < nkb; kb++) {
        int st = kb & 1;
        if (kb + 1 < nkb) issue_stage(kb + 1, st ^ 1);
        uint32_t base = sb + st * STG;
        #pragma unroll
        for (int kk = 0; kk < 2; kk++) {
            uint32_t ka = base + a_off + kk * 32;
            uint32_t af[NA][2][4];
            #pragma unroll
            for (int s = 0; s < NA; s++) {
                LDSM_X4(af[s][0][0], af[s][0][1], af[s][0][2], af[s][0][3], ka + s * MAT_B);
                LDSM_X4(af[s][1][0], af[s][1][1], af[s][1][2], af[s][1][3], ka + s * MAT_B + 16 * SK * 2);
            }
            #pragma unroll
            for (int nt2 = 0; nt2 < 4; nt2++) {
                uint32_t kb2 = base + NA * MAT_B + b_off + kk * 32 + nt2 * 16 * SK * 2;
                uint32_t bf[NB - NA][4];
                #pragma unroll
                for (int s = 0; s < NB - NA; s++)
                    LDSM_X4(bf[s][0], bf[s][1], bf[s][2], bf[s][3], kb2 + s * MAT_B);
                #pragma unroll
                for (int half = 0; half < 2; half++) {
                    int nt = nt2 * 2 + half;
                    #pragma unroll
                    for (int mt = 0; mt < 2; mt++) {
                        MMA_BF16(c[mt][nt], af[0][mt], bf[0] + half * 2);   // a0 b0
                        MMA_BF16(c[mt][nt], af[0][mt], bf[1] + half * 2);   // a0 b1
                        MMA_BF16(c[mt][nt], af[1][mt], bf[0] + half * 2);   // a1 b0
                        if (NB == 6) {
                            MMA_BF16(c[mt][nt], af[1][mt], bf[1] + half * 2); // a1 b1
                            MMA_BF16(c[mt][nt], af[0][mt], bf[2] + half * 2); // a0 b2
                            MMA_BF16(c[mt][nt], af[2][mt], bf[0] + half * 2); // a2 b0
                        }
                    }
                }
            }
        }
        if (kb + 1 < nkb) CPA_WAIT0();
        __syncthreads();
    }

    const int grp = lane >> 2, tig = lane & 3;
    #pragma unroll
    for (int mt = 0; mt < 2; mt++) {
        #pragma unroll
        for (int nt = 0; nt < 8; nt++) {
            int col = n0 + wn * 64 + nt * 8 + tig * 2;
            float b0 = bias[col], b1 = bias[col + 1];
            #pragma unroll
            for (int hrow = 0; hrow < 2; hrow++) {
                int row = m0 + wm * 32 + mt * 16 + grp + hrow * 8;
                if (row >= M) continue;
                float vx = c[mt][nt][hrow * 2 + 0] + b0;
                float vy = c[mt][nt][hrow * 2 + 1] + b1;
                if (act == 1) {
                    vx = fmaxf(vx, 0.f); vy = fmaxf(vy, 0.f);
                } else if (act == 2) {
                    vx = 0.5f * vx * (1.f + erff(vx * 0.7071067811865475f));
                    vy = 0.5f * vy * (1.f + erff(vy * 0.7071067811865475f));
                }
                size_t off = (size_t)row * N + col;
                if (res) {
                    float2 r = *(const float2*)(res + off);
                    vx += r.x; vy += r.y;
                }
                float2 o; o.x = vx; o.y = vy;
                *(float2*)(C + off) = o;
            }
        }
    }
}

// ---- chunk mean ----
__global__ void chunk_avg_kernel(const float* __restrict__ h, const int* __restrict__ ids,
                                 float* __restrict__ avg) {
    int c = blockIdx.x, b = blockIdx.y;
    __shared__ float msk[CS_];
    __shared__ float s_cnt;
    int tid = threadIdx.x;
    if (tid < CS_) msk[tid] = (ids[b * S_ + c * CS_ + tid] != 0) ? 1.f : 0.f;
    __syncthreads();
    if (tid == 0) {
        float cn = 0.f;
        for (int p = 0; p < CS_; p++) cn += msk[p];
        s_cnt = cn;
    }
    __syncthreads();
    float inv = 1.f / (s_cnt + 1e-10f);
    for (int d = tid; d < H_; d += blockDim.x) {
        float s = 0.f;
        for (int p = 0; p < CS_; p++)
            s += h[(size_t)(b * S_ + c * CS_ + p) * H_ + d] * msk[p];
        avg[(size_t)(b * NC_ + c) * H_ + d] = s * inv;
    }
}

// ---- topk ----
__global__ void __launch_bounds__(512)
topk_kernel(const float* __restrict__ qe, const float* __restrict__ cenc,
            unsigned* __restrict__ sel) {
    int s = blockIdx.x, b = blockIdx.y;
    int tid = threadIdx.x, warp = tid >> 5, lane = tid & 31;
    __shared__ float sc[NC_];
    const float* q = qe + (size_t)(b * S_ + s) * H_;
    const float* c = cenc + (size_t)(b * NC_ + warp) * H_;
    float d = 0.f;
    for (int e = lane; e < H_; e += 32) d += q[e] * c[e];
    d = warpSum(d);
    if (lane == 0) sc[warp] = d;
    __syncthreads();
    if (tid == 0) {
        unsigned chosen = 0;
        for (int t = 0; t < TOPK_; t++) {
            float best = -INFINITY;
            int bi = 0;
            for (int cc = 0; cc < NC_; cc++)
                if (!((chosen >> cc) & 1u) && sc[cc] > best) { best = sc[cc]; bi = cc; }
            chosen |= 1u << bi;
        }
        sel[b * S_ + s] = chosen;
    }
}

// ---- LayerNorm ----
__global__ void ln_kernel(const float* __restrict__ x, const float* __restrict__ g,
                          const float* __restrict__ bt, float* __restrict__ y) {
    int r = blockIdx.x;
    int tid = threadIdx.x, warp = tid >> 5, lane = tid & 31;
    const float* xr = x + (size_t)r * H_;
    float s = 0.f, sq = 0.f;
    for (int e = tid; e < H_; e += 256) {
        float v = xr[e];
        s += v; sq += v * v;
    }
    __shared__ float rs[8], rq[8];
    __shared__ float s_mean, s_rstd;
    s = warpSum(s); sq = warpSum(sq);
    if (lane == 0) { rs[warp] = s; rq[warp] = sq; }
    __syncthreads();
    if (tid == 0) {
        float Sm = 0.f, Q = 0.f;
        for (int ww = 0; ww < 8; ww++) { Sm += rs[ww]; Q += rq[ww]; }
        float mean = Sm / (float)H_;
        float var = Q / (float)H_ - mean * mean;
        s_mean = mean;
        s_rstd = rsqrtf(var + 1e-5f);
    }
    __syncthreads();
    float mean = s_mean, rstd = s_rstd;
    float* yr = y + (size_t)r * H_;
    for (int e = tid; e < H_; e += 256)
        yr[e] = (xr[e] - mean) * rstd * g[e] + bt[e];
}

// ---- sparse chunk attention ----
__global__ void __launch_bounds__(128)
attn_kernel(const float* __restrict__ q, const float* __restrict__ k,
            const float* __restrict__ v, const unsigned* __restrict__ sel,
            const int* __restrict__ ids, float* __restrict__ out) {
    int s = blockIdx.x, head = blockIdx.y, b = blockIdx.z;
    int tid = threadIdx.x, warp = tid >> 5, lane = tid & 31;
    __shared__ float qv[HD_];
    __shared__ float sc[CS_];
    __shared__ float red[4];
    __shared__ float bcast[2];

    size_t qoff = (size_t)(b * S_ + s) * H_ + head * HD_;
    qv[tid] = q[qoff + tid];
    __syncthreads();
    float4 q4 = *(const float4*)&qv[lane * 4];

    unsigned msk = sel[b * S_ + s];
    float m = -INFINITY, l = 0.f, acc = 0.f;

    for (int c = 0; c < NC_; c++) {
        if (!((msk >> c) & 1u)) continue;
        int j0 = c * CS_;
        for (int kk = 0; kk < 32; kk++) {
            int j = j0 + warp * 32 + kk;
            const float4 kv = *(const float4*)&k[(size_t)(b * S_ + j) * H_ + head * HD_ + lane * 4];
            float d = q4.x * kv.x + q4.y * kv.y + q4.z * kv.z + q4.w * kv.w;
            d = warpSum(d);
            if (lane == 0) sc[warp * 32 + kk] = d;
        }
        __syncthreads();
        float scv = sc[tid] * SCALE_;
        if (ids[b * S_ + j0 + tid] == 0) scv = -INFINITY;
        float wm = warpMax(scv);
        if (lane == 0) red[warp] = wm;
        __syncthreads();
        if (tid == 0) bcast[0] = fmaxf(fmaxf(red[0], red[1]), fmaxf(red[2], red[3]));
        __syncthreads();
        float newm = fmaxf(m, bcast[0]);
        float p = expf(scv - newm);
        sc[tid] = p;
        float ws = warpSum(p);
        if (lane == 0) red[warp] = ws;
        __syncthreads();
        if (tid == 0) bcast[1] = red[0] + red[1] + red[2] + red[3];
        __syncthreads();
        float f = expf(m - newm);
        l = l * f + bcast[1];
        acc *= f;
        const float* vb = v + (size_t)(b * S_ + j0) * H_ + head * HD_ + tid;
        for (int j = 0; j < CS_; j++) acc += sc[j] * vb[(size_t)j * H_];
        m = newm;
        __syncthreads();
    }
    out[qoff + tid] = acc / l;
}

// ---- host ----
static __nv_bfloat16 *s_A0, *s_A1, *s_A2, *s_W0, *s_W1, *s_W2;
#define GSMEM4 (2 * 4 * MAT_B)
#define GSMEM6 (2 * 6 * MAT_B)

static inline void cvtA(const float* A, int n) {
    cvt_split3_kernel<<<(n / 4 + 255) / 256, 256>>>(A, s_A0, s_A1, s_A2, n);
}
static inline void run_gemm(const float* W, const float* bias, const float* res,
                            float* C, int M, int K, int N, int act, int hi) {
    cvt_t3_kernel<<<dim3(N / 32, K / 32), dim3(32, 8)>>>(W, s_W0, s_W1, s_W2, K, N);
    dim3 grid(N / 128, (M + 127) / 128);
    if (hi)
        gemm_tc_kernel<6><<<grid, 256, GSMEM6>>>(s_A0, s_A1, s_A2, s_W0, s_W1, s_W2,
                                                 bias, res, C, M, K, N, act);
    else
        gemm_tc_kernel<4><<<grid, 256, GSMEM4>>>(s_A0, s_A1, s_A2, s_W0, s_W1, s_W2,
                                                 bias, res, C, M, K, N, act);
}

extern "C" void kernel_launch(void* const* d_in, const int* in_sizes, int n_in,
                              void* d_out, int out_size) {
    const int*   ids     = (const int*)  d_in[0];
    const float* tok_emb = (const float*)d_in[1];
    const float* pos_emb = (const float*)d_in[2];
    const float* in_w    = (const float*)d_in[3];
    const float* in_b    = (const float*)d_in[4];
    const float* ch_w1   = (const float*)d_in[5];
    const float* ch_b1   = (const float*)d_in[6];
    const float* ch_w2   = (const float*)d_in[7];
    const float* ch_b2   = (const float*)d_in[8];
    const float* qe_w1   = (const float*)d_in[9];
    const float* qe_b1   = (const float*)d_in[10];
    const float* qe_w2   = (const float*)d_in[11];
    const float* qe_b2   = (const float*)d_in[12];
    const float* q_w     = (const float*)d_in[13];
    const float* q_b     = (const float*)d_in[14];
    const float* k_w     = (const float*)d_in[15];
    const float* k_b     = (const float*)d_in[16];
    const float* v_w     = (const float*)d_in[17];
    const float* v_b     = (const float*)d_in[18];
    const float* o_w     = (const float*)d_in[19];
    const float* o_b     = (const float*)d_in[20];
    const float* f_w1    = (const float*)d_in[21];
    const float* f_b1    = (const float*)d_in[22];
    const float* f_w2    = (const float*)d_in[23];
    const float* f_b2    = (const float*)d_in[24];
    const float* ln1_g   = (const float*)d_in[25];
    const float* ln1_b   = (const float*)d_in[26];
    const float* ln2_g   = (const float*)d_in[27];
    const float* ln2_b   = (const float*)d_in[28];
    const float* out_w   = (const float*)d_in[29];
    const float* out_b   = (const float*)d_in[30];
    float* logits = (float*)d_out;

    cudaFuncSetAttribute(gemm_tc_kernel<6>, cudaFuncAttributeMaxDynamicSharedMemorySize, GSMEM6);
    cudaFuncSetAttribute(gemm_tc_kernel<4>, cudaFuncAttributeMaxDynamicSharedMemorySize, GSMEM4);

    float *h, *x, *q, *k, *v, *ao, *mid, *avg, *cmid, *cenc;
    unsigned* sel;
    cudaGetSymbolAddress((void**)&h,    g_h);
    cudaGetSymbolAddress((void**)&x,    g_x);
    cudaGetSymbolAddress((void**)&q,    g_q);
    cudaGetSymbolAddress((void**)&k,    g_k);
    cudaGetSymbolAddress((void**)&v,    g_v);
    cudaGetSymbolAddress((void**)&ao,   g_ao);
    cudaGetSymbolAddress((void**)&mid,  g_mid);
    cudaGetSymbolAddress((void**)&avg,  g_avg);
    cudaGetSymbolAddress((void**)&cmid, g_cmid);
    cudaGetSymbolAddress((void**)&cenc, g_cenc);
    cudaGetSymbolAddress((void**)&sel,  g_sel);
    cudaGetSymbolAddress((void**)&s_A0, g_A0);
    cudaGetSymbolAddress((void**)&s_A1, g_A1);
    cudaGetSymbolAddress((void**)&s_A2, g_A2);
    cudaGetSymbolAddress((void**)&s_W0, g_W0);
    cudaGetSymbolAddress((void**)&s_W1, g_W1);
    cudaGetSymbolAddress((void**)&s_W2, g_W2);

    embed_kernel<<<R_, 256>>>(ids, tok_emb, pos_emb, x);
    cvtA(x, R_ * E_);
    run_gemm(in_w, in_b, nullptr, h, R_, E_, H_, 0, 1);

    chunk_avg_kernel<<<dim3(NC_, B_), 256>>>(h, ids, avg);
    cvtA(avg, B_ * NC_ * H_);
    run_gemm(ch_w1, ch_b1, nullptr, cmid, B_ * NC_, H_, HH_, 1, 1);
    cvtA(cmid, B_ * NC_ * HH_);
    run_gemm(ch_w2, ch_b2, nullptr, cenc, B_ * NC_, HH_, H_, 0, 1);

    for (int i = 0; i < L_; i++) {
        cvtA(h, R_ * H_);
        run_gemm(qe_w1, qe_b1, nullptr, mid, R_, H_, HH_, 1, 1);
        cvtA(mid, R_ * HH_);
        run_gemm(qe_w2, qe_b2, nullptr, x, R_, HH_, H_, 0, 1);
        topk_kernel<<<dim3(S_, B_), 512>>>(x, cenc, sel);

        ln_kernel<<<R_, 256>>>(h, ln1_g + i * H_, ln1_b + i * H_, x);
        cvtA(x, R_ * H_);
        run_gemm(q_w + (size_t)i * H_ * H_, q_b + i * H_, nullptr, q, R_, H_, H_, 0, 1);
        run_gemm(k_w + (size_t)i * H_ * H_, k_b + i * H_, nullptr, k, R_, H_, H_, 0, 1);
        run_gemm(v_w + (size_t)i * H_ * H_, v_b + i * H_, nullptr, v, R_, H_, H_, 0, 1);
        attn_kernel<<<dim3(S_, NH_, B_), 128>>>(q, k, v, sel, ids, ao);
        cvtA(ao, R_ * H_);
        run_gemm(o_w + (size_t)i * H_ * H_, o_b + i * H_, h, h, R_, H_, H_, 0, 1);

        ln_kernel<<<R_, 256>>>(h, ln2_g + i * H_, ln2_b + i * H_, x);
        cvtA(x, R_ * H_);
        run_gemm(f_w1 + (size_t)i * H_ * FF_, f_b1 + i * FF_, nullptr, mid, R_, H_, FF_, 2, 1);
        cvtA(mid, R_ * FF_);
        run_gemm(f_w2 + (size_t)i * FF_ * H_, f_b2 + i * H_, h, h, R_, FF_, H_, 0, 1);
    }

    // logits: smooth output path, 3-product precision (~1e-5 << 1e-3) is sufficient
    cvtA(h, R_ * H_);
    run_gemm(out_w, out_b, nullptr, logits, R_, H_, V_, 0, 0);
}

// round 6
// speedup vs baseline: 1.5621x; 1.0899x over previous
#include <cuda_runtime.h>
#include <cuda_bf16.h>
#include <math.h>
#include <stdint.h>

#define B_  2
#define S_  2048
#define E_  1024
#define H_  1024
#define NH_ 8
#define HD_ 128
#define L_  2
#define V_  32000
#define CS_ 128
#define NC_ 16
#define TOPK_ 8
#define R_  (B_ * S_)
#define FF_ (4 * H_)
#define HH_ (H_ / 2)
#define SCALE_ 0.08838834764831843f

// ---- scratch ----
__device__ __align__(16) float g_h  [R_ * H_];
__device__ __align__(16) float g_x  [R_ * H_];
__device__ __align__(16) float g_q  [R_ * H_];
__device__ __align__(16) float g_k  [R_ * H_];
__device__ __align__(16) float g_v  [R_ * H_];
__device__ __align__(16) float g_ao [R_ * H_];
__device__ __align__(16) float g_mid[R_ * FF_];
__device__ __align__(16) float g_avg [B_ * NC_ * H_];
__device__ __align__(16) float g_cmid[B_ * NC_ * HH_];
__device__ __align__(16) float g_cenc[B_ * NC_ * H_];
__device__ unsigned g_sel[R_];
__device__ __align__(16) __nv_bfloat16 g_A0[4096 * 4096];
__device__ __align__(16) __nv_bfloat16 g_A1[4096 * 4096];
__device__ __align__(16) __nv_bfloat16 g_A2[4096 * 4096];
__device__ __align__(16) __nv_bfloat16 g_W0[32000 * 1024];
__device__ __align__(16) __nv_bfloat16 g_W1[32000 * 1024];
__device__ __align__(16) __nv_bfloat16 g_W2[32000 * 1024];

// ---- helpers ----
__device__ __forceinline__ float warpSum(float v) {
    #pragma unroll
    for (int o = 16; o > 0; o >>= 1) v += __shfl_xor_sync(0xffffffffu, v, o);
    return v;
}
__device__ __forceinline__ float warpMax(float v) {
    #pragma unroll
    for (int o = 16; o > 0; o >>= 1) v = fmaxf(v, __shfl_xor_sync(0xffffffffu, v, o));
    return v;
}
__device__ __forceinline__ uint32_t smem_u32(const void* p) {
    uint32_t a;
    asm("{ .reg .u64 t; cvta.to.shared.u64 t, %1; cvt.u32.u64 %0, t; }" : "=r"(a) : "l"(p));
    return a;
}
#define CPA(d, s) asm volatile("cp.async.cg.shared.global [%0], [%1], 16;" :: "r"(d), "l"(s))
#define CPA_COMMIT() asm volatile("cp.async.commit_group;" ::: "memory")
#define CPA_WAIT0()  asm volatile("cp.async.wait_group 0;" ::: "memory")

#define LDSM_X4(r0, r1, r2, r3, a) \
    asm volatile("ldmatrix.sync.aligned.m8n8.x4.shared.b16 {%0,%1,%2,%3}, [%4];" \
        : "=r"(r0), "=r"(r1), "=r"(r2), "=r"(r3) : "r"(a))

#define MMA_BF16(c, a, b) \
    asm volatile("mma.sync.aligned.m16n8k16.row.col.f32.bf16.bf16.f32 " \
        "{%0,%1,%2,%3}, {%4,%5,%6,%7}, {%8,%9}, {%0,%1,%2,%3};" \
        : "+f"((c)[0]), "+f"((c)[1]), "+f"((c)[2]), "+f"((c)[3]) \
        : "r"((a)[0]), "r"((a)[1]), "r"((a)[2]), "r"((a)[3]), "r"((b)[0]), "r"((b)[1]))

// ---- embedding ----
__global__ void embed_kernel(const int* __restrict__ ids, const float* __restrict__ tok,
                             const float* __restrict__ pos, float* __restrict__ out) {
    int r = blockIdx.x;
    int id = ids[r];
    const float* t = tok + (size_t)id * E_;
    const float* p = pos + (size_t)(r % S_) * E_;
    float* o = out + (size_t)r * E_;
    for (int e = threadIdx.x; e < E_; e += blockDim.x) o[e] = t[e] + p[e];
}

// ---- fp32 -> 3-way bf16 split ----
__global__ void cvt_split3_kernel(const float* __restrict__ a, __nv_bfloat16* __restrict__ o0,
                                  __nv_bfloat16* __restrict__ o1, __nv_bfloat16* __restrict__ o2,
                                  int n) {
    int i = (blockIdx.x * blockDim.x + threadIdx.x) * 4;
    if (i >= n) return;
    float4 v = *(const float4*)(a + i);
    union { __nv_bfloat16 b[4]; uint2 u; } U0, U1, U2;
    float f[4] = {v.x, v.y, v.z, v.w};
    #pragma unroll
    for (int j = 0; j < 4; j++) {
        __nv_bfloat16 b0 = __float2bfloat16_rn(f[j]);
        float r1 = f[j] - __bfloat162float(b0);
        __nv_bfloat16 b1 = __float2bfloat16_rn(r1);
        float r2 = r1 - __bfloat162float(b1);
        U0.b[j] = b0; U1.b[j] = b1; U2.b[j] = __float2bfloat16_rn(r2);
    }
    *(uint2*)(o0 + i) = U0.u;
    *(uint2*)(o1 + i) = U1.u;
    *(uint2*)(o2 + i) = U2.u;
}

// ---- fp32 W[K,N] -> 3-way split W^T[N,K] ----
__global__ void cvt_t3_kernel(const float* __restrict__ w, __nv_bfloat16* __restrict__ o0,
                              __nv_bfloat16* __restrict__ o1, __nv_bfloat16* __restrict__ o2,
                              int Kd, int Nd) {
    __shared__ float t[32][33];
    int n0 = blockIdx.x * 32, k0 = blockIdx.y * 32;
    int tx = threadIdx.x, ty = threadIdx.y;
    #pragma unroll
    for (int i = 0; i < 32; i += 8)
        t[ty + i][tx] = w[(size_t)(k0 + ty + i) * Nd + n0 + tx];
    __syncthreads();
    #pragma unroll
    for (int i = 0; i < 32; i += 8) {
        float v = t[tx][ty + i];
        __nv_bfloat16 b0 = __float2bfloat16_rn(v);
        float r1 = v - __bfloat162float(b0);
        __nv_bfloat16 b1 = __float2bfloat16_rn(r1);
        float r2 = r1 - __bfloat162float(b1);
        size_t o = (size_t)(n0 + ty + i) * Kd + k0 + tx;
        o0[o] = b0; o1[o] = b1; o2[o] = __float2bfloat16_rn(r2);
    }
}

// ---- HMMA bf16x3 GEMM: C = act(A@W + bias) [+res] ----
// CTA tile 128x256, BK=32, 8 warps of 64x64 (2x4 grid). NB=6 hi / NB=4 lo.
#define SK 40
#define A_MAT (128 * SK * 2)   // 10240
#define B_MAT (256 * SK * 2)   // 20480

template<int NB>
__global__ void __launch_bounds__(256)
gemm_tc_kernel(const __nv_bfloat16* __restrict__ A0, const __nv_bfloat16* __restrict__ A1,
               const __nv_bfloat16* __restrict__ A2,
               const __nv_bfloat16* __restrict__ B0, const __nv_bfloat16* __restrict__ B1,
               const __nv_bfloat16* __restrict__ B2,
               const float* __restrict__ bias, const float* __restrict__ res,
               float* __restrict__ C, int M, int K, int N, int act) {
    constexpr int NA  = (NB == 6) ? 3 : 2;
    constexpr int NBB = NB - NA;
    constexpr int STG = NA * A_MAT + NBB * B_MAT;
    extern __shared__ char smem[];
    const uint32_t sb = smem_u32(smem);
    const int tid = threadIdx.x, lane = tid & 31;
    const int w = tid >> 5, wm = w >> 2, wn = w & 3;
    const int m0 = blockIdx.y * 128, n0 = blockIdx.x * 256;

    float c[4][8][4];
    #pragma unroll
    for (int i = 0; i < 4; i++)
        #pragma unroll
        for (int j = 0; j < 8; j++)
            #pragma unroll
            for (int e = 0; e < 4; e++) c[i][j][e] = 0.f;

    // A: 512 slots (2/thread), B: 1024 slots (4/thread)
    int arow[2], aseg[2];
    #pragma unroll
    for (int i = 0; i < 2; i++) {
        int idx = tid + i * 256;
        int r = idx >> 2;
        aseg[i] = idx & 3;
        int ar = m0 + r;
        arow[i] = r;
        if (ar >= M) arow[i] = r;           // smem row stays r
        arow[i] = r;
    }
    int agrow[2];
    #pragma unroll
    for (int i = 0; i < 2; i++) {
        int ar = m0 + arow[i];
        agrow[i] = ar < M ? ar : (M - 1);
    }

    auto issue_stage = [&](int kb, int st) {
        size_t gk = (size_t)kb * 32;
        uint32_t stb = sb + st * STG;
        #pragma unroll
        for (int i = 0; i < 2; i++) {
            uint32_t d = stb + (arow[i] * SK + aseg[i] * 8) * 2;
            size_t o = (size_t)agrow[i] * K + gk + aseg[i] * 8;
            CPA(d, A0 + o);
            CPA(d + A_MAT, A1 + o);
            if (NB == 6) CPA(d + 2 * A_MAT, A2 + o);
        }
        #pragma unroll
        for (int i = 0; i < 4; i++) {
            int idx = tid + i * 256;
            int r = idx >> 2, sg = idx & 3;
            uint32_t d = stb + NA * A_MAT + (r * SK + sg * 8) * 2;
            size_t o = (size_t)(n0 + r) * K + gk + sg * 8;
            CPA(d, B0 + o);
            CPA(d + B_MAT, B1 + o);
            if (NB == 6) CPA(d + 2 * B_MAT, B2 + o);
        }
        CPA_COMMIT();
    };

    const int nkb = K >> 5;
    issue_stage(0, 0);
    CPA_WAIT0();
    __syncthreads();

    const uint32_t a_off = ((wm * 64 + (lane & 15)) * SK + ((lane >> 4) << 3)) * 2;
    const uint32_t b_off = ((wn * 64 + (lane & 7) + ((lane >> 4) << 3)) * SK + (((lane >> 3) & 1) << 3)) * 2;

    for (int kb = 0; kb < nkb; kb++) {
        int st = kb & 1;
        if (kb + 1 < nkb) issue_stage(kb + 1, st ^ 1);
        uint32_t base = sb + st * STG;
        #pragma unroll
        for (int kk = 0; kk < 2; kk++) {
            // A fragments: NA splits x 4 mt
            uint32_t af[NA][4][4];
            #pragma unroll
            for (int s = 0; s < NA; s++)
                #pragma unroll
                for (int mt = 0; mt < 4; mt++) {
                    uint32_t ad = base + s * A_MAT + a_off + kk * 32 + mt * 16 * SK * 2;
                    LDSM_X4(af[s][mt][0], af[s][mt][1], af[s][mt][2], af[s][mt][3], ad);
                }
            #pragma unroll
            for (int nt2 = 0; nt2 < 4; nt2++) {
                uint32_t bf[NBB][4];
                #pragma unroll
                for (int s = 0; s < NBB; s++) {
                    uint32_t bd = base + NA * A_MAT + s * B_MAT + b_off + kk * 32 + nt2 * 16 * SK * 2;
                    LDSM_X4(bf[s][0], bf[s][1], bf[s][2], bf[s][3], bd);
                }
                // products: interleave (mt, half) between same-acc reuse to hide MMA latency
                #pragma unroll
                for (int p = 0; p < NB; p++) {
                    const int pa = (NB == 6) ? ((int[]){0,0,1,1,0,2})[p] : ((int[]){0,0,1,0})[p >= 3 ? 0 : p];
                    const int pb = (NB == 6) ? ((int[]){0,1,0,1,2,0})[p] : ((int[]){0,1,0,0})[p >= 3 ? 0 : p];
                    if (NB == 4 && p >= 3) break;
                    #pragma unroll
                    for (int mt = 0; mt < 4; mt++)
                        #pragma unroll
                        for (int half = 0; half < 2; half++)
                            MMA_BF16(c[mt][nt2 * 2 + half], af[pa][mt], bf[pb] + half * 2);
                }
            }
        }
        if (kb + 1 < nkb) CPA_WAIT0();
        __syncthreads();
    }

    const int grp = lane >> 2, tig = lane & 3;
    #pragma unroll
    for (int mt = 0; mt < 4; mt++) {
        #pragma unroll
        for (int nt = 0; nt < 8; nt++) {
            int col = n0 + wn * 64 + nt * 8 + tig * 2;
            float b0 = bias[col], b1 = bias[col + 1];
            #pragma unroll
            for (int hrow = 0; hrow < 2; hrow++) {
                int row = m0 + wm * 64 + mt * 16 + grp + hrow * 8;
                if (row >= M) continue;
                float vx = c[mt][nt][hrow * 2 + 0] + b0;
                float vy = c[mt][nt][hrow * 2 + 1] + b1;
                if (act == 1) {
                    vx = fmaxf(vx, 0.f); vy = fmaxf(vy, 0.f);
                } else if (act == 2) {
                    vx = 0.5f * vx * (1.f + erff(vx * 0.7071067811865475f));
                    vy = 0.5f * vy * (1.f + erff(vy * 0.7071067811865475f));
                }
                size_t off = (size_t)row * N + col;
                if (res) {
                    float2 r = *(const float2*)(res + off);
                    vx += r.x; vy += r.y;
                }
                float2 o; o.x = vx; o.y = vy;
                *(float2*)(C + off) = o;
            }
        }
    }
}

// ---- chunk mean ----
__global__ void chunk_avg_kernel(const float* __restrict__ h, const int* __restrict__ ids,
                                 float* __restrict__ avg) {
    int c = blockIdx.x, b = blockIdx.y;
    __shared__ float msk[CS_];
    __shared__ float s_cnt;
    int tid = threadIdx.x;
    if (tid < CS_) msk[tid] = (ids[b * S_ + c * CS_ + tid] != 0) ? 1.f : 0.f;
    __syncthreads();
    if (tid == 0) {
        float cn = 0.f;
        for (int p = 0; p < CS_; p++) cn += msk[p];
        s_cnt = cn;
    }
    __syncthreads();
    float inv = 1.f / (s_cnt + 1e-10f);
    for (int d = tid; d < H_; d += blockDim.x) {
        float s = 0.f;
        for (int p = 0; p < CS_; p++)
            s += h[(size_t)(b * S_ + c * CS_ + p) * H_ + d] * msk[p];
        avg[(size_t)(b * NC_ + c) * H_ + d] = s * inv;
    }
}

// ---- topk ----
__global__ void __launch_bounds__(512)
topk_kernel(const float* __restrict__ qe, const float* __restrict__ cenc,
            unsigned* __restrict__ sel) {
    int s = blockIdx.x, b = blockIdx.y;
    int tid = threadIdx.x, warp = tid >> 5, lane = tid & 31;
    __shared__ float sc[NC_];
    const float* q = qe + (size_t)(b * S_ + s) * H_;
    const float* c = cenc + (size_t)(b * NC_ + warp) * H_;
    float d = 0.f;
    for (int e = lane; e < H_; e += 32) d += q[e] * c[e];
    d = warpSum(d);
    if (lane == 0) sc[warp] = d;
    __syncthreads();
    if (tid == 0) {
        unsigned chosen = 0;
        for (int t = 0; t < TOPK_; t++) {
            float best = -INFINITY;
            int bi = 0;
            for (int cc = 0; cc < NC_; cc++)
                if (!((chosen >> cc) & 1u) && sc[cc] > best) { best = sc[cc]; bi = cc; }
            chosen |= 1u << bi;
        }
        sel[b * S_ + s] = chosen;
    }
}

// ---- LayerNorm ----
__global__ void ln_kernel(const float* __restrict__ x, const float* __restrict__ g,
                          const float* __restrict__ bt, float* __restrict__ y) {
    int r = blockIdx.x;
    int tid = threadIdx.x, warp = tid >> 5, lane = tid & 31;
    const float* xr = x + (size_t)r * H_;
    float s = 0.f, sq = 0.f;
    for (int e = tid; e < H_; e += 256) {
        float v = xr[e];
        s += v; sq += v * v;
    }
    __shared__ float rs[8], rq[8];
    __shared__ float s_mean, s_rstd;
    s = warpSum(s); sq = warpSum(sq);
    if (lane == 0) { rs[warp] = s; rq[warp] = sq; }
    __syncthreads();
    if (tid == 0) {
        float Sm = 0.f, Q = 0.f;
        for (int ww = 0; ww < 8; ww++) { Sm += rs[ww]; Q += rq[ww]; }
        float mean = Sm / (float)H_;
        float var = Q / (float)H_ - mean * mean;
        s_mean = mean;
        s_rstd = rsqrtf(var + 1e-5f);
    }
    __syncthreads();
    float mean = s_mean, rstd = s_rstd;
    float* yr = y + (size_t)r * H_;
    for (int e = tid; e < H_; e += 256)
        yr[e] = (xr[e] - mean) * rstd * g[e] + bt[e];
}

// ---- sparse chunk attention ----
__global__ void __launch_bounds__(128)
attn_kernel(const float* __restrict__ q, const float* __restrict__ k,
            const float* __restrict__ v, const unsigned* __restrict__ sel,
            const int* __restrict__ ids, float* __restrict__ out) {
    int s = blockIdx.x, head = blockIdx.y, b = blockIdx.z;
    int tid = threadIdx.x, warp = tid >> 5, lane = tid & 31;
    __shared__ float qv[HD_];
    __shared__ float sc[CS_];
    __shared__ float red[4];
    __shared__ float bcast[2];

    size_t qoff = (size_t)(b * S_ + s) * H_ + head * HD_;
    qv[tid] = q[qoff + tid];
    __syncthreads();
    float4 q4 = *(const float4*)&qv[lane * 4];

    unsigned msk = sel[b * S_ + s];
    float m = -INFINITY, l = 0.f, acc = 0.f;

    for (int c = 0; c < NC_; c++) {
        if (!((msk >> c) & 1u)) continue;
        int j0 = c * CS_;
        for (int kk = 0; kk < 32; kk++) {
            int j = j0 + warp * 32 + kk;
            const float4 kv = *(const float4*)&k[(size_t)(b * S_ + j) * H_ + head * HD_ + lane * 4];
            float d = q4.x * kv.x + q4.y * kv.y + q4.z * kv.z + q4.w * kv.w;
            d = warpSum(d);
            if (lane == 0) sc[warp * 32 + kk] = d;
        }
        __syncthreads();
        float scv = sc[tid] * SCALE_;
        if (ids[b * S_ + j0 + tid] == 0) scv = -INFINITY;
        float wm = warpMax(scv);
        if (lane == 0) red[warp] = wm;
        __syncthreads();
        if (tid == 0) bcast[0] = fmaxf(fmaxf(red[0], red[1]), fmaxf(red[2], red[3]));
        __syncthreads();
        float newm = fmaxf(m, bcast[0]);
        float p = expf(scv - newm);
        sc[tid] = p;
        float ws = warpSum(p);
        if (lane == 0) red[warp] = ws;
        __syncthreads();
        if (tid == 0) bcast[1] = red[0] + red[1] + red[2] + red[3];
        __syncthreads();
        float f = expf(m - newm);
        l = l * f + bcast[1];
        acc *= f;
        const float* vb = v + (size_t)(b * S_ + j0) * H_ + head * HD_ + tid;
        for (int j = 0; j < CS_; j++) acc += sc[j] * vb[(size_t)j * H_];
        m = newm;
        __syncthreads();
    }
    out[qoff + tid] = acc / l;
}

// ---- host ----
static __nv_bfloat16 *s_A0, *s_A1, *s_A2, *s_W0, *s_W1, *s_W2;
#define GSMEM6 (2 * (3 * A_MAT + 3 * B_MAT))   // 184320
#define GSMEM4 (2 * (2 * A_MAT + 2 * B_MAT))   // 122880

static inline void cvtA(const float* A, int n) {
    cvt_split3_kernel<<<(n / 4 + 255) / 256, 256>>>(A, s_A0, s_A1, s_A2, n);
}
static inline void run_gemm(const float* W, const float* bias, const float* res,
                            float* C, int M, int K, int N, int act, int hi) {
    cvt_t3_kernel<<<dim3(N / 32, K / 32), dim3(32, 8)>>>(W, s_W0, s_W1, s_W2, K, N);
    dim3 grid(N / 256, (M + 127) / 128);
    if (hi)
        gemm_tc_kernel<6><<<grid, 256, GSMEM6>>>(s_A0, s_A1, s_A2, s_W0, s_W1, s_W2,
                                                 bias, res, C, M, K, N, act);
    else
        gemm_tc_kernel<4><<<grid, 256, GSMEM4>>>(s_A0, s_A1, s_A2, s_W0, s_W1, s_W2,
                                                 bias, res, C, M, K, N, act);
}

extern "C" void kernel_launch(void* const* d_in, const int* in_sizes, int n_in,
                              void* d_out, int out_size) {
    const int*   ids     = (const int*)  d_in[0];
    const float* tok_emb = (const float*)d_in[1];
    const float* pos_emb = (const float*)d_in[2];
    const float* in_w    = (const float*)d_in[3];
    const float* in_b    = (const float*)d_in[4];
    const float* ch_w1   = (const float*)d_in[5];
    const float* ch_b1   = (const float*)d_in[6];
    const float* ch_w2   = (const float*)d_in[7];
    const float* ch_b2   = (const float*)d_in[8];
    const float* qe_w1   = (const float*)d_in[9];
    const float* qe_b1   = (const float*)d_in[10];
    const float* qe_w2   = (const float*)d_in[11];
    const float* qe_b2   = (const float*)d_in[12];
    const float* q_w     = (const float*)d_in[13];
    const float* q_b     = (const float*)d_in[14];
    const float* k_w     = (const float*)d_in[15];
    const float* k_b     = (const float*)d_in[16];
    const float* v_w     = (const float*)d_in[17];
    const float* v_b     = (const float*)d_in[18];
    const float* o_w     = (const float*)d_in[19];
    const float* o_b     = (const float*)d_in[20];
    const float* f_w1    = (const float*)d_in[21];
    const float* f_b1    = (const float*)d_in[22];
    const float* f_w2    = (const float*)d_in[23];
    const float* f_b2    = (const float*)d_in[24];
    const float* ln1_g   = (const float*)d_in[25];
    const float* ln1_b   = (const float*)d_in[26];
    const float* ln2_g   = (const float*)d_in[27];
    const float* ln2_b   = (const float*)d_in[28];
    const float* out_w   = (const float*)d_in[29];
    const float* out_b   = (const float*)d_in[30];
    float* logits = (float*)d_out;

    cudaFuncSetAttribute(gemm_tc_kernel<6>, cudaFuncAttributeMaxDynamicSharedMemorySize, GSMEM6);
    cudaFuncSetAttribute(gemm_tc_kernel<4>, cudaFuncAttributeMaxDynamicSharedMemorySize, GSMEM4);

    float *h, *x, *q, *k, *v, *ao, *mid, *avg, *cmid, *cenc;
    unsigned* sel;
    cudaGetSymbolAddress((void**)&h,    g_h);
    cudaGetSymbolAddress((void**)&x,    g_x);
    cudaGetSymbolAddress((void**)&q,    g_q);
    cudaGetSymbolAddress((void**)&k,    g_k);
    cudaGetSymbolAddress((void**)&v,    g_v);
    cudaGetSymbolAddress((void**)&ao,   g_ao);
    cudaGetSymbolAddress((void**)&mid,  g_mid);
    cudaGetSymbolAddress((void**)&avg,  g_avg);
    cudaGetSymbolAddress((void**)&cmid, g_cmid);
    cudaGetSymbolAddress((void**)&cenc, g_cenc);
    cudaGetSymbolAddress((void**)&sel,  g_sel);
    cudaGetSymbolAddress((void**)&s_A0, g_A0);
    cudaGetSymbolAddress((void**)&s_A1, g_A1);
    cudaGetSymbolAddress((void**)&s_A2, g_A2);
    cudaGetSymbolAddress((void**)&s_W0, g_W0);
    cudaGetSymbolAddress((void**)&s_W1, g_W1);
    cudaGetSymbolAddress((void**)&s_W2, g_W2);

    embed_kernel<<<R_, 256>>>(ids, tok_emb, pos_emb, x);
    cvtA(x, R_ * E_);
    run_gemm(in_w, in_b, nullptr, h, R_, E_, H_, 0, 1);

    chunk_avg_kernel<<<dim3(NC_, B_), 256>>>(h, ids, avg);
    cvtA(avg, B_ * NC_ * H_);
    run_gemm(ch_w1, ch_b1, nullptr, cmid, B_ * NC_, H_, HH_, 1, 1);
    cvtA(cmid, B_ * NC_ * HH_);
    run_gemm(ch_w2, ch_b2, nullptr, cenc, B_ * NC_, HH_, H_, 0, 1);

    for (int i = 0; i < L_; i++) {
        // selection path: always hi precision
        cvtA(h, R_ * H_);
        run_gemm(qe_w1, qe_b1, nullptr, mid, R_, H_, HH_, 1, 1);
        cvtA(mid, R_ * HH_);
        run_gemm(qe_w2, qe_b2, nullptr, x, R_, HH_, H_, 0, 1);
        topk_kernel<<<dim3(S_, B_), 512>>>(x, cenc, sel);

        // layer-1 post-selection GEMMs only feed logits (smooth) -> lo precision
        int hi = (i == 0) ? 1 : 0;
        ln_kernel<<<R_, 256>>>(h, ln1_g + i * H_, ln1_b + i * H_, x);
        cvtA(x, R_ * H_);
        run_gemm(q_w + (size_t)i * H_ * H_, q_b + i * H_, nullptr, q, R_, H_, H_, 0, hi);
        run_gemm(k_w + (size_t)i * H_ * H_, k_b + i * H_, nullptr, k, R_, H_, H_, 0, hi);
        run_gemm(v_w + (size_t)i * H_ * H_, v_b + i * H_, nullptr, v, R_, H_, H_, 0, hi);
        attn_kernel<<<dim3(S_, NH_, B_), 128>>>(q, k, v, sel, ids, ao);
        cvtA(ao, R_ * H_);
        run_gemm(o_w + (size_t)i * H_ * H_, o_b + i * H_, h, h, R_, H_, H_, 0, hi);

        ln_kernel<<<R_, 256>>>(h, ln2_g + i * H_, ln2_b + i * H_, x);
        cvtA(x, R_ * H_);
        run_gemm(f_w1 + (size_t)i * H_ * FF_, f_b1 + i * FF_, nullptr, mid, R_, H_, FF_, 2, hi);
        cvtA(mid, R_ * FF_);
        run_gemm(f_w2 + (size_t)i * FF_ * H_, f_b2 + i * H_, h, h, R_, FF_, H_, 0, hi);
    }

    cvtA(h, R_ * H_);
    run_gemm(out_w, out_b, nullptr, logits, R_, H_, V_, 0, 0);
}

// round 7
// speedup vs baseline: 1.6973x; 1.0866x over previous
#include <cuda_runtime.h>
#include <cuda_bf16.h>
#include <math.h>
#include <stdint.h>

#define B_  2
#define S_  2048
#define E_  1024
#define H_  1024
#define NH_ 8
#define HD_ 128
#define L_  2
#define V_  32000
#define CS_ 128
#define NC_ 16
#define TOPK_ 8
#define R_  (B_ * S_)
#define FF_ (4 * H_)
#define HH_ (H_ / 2)
#define SCALE_ 0.08838834764831843f

// ---- scratch ----
__device__ __align__(16) float g_h  [R_ * H_];
__device__ __align__(16) float g_x  [R_ * H_];
__device__ __align__(16) float g_q  [R_ * H_];
__device__ __align__(16) float g_k  [R_ * H_];
__device__ __align__(16) float g_v  [R_ * H_];
__device__ __align__(16) float g_ao [R_ * H_];
__device__ __align__(16) float g_mid[R_ * FF_];
__device__ __align__(16) float g_avg [B_ * NC_ * H_];
__device__ __align__(16) float g_cmid[B_ * NC_ * HH_];
__device__ __align__(16) float g_cenc[B_ * NC_ * H_];
__device__ unsigned g_sel[R_];
__device__ __align__(16) __nv_bfloat16 g_A0[4096 * 4096];
__device__ __align__(16) __nv_bfloat16 g_A1[4096 * 4096];
__device__ __align__(16) __nv_bfloat16 g_W0[32000 * 1024];
__device__ __align__(16) __nv_bfloat16 g_W1[32000 * 1024];

// ---- helpers ----
__device__ __forceinline__ float warpSum(float v) {
    #pragma unroll
    for (int o = 16; o > 0; o >>= 1) v += __shfl_xor_sync(0xffffffffu, v, o);
    return v;
}
__device__ __forceinline__ float warpMax(float v) {
    #pragma unroll
    for (int o = 16; o > 0; o >>= 1) v = fmaxf(v, __shfl_xor_sync(0xffffffffu, v, o));
    return v;
}
__device__ __forceinline__ uint32_t smem_u32(const void* p) {
    uint32_t a;
    asm("{ .reg .u64 t; cvta.to.shared.u64 t, %1; cvt.u32.u64 %0, t; }" : "=r"(a) : "l"(p));
    return a;
}
#define CPA(d, s) asm volatile("cp.async.cg.shared.global [%0], [%1], 16;" :: "r"(d), "l"(s))
#define CPA_COMMIT() asm volatile("cp.async.commit_group;" ::: "memory")
#define CPA_WAIT0()  asm volatile("cp.async.wait_group 0;" ::: "memory")

#define LDSM_X4(r0, r1, r2, r3, a) \
    asm volatile("ldmatrix.sync.aligned.m8n8.x4.shared.b16 {%0,%1,%2,%3}, [%4];" \
        : "=r"(r0), "=r"(r1), "=r"(r2), "=r"(r3) : "r"(a))

#define MMA_BF16(c, a, b) \
    asm volatile("mma.sync.aligned.m16n8k16.row.col.f32.bf16.bf16.f32 " \
        "{%0,%1,%2,%3}, {%4,%5,%6,%7}, {%8,%9}, {%0,%1,%2,%3};" \
        : "+f"((c)[0]), "+f"((c)[1]), "+f"((c)[2]), "+f"((c)[3]) \
        : "r"((a)[0]), "r"((a)[1]), "r"((a)[2]), "r"((a)[3]), "r"((b)[0]), "r"((b)[1]))

// ---- embedding ----
__global__ void embed_kernel(const int* __restrict__ ids, const float* __restrict__ tok,
                             const float* __restrict__ pos, float* __restrict__ out) {
    int r = blockIdx.x;
    int id = ids[r];
    const float* t = tok + (size_t)id * E_;
    const float* p = pos + (size_t)(r % S_) * E_;
    float* o = out + (size_t)r * E_;
    for (int e = threadIdx.x; e < E_; e += blockDim.x) o[e] = t[e] + p[e];
}

// ---- fp32 -> 2-way bf16 split ----
__global__ void cvt_split2_kernel(const float* __restrict__ a, __nv_bfloat16* __restrict__ o0,
                                  __nv_bfloat16* __restrict__ o1, int n) {
    int i = (blockIdx.x * blockDim.x + threadIdx.x) * 4;
    if (i >= n) return;
    float4 v = *(const float4*)(a + i);
    union { __nv_bfloat16 b[4]; uint2 u; } U0, U1;
    float f[4] = {v.x, v.y, v.z, v.w};
    #pragma unroll
    for (int j = 0; j < 4; j++) {
        __nv_bfloat16 b0 = __float2bfloat16_rn(f[j]);
        U0.b[j] = b0;
        U1.b[j] = __float2bfloat16_rn(f[j] - __bfloat162float(b0));
    }
    *(uint2*)(o0 + i) = U0.u;
    *(uint2*)(o1 + i) = U1.u;
}

// ---- fp32 W[K,N] -> 2-way split W^T[N,K] ----
__global__ void cvt_t2_kernel(const float* __restrict__ w, __nv_bfloat16* __restrict__ o0,
                              __nv_bfloat16* __restrict__ o1, int Kd, int Nd) {
    __shared__ float t[32][33];
    int n0 = blockIdx.x * 32, k0 = blockIdx.y * 32;
    int tx = threadIdx.x, ty = threadIdx.y;
    #pragma unroll
    for (int i = 0; i < 32; i += 8)
        t[ty + i][tx] = w[(size_t)(k0 + ty + i) * Nd + n0 + tx];
    __syncthreads();
    #pragma unroll
    for (int i = 0; i < 32; i += 8) {
        float v = t[tx][ty + i];
        __nv_bfloat16 b0 = __float2bfloat16_rn(v);
        size_t o = (size_t)(n0 + ty + i) * Kd + k0 + tx;
        o0[o] = b0;
        o1[o] = __float2bfloat16_rn(v - __bfloat162float(b0));
    }
}

// ---- HMMA split-bf16 GEMM: C = act(A@W + bias) [+res] ----
// CTA 128x256, BK=32, 8 warps 64x64 (2x4). NP=4: full fp32-equiv; NP=3: ~1e-5.
#define SK 40
#define A_MAT (128 * SK * 2)   // 10240
#define B_MAT (256 * SK * 2)   // 20480
#define STG (2 * A_MAT + 2 * B_MAT)
#define GSMEM (2 * STG)        // 122880

template<int NP>
__global__ void __launch_bounds__(256)
gemm_tc_kernel(const __nv_bfloat16* __restrict__ A0, const __nv_bfloat16* __restrict__ A1,
               const __nv_bfloat16* __restrict__ B0, const __nv_bfloat16* __restrict__ B1,
               const float* __restrict__ bias, const float* __restrict__ res,
               float* __restrict__ C, int M, int K, int N, int act) {
    extern __shared__ char smem[];
    const uint32_t sb = smem_u32(smem);
    const int tid = threadIdx.x, lane = tid & 31;
    const int w = tid >> 5, wm = w >> 2, wn = w & 3;
    const int m0 = blockIdx.y * 128, n0 = blockIdx.x * 256;

    float c[4][8][4];
    #pragma unroll
    for (int i = 0; i < 4; i++)
        #pragma unroll
        for (int j = 0; j < 8; j++)
            #pragma unroll
            for (int e = 0; e < 4; e++) c[i][j][e] = 0.f;

    int arow[2], aseg[2], agrow[2];
    #pragma unroll
    for (int i = 0; i < 2; i++) {
        int idx = tid + i * 256;
        arow[i] = idx >> 2;
        aseg[i] = idx & 3;
        int ar = m0 + arow[i];
        agrow[i] = ar < M ? ar : (M - 1);
    }

    auto issue_stage = [&](int kb, int st) {
        size_t gk = (size_t)kb * 32;
        uint32_t stb = sb + st * STG;
        #pragma unroll
        for (int i = 0; i < 2; i++) {
            uint32_t d = stb + (arow[i] * SK + aseg[i] * 8) * 2;
            size_t o = (size_t)agrow[i] * K + gk + aseg[i] * 8;
            CPA(d, A0 + o);
            CPA(d + A_MAT, A1 + o);
        }
        #pragma unroll
        for (int i = 0; i < 4; i++) {
            int idx = tid + i * 256;
            int r = idx >> 2, sg = idx & 3;
            uint32_t d = stb + 2 * A_MAT + (r * SK + sg * 8) * 2;
            size_t o = (size_t)(n0 + r) * K + gk + sg * 8;
            CPA(d, B0 + o);
            CPA(d + B_MAT, B1 + o);
        }
        CPA_COMMIT();
    };

    const int nkb = K >> 5;
    issue_stage(0, 0);
    CPA_WAIT0();
    __syncthreads();

    const uint32_t a_off = ((wm * 64 + (lane & 15)) * SK + ((lane >> 4) << 3)) * 2;
    const uint32_t b_off = ((wn * 64 + (lane & 7) + ((lane >> 4) << 3)) * SK + (((lane >> 3) & 1) << 3)) * 2;
    const int pa[4] = {0, 0, 1, 1};
    const int pb[4] = {0, 1, 0, 1};

    for (int kb = 0; kb < nkb; kb++) {
        int st = kb & 1;
        if (kb + 1 < nkb) issue_stage(kb + 1, st ^ 1);
        uint32_t base = sb + st * STG;
        #pragma unroll
        for (int kk = 0; kk < 2; kk++) {
            uint32_t af[2][4][4];
            #pragma unroll
            for (int s = 0; s < 2; s++)
                #pragma unroll
                for (int mt = 0; mt < 4; mt++) {
                    uint32_t ad = base + s * A_MAT + a_off + kk * 32 + mt * 16 * SK * 2;
                    LDSM_X4(af[s][mt][0], af[s][mt][1], af[s][mt][2], af[s][mt][3], ad);
                }
            // B register double-buffer: prefetch nt2+1 while MMAing nt2
            uint32_t bf[2][2][4];
            #pragma unroll
            for (int s = 0; s < 2; s++) {
                uint32_t bd = base + 2 * A_MAT + s * B_MAT + b_off + kk * 32;
                LDSM_X4(bf[0][s][0], bf[0][s][1], bf[0][s][2], bf[0][s][3], bd);
            }
            #pragma unroll
            for (int nt2 = 0; nt2 < 4; nt2++) {
                int cur = nt2 & 1, nxt = cur ^ 1;
                if (nt2 < 3) {
                    #pragma unroll
                    for (int s = 0; s < 2; s++) {
                        uint32_t bd = base + 2 * A_MAT + s * B_MAT + b_off + kk * 32 + (nt2 + 1) * 16 * SK * 2;
                        LDSM_X4(bf[nxt][s][0], bf[nxt][s][1], bf[nxt][s][2], bf[nxt][s][3], bd);
                    }
                }
                #pragma unroll
                for (int p = 0; p < NP; p++)
                    #pragma unroll
                    for (int mt = 0; mt < 4; mt++)
                        #pragma unroll
                        for (int half = 0; half < 2; half++)
                            MMA_BF16(c[mt][nt2 * 2 + half], af[pa[p]][mt], bf[cur][pb[p]] + half * 2);
            }
        }
        if (kb + 1 < nkb) CPA_WAIT0();
        __syncthreads();
    }

    const int grp = lane >> 2, tig = lane & 3;
    #pragma unroll
    for (int mt = 0; mt < 4; mt++) {
        #pragma unroll
        for (int nt = 0; nt < 8; nt++) {
            int col = n0 + wn * 64 + nt * 8 + tig * 2;
            float b0 = bias[col], b1 = bias[col + 1];
            #pragma unroll
            for (int hrow = 0; hrow < 2; hrow++) {
                int row = m0 + wm * 64 + mt * 16 + grp + hrow * 8;
                if (row >= M) continue;
                float vx = c[mt][nt][hrow * 2 + 0] + b0;
                float vy = c[mt][nt][hrow * 2 + 1] + b1;
                if (act == 1) {
                    vx = fmaxf(vx, 0.f); vy = fmaxf(vy, 0.f);
                } else if (act == 2) {
                    vx = 0.5f * vx * (1.f + erff(vx * 0.7071067811865475f));
                    vy = 0.5f * vy * (1.f + erff(vy * 0.7071067811865475f));
                }
                size_t off = (size_t)row * N + col;
                if (res) {
                    float2 r = *(const float2*)(res + off);
                    vx += r.x; vy += r.y;
                }
                float2 o; o.x = vx; o.y = vy;
                *(float2*)(C + off) = o;
            }
        }
    }
}

// ---- chunk mean ----
__global__ void chunk_avg_kernel(const float* __restrict__ h, const int* __restrict__ ids,
                                 float* __restrict__ avg) {
    int c = blockIdx.x, b = blockIdx.y;
    __shared__ float msk[CS_];
    __shared__ float s_cnt;
    int tid = threadIdx.x;
    if (tid < CS_) msk[tid] = (ids[b * S_ + c * CS_ + tid] != 0) ? 1.f : 0.f;
    __syncthreads();
    if (tid == 0) {
        float cn = 0.f;
        for (int p = 0; p < CS_; p++) cn += msk[p];
        s_cnt = cn;
    }
    __syncthreads();
    float inv = 1.f / (s_cnt + 1e-10f);
    for (int d = tid; d < H_; d += blockDim.x) {
        float s = 0.f;
        for (int p = 0; p < CS_; p++)
            s += h[(size_t)(b * S_ + c * CS_ + p) * H_ + d] * msk[p];
        avg[(size_t)(b * NC_ + c) * H_ + d] = s * inv;
    }
}

// ---- topk ----
__global__ void __launch_bounds__(512)
topk_kernel(const float* __restrict__ qe, const float* __restrict__ cenc,
            unsigned* __restrict__ sel) {
    int s = blockIdx.x, b = blockIdx.y;
    int tid = threadIdx.x, warp = tid >> 5, lane = tid & 31;
    __shared__ float sc[NC_];
    const float* q = qe + (size_t)(b * S_ + s) * H_;
    const float* c = cenc + (size_t)(b * NC_ + warp) * H_;
    float d = 0.f;
    for (int e = lane; e < H_; e += 32) d += q[e] * c[e];
    d = warpSum(d);
    if (lane == 0) sc[warp] = d;
    __syncthreads();
    if (tid == 0) {
        unsigned chosen = 0;
        for (int t = 0; t < TOPK_; t++) {
            float best = -INFINITY;
            int bi = 0;
            for (int cc = 0; cc < NC_; cc++)
                if (!((chosen >> cc) & 1u) && sc[cc] > best) { best = sc[cc]; bi = cc; }
            chosen |= 1u << bi;
        }
        sel[b * S_ + s] = chosen;
    }
}

// ---- LayerNorm ----
__global__ void ln_kernel(const float* __restrict__ x, const float* __restrict__ g,
                          const float* __restrict__ bt, float* __restrict__ y) {
    int r = blockIdx.x;
    int tid = threadIdx.x, warp = tid >> 5, lane = tid & 31;
    const float* xr = x + (size_t)r * H_;
    float s = 0.f, sq = 0.f;
    for (int e = tid; e < H_; e += 256) {
        float v = xr[e];
        s += v; sq += v * v;
    }
    __shared__ float rs[8], rq[8];
    __shared__ float s_mean, s_rstd;
    s = warpSum(s); sq = warpSum(sq);
    if (lane == 0) { rs[warp] = s; rq[warp] = sq; }
    __syncthreads();
    if (tid == 0) {
        float Sm = 0.f, Q = 0.f;
        for (int ww = 0; ww < 8; ww++) { Sm += rs[ww]; Q += rq[ww]; }
        float mean = Sm / (float)H_;
        float var = Q / (float)H_ - mean * mean;
        s_mean = mean;
        s_rstd = rsqrtf(var + 1e-5f);
    }
    __syncthreads();
    float mean = s_mean, rstd = s_rstd;
    float* yr = y + (size_t)r * H_;
    for (int e = tid; e < H_; e += 256)
        yr[e] = (xr[e] - mean) * rstd * g[e] + bt[e];
}

// ---- sparse chunk attention ----
__global__ void __launch_bounds__(128)
attn_kernel(const float* __restrict__ q, const float* __restrict__ k,
            const float* __restrict__ v, const unsigned* __restrict__ sel,
            const int* __restrict__ ids, float* __restrict__ out) {
    int s = blockIdx.x, head = blockIdx.y, b = blockIdx.z;
    int tid = threadIdx.x, warp = tid >> 5, lane = tid & 31;
    __shared__ float qv[HD_];
    __shared__ float sc[CS_];
    __shared__ float red[4];
    __shared__ float bcast[2];

    size_t qoff = (size_t)(b * S_ + s) * H_ + head * HD_;
    qv[tid] = q[qoff + tid];
    __syncthreads();
    float4 q4 = *(const float4*)&qv[lane * 4];

    unsigned msk = sel[b * S_ + s];
    float m = -INFINITY, l = 0.f, acc = 0.f;

    for (int c = 0; c < NC_; c++) {
        if (!((msk >> c) & 1u)) continue;
        int j0 = c * CS_;
        for (int kk = 0; kk < 32; kk++) {
            int j = j0 + warp * 32 + kk;
            const float4 kv = *(const float4*)&k[(size_t)(b * S_ + j) * H_ + head * HD_ + lane * 4];
            float d = q4.x * kv.x + q4.y * kv.y + q4.z * kv.z + q4.w * kv.w;
            d = warpSum(d);
            if (lane == 0) sc[warp * 32 + kk] = d;
        }
        __syncthreads();
        float scv = sc[tid] * SCALE_;
        if (ids[b * S_ + j0 + tid] == 0) scv = -INFINITY;
        float wm = warpMax(scv);
        if (lane == 0) red[warp] = wm;
        __syncthreads();
        if (tid == 0) bcast[0] = fmaxf(fmaxf(red[0], red[1]), fmaxf(red[2], red[3]));
        __syncthreads();
        float newm = fmaxf(m, bcast[0]);
        float p = expf(scv - newm);
        sc[tid] = p;
        float ws = warpSum(p);
        if (lane == 0) red[warp] = ws;
        __syncthreads();
        if (tid == 0) bcast[1] = red[0] + red[1] + red[2] + red[3];
        __syncthreads();
        float f = expf(m - newm);
        l = l * f + bcast[1];
        // PV: 4 independent partials to break the FMA dependency chain
        const float* vb = v + (size_t)(b * S_ + j0) * H_ + head * HD_ + tid;
        float a0 = 0.f, a1 = 0.f, a2 = 0.f, a3 = 0.f;
        #pragma unroll 8
        for (int j = 0; j < CS_; j += 4) {
            a0 += sc[j + 0] * vb[(size_t)(j + 0) * H_];
            a1 += sc[j + 1] * vb[(size_t)(j + 1) * H_];
            a2 += sc[j + 2] * vb[(size_t)(j + 2) * H_];
            a3 += sc[j + 3] * vb[(size_t)(j + 3) * H_];
        }
        acc = acc * f + ((a0 + a1) + (a2 + a3));
        m = newm;
        __syncthreads();
    }
    out[qoff + tid] = acc / l;
}

// ---- host ----
static __nv_bfloat16 *s_A0, *s_A1, *s_W0, *s_W1;

static inline void cvtA(const float* A, int n) {
    cvt_split2_kernel<<<(n / 4 + 255) / 256, 256>>>(A, s_A0, s_A1, n);
}
static inline void run_gemm(const float* W, const float* bias, const float* res,
                            float* C, int M, int K, int N, int act, int hi) {
    cvt_t2_kernel<<<dim3(N / 32, K / 32), dim3(32, 8)>>>(W, s_W0, s_W1, K, N);
    dim3 grid(N / 256, (M + 127) / 128);
    if (hi)
        gemm_tc_kernel<4><<<grid, 256, GSMEM>>>(s_A0, s_A1, s_W0, s_W1, bias, res, C, M, K, N, act);
    else
        gemm_tc_kernel<3><<<grid, 256, GSMEM>>>(s_A0, s_A1, s_W0, s_W1, bias, res, C, M, K, N, act);
}

extern "C" void kernel_launch(void* const* d_in, const int* in_sizes, int n_in,
                              void* d_out, int out_size) {
    const int*   ids     = (const int*)  d_in[0];
    const float* tok_emb = (const float*)d_in[1];
    const float* pos_emb = (const float*)d_in[2];
    const float* in_w    = (const float*)d_in[3];
    const float* in_b    = (const float*)d_in[4];
    const float* ch_w1   = (const float*)d_in[5];
    const float* ch_b1   = (const float*)d_in[6];
    const float* ch_w2   = (const float*)d_in[7];
    const float* ch_b2   = (const float*)d_in[8];
    const float* qe_w1   = (const float*)d_in[9];
    const float* qe_b1   = (const float*)d_in[10];
    const float* qe_w2   = (const float*)d_in[11];
    const float* qe_b2   = (const float*)d_in[12];
    const float* q_w     = (const float*)d_in[13];
    const float* q_b     = (const float*)d_in[14];
    const float* k_w     = (const float*)d_in[15];
    const float* k_b     = (const float*)d_in[16];
    const float* v_w     = (const float*)d_in[17];
    const float* v_b     = (const float*)d_in[18];
    const float* o_w     = (const float*)d_in[19];
    const float* o_b     = (const float*)d_in[20];
    const float* f_w1    = (const float*)d_in[21];
    const float* f_b1    = (const float*)d_in[22];
    const float* f_w2    = (const float*)d_in[23];
    const float* f_b2    = (const float*)d_in[24];
    const float* ln1_g   = (const float*)d_in[25];
    const float* ln1_b   = (const float*)d_in[26];
    const float* ln2_g   = (const float*)d_in[27];
    const float* ln2_b   = (const float*)d_in[28];
    const float* out_w   = (const float*)d_in[29];
    const float* out_b   = (const float*)d_in[30];
    float* logits = (float*)d_out;

    cudaFuncSetAttribute(gemm_tc_kernel<4>, cudaFuncAttributeMaxDynamicSharedMemorySize, GSMEM);
    cudaFuncSetAttribute(gemm_tc_kernel<3>, cudaFuncAttributeMaxDynamicSharedMemorySize, GSMEM);

    float *h, *x, *q, *k, *v, *ao, *mid, *avg, *cmid, *cenc;
    unsigned* sel;
    cudaGetSymbolAddress((void**)&h,    g_h);
    cudaGetSymbolAddress((void**)&x,    g_x);
    cudaGetSymbolAddress((void**)&q,    g_q);
    cudaGetSymbolAddress((void**)&k,    g_k);
    cudaGetSymbolAddress((void**)&v,    g_v);
    cudaGetSymbolAddress((void**)&ao,   g_ao);
    cudaGetSymbolAddress((void**)&mid,  g_mid);
    cudaGetSymbolAddress((void**)&avg,  g_avg);
    cudaGetSymbolAddress((void**)&cmid, g_cmid);
    cudaGetSymbolAddress((void**)&cenc, g_cenc);
    cudaGetSymbolAddress((void**)&sel,  g_sel);
    cudaGetSymbolAddress((void**)&s_A0, g_A0);
    cudaGetSymbolAddress((void**)&s_A1, g_A1);
    cudaGetSymbolAddress((void**)&s_W0, g_W0);
    cudaGetSymbolAddress((void**)&s_W1, g_W1);

    embed_kernel<<<R_, 256>>>(ids, tok_emb, pos_emb, x);
    cvtA(x, R_ * E_);
    run_gemm(in_w, in_b, nullptr, h, R_, E_, H_, 0, 1);

    chunk_avg_kernel<<<dim3(NC_, B_), 256>>>(h, ids, avg);
    cvtA(avg, B_ * NC_ * H_);
    run_gemm(ch_w1, ch_b1, nullptr, cmid, B_ * NC_, H_, HH_, 1, 1);
    cvtA(cmid, B_ * NC_ * HH_);
    run_gemm(ch_w2, ch_b2, nullptr, cenc, B_ * NC_, HH_, H_, 0, 1);

    for (int i = 0; i < L_; i++) {
        // selection path: hi (fp32-equivalent 4-product)
        cvtA(h, R_ * H_);
        run_gemm(qe_w1, qe_b1, nullptr, mid, R_, H_, HH_, 1, 1);
        cvtA(mid, R_ * HH_);
        run_gemm(qe_w2, qe_b2, nullptr, x, R_, HH_, H_, 0, 1);
        topk_kernel<<<dim3(S_, B_), 512>>>(x, cenc, sel);

        // layer-1 post-selection GEMMs only feed logits -> 3-product
        int hi = (i == 0) ? 1 : 0;
        ln_kernel<<<R_, 256>>>(h, ln1_g + i * H_, ln1_b + i * H_, x);
        cvtA(x, R_ * H_);
        run_gemm(q_w + (size_t)i * H_ * H_, q_b + i * H_, nullptr, q, R_, H_, H_, 0, hi);
        run_gemm(k_w + (size_t)i * H_ * H_, k_b + i * H_, nullptr, k, R_, H_, H_, 0, hi);
        run_gemm(v_w + (size_t)i * H_ * H_, v_b + i * H_, nullptr, v, R_, H_, H_, 0, hi);
        attn_kernel<<<dim3(S_, NH_, B_), 128>>>(q, k, v, sel, ids, ao);
        cvtA(ao, R_ * H_);
        run_gemm(o_w + (size_t)i * H_ * H_, o_b + i * H_, h, h, R_, H_, H_, 0, hi);

        ln_kernel<<<R_, 256>>>(h, ln2_g + i * H_, ln2_b + i * H_, x);
        cvtA(x, R_ * H_);
        run_gemm(f_w1 + (size_t)i * H_ * FF_, f_b1 + i * FF_, nullptr, mid, R_, H_, FF_, 2, hi);
        cvtA(mid, R_ * FF_);
        run_gemm(f_w2 + (size_t)i * FF_ * H_, f_b2 + i * H_, h, h, R_, FF_, H_, 0, hi);
    }

    cvtA(h, R_ * H_);
    run_gemm(out_w, out_b, nullptr, logits, R_, H_, V_, 0, 0);
}

// round 8
// speedup vs baseline: 1.9608x; 1.1552x over previous
#include <cuda_runtime.h>
#include <cuda_bf16.h>
#include <math.h>
#include <stdint.h>

#define B_  2
#define S_  2048
#define E_  1024
#define H_  1024
#define NH_ 8
#define HD_ 128
#define L_  2
#define V_  32000
#define CS_ 128
#define NC_ 16
#define TOPK_ 8
#define R_  (B_ * S_)
#define FF_ (4 * H_)
#define HH_ (H_ / 2)
#define SCALE_ 0.08838834764831843f

// ---- scratch ----
__device__ __align__(16) float g_h  [R_ * H_];
__device__ __align__(16) float g_x  [R_ * H_];
__device__ __align__(16) float g_q  [R_ * H_];
__device__ __align__(16) float g_k  [R_ * H_];
__device__ __align__(16) float g_v  [R_ * H_];
__device__ __align__(16) float g_ao [R_ * H_];
__device__ __align__(16) float g_mid[R_ * FF_];
__device__ __align__(16) float g_avg [B_ * NC_ * H_];
__device__ __align__(16) float g_cmid[B_ * NC_ * HH_];
__device__ __align__(16) float g_cenc[B_ * NC_ * H_];
__device__ unsigned g_sel[R_];
__device__ __align__(16) __nv_bfloat16 g_A0[4096 * 4096];
__device__ __align__(16) __nv_bfloat16 g_A1[4096 * 4096];
__device__ __align__(16) __nv_bfloat16 g_W0[32000 * 1024];
__device__ __align__(16) __nv_bfloat16 g_W1[32000 * 1024];
__device__ __align__(16) __nv_bfloat16 g_at0[3 * R_ * H_];
__device__ __align__(16) __nv_bfloat16 g_at1[3 * R_ * H_];

// ---- helpers ----
__device__ __forceinline__ float warpSum(float v) {
    #pragma unroll
    for (int o = 16; o > 0; o >>= 1) v += __shfl_xor_sync(0xffffffffu, v, o);
    return v;
}
__device__ __forceinline__ uint32_t smem_u32(const void* p) {
    uint32_t a;
    asm("{ .reg .u64 t; cvta.to.shared.u64 t, %1; cvt.u32.u64 %0, t; }" : "=r"(a) : "l"(p));
    return a;
}
#define CPA(d, s) asm volatile("cp.async.cg.shared.global [%0], [%1], 16;" :: "r"(d), "l"(s))
#define CPA_COMMIT() asm volatile("cp.async.commit_group;" ::: "memory")
#define CPA_WAIT0()  asm volatile("cp.async.wait_group 0;" ::: "memory")
#define CPA_WAIT1()  asm volatile("cp.async.wait_group 1;" ::: "memory")

#define LDSM_X4(r0, r1, r2, r3, a) \
    asm volatile("ldmatrix.sync.aligned.m8n8.x4.shared.b16 {%0,%1,%2,%3}, [%4];" \
        : "=r"(r0), "=r"(r1), "=r"(r2), "=r"(r3) : "r"(a))
#define LDSM_X4T(r0, r1, r2, r3, a) \
    asm volatile("ldmatrix.sync.aligned.m8n8.x4.trans.shared.b16 {%0,%1,%2,%3}, [%4];" \
        : "=r"(r0), "=r"(r1), "=r"(r2), "=r"(r3) : "r"(a))

#define MMA_BF16(c, a, b) \
    asm volatile("mma.sync.aligned.m16n8k16.row.col.f32.bf16.bf16.f32 " \
        "{%0,%1,%2,%3}, {%4,%5,%6,%7}, {%8,%9}, {%0,%1,%2,%3};" \
        : "+f"((c)[0]), "+f"((c)[1]), "+f"((c)[2]), "+f"((c)[3]) \
        : "r"((a)[0]), "r"((a)[1]), "r"((a)[2]), "r"((a)[3]), "r"((b)[0]), "r"((b)[1]))

__device__ __forceinline__ uint32_t packbf(float lo, float hi) {
    __nv_bfloat162 t = __floats2bfloat162_rn(lo, hi);
    return *(uint32_t*)&t;
}

// ---- embedding ----
__global__ void embed_kernel(const int* __restrict__ ids, const float* __restrict__ tok,
                             const float* __restrict__ pos, float* __restrict__ out) {
    int r = blockIdx.x;
    int id = ids[r];
    const float* t = tok + (size_t)id * E_;
    const float* p = pos + (size_t)(r % S_) * E_;
    float* o = out + (size_t)r * E_;
    for (int e = threadIdx.x; e < E_; e += blockDim.x) o[e] = t[e] + p[e];
}

// ---- fp32 -> 2-way bf16 split ----
__global__ void cvt_split2_kernel(const float* __restrict__ a, __nv_bfloat16* __restrict__ o0,
                                  __nv_bfloat16* __restrict__ o1, int n) {
    int i = (blockIdx.x * blockDim.x + threadIdx.x) * 4;
    if (i >= n) return;
    float4 v = *(const float4*)(a + i);
    union { __nv_bfloat16 b[4]; uint2 u; } U0, U1;
    float f[4] = {v.x, v.y, v.z, v.w};
    #pragma unroll
    for (int j = 0; j < 4; j++) {
        __nv_bfloat16 b0 = __float2bfloat16_rn(f[j]);
        U0.b[j] = b0;
        U1.b[j] = __float2bfloat16_rn(f[j] - __bfloat162float(b0));
    }
    *(uint2*)(o0 + i) = U0.u;
    *(uint2*)(o1 + i) = U1.u;
}

// ---- fp32 W[K,N] -> 2-way split W^T[N,K] ----
__global__ void cvt_t2_kernel(const float* __restrict__ w, __nv_bfloat16* __restrict__ o0,
                              __nv_bfloat16* __restrict__ o1, int Kd, int Nd) {
    __shared__ float t[32][33];
    int n0 = blockIdx.x * 32, k0 = blockIdx.y * 32;
    int tx = threadIdx.x, ty = threadIdx.y;
    #pragma unroll
    for (int i = 0; i < 32; i += 8)
        t[ty + i][tx] = w[(size_t)(k0 + ty + i) * Nd + n0 + tx];
    __syncthreads();
    #pragma unroll
    for (int i = 0; i < 32; i += 8) {
        float v = t[tx][ty + i];
        __nv_bfloat16 b0 = __float2bfloat16_rn(v);
        size_t o = (size_t)(n0 + ty + i) * Kd + k0 + tx;
        o0[o] = b0;
        o1[o] = __float2bfloat16_rn(v - __bfloat162float(b0));
    }
}

// ---- HMMA split-bf16 GEMM (3-stage pipeline) ----
#define SK 40
#define A_MAT (128 * SK * 2)
#define B_MAT (256 * SK * 2)
#define STG (2 * A_MAT + 2 * B_MAT)
#define GSMEM (3 * STG)     // 184320

template<int NP>
__global__ void __launch_bounds__(256)
gemm_tc_kernel(const __nv_bfloat16* __restrict__ A0, const __nv_bfloat16* __restrict__ A1,
               const __nv_bfloat16* __restrict__ B0, const __nv_bfloat16* __restrict__ B1,
               const float* __restrict__ bias, const float* __restrict__ res,
               float* __restrict__ C, int M, int K, int N, int act) {
    extern __shared__ char smem[];
    const uint32_t sb = smem_u32(smem);
    const int tid = threadIdx.x, lane = tid & 31;
    const int w = tid >> 5, wm = w >> 2, wn = w & 3;
    const int m0 = blockIdx.y * 128, n0 = blockIdx.x * 256;

    float c[4][8][4];
    #pragma unroll
    for (int i = 0; i < 4; i++)
        #pragma unroll
        for (int j = 0; j < 8; j++)
            #pragma unroll
            for (int e = 0; e < 4; e++) c[i][j][e] = 0.f;

    int arow[2], aseg[2], agrow[2];
    #pragma unroll
    for (int i = 0; i < 2; i++) {
        int idx = tid + i * 256;
        arow[i] = idx >> 2;
        aseg[i] = idx & 3;
        int ar = m0 + arow[i];
        agrow[i] = ar < M ? ar : (M - 1);
    }

    auto issue_stage = [&](int kb, int st) {
        size_t gk = (size_t)kb * 32;
        uint32_t stb = sb + st * STG;
        #pragma unroll
        for (int i = 0; i < 2; i++) {
            uint32_t d = stb + (arow[i] * SK + aseg[i] * 8) * 2;
            size_t o = (size_t)agrow[i] * K + gk + aseg[i] * 8;
            CPA(d, A0 + o);
            CPA(d + A_MAT, A1 + o);
        }
        #pragma unroll
        for (int i = 0; i < 4; i++) {
            int idx = tid + i * 256;
            int r = idx >> 2, sg = idx & 3;
            uint32_t d = stb + 2 * A_MAT + (r * SK + sg * 8) * 2;
            size_t o = (size_t)(n0 + r) * K + gk + sg * 8;
            CPA(d, B0 + o);
            CPA(d + B_MAT, B1 + o);
        }
        CPA_COMMIT();
    };

    const int nkb = K >> 5;
    issue_stage(0, 0);
    if (nkb > 1) issue_stage(1, 1);

    const uint32_t a_off = ((wm * 64 + (lane & 15)) * SK + ((lane >> 4) << 3)) * 2;
    const uint32_t b_off = ((wn * 64 + (lane & 7) + ((lane >> 4) << 3)) * SK + (((lane >> 3) & 1) << 3)) * 2;
    const int pa[4] = {0, 0, 1, 1};
    const int pb[4] = {0, 1, 0, 1};

    for (int kb = 0; kb < nkb; kb++) {
        if (kb + 1 < nkb) CPA_WAIT1(); else CPA_WAIT0();
        __syncthreads();
        uint32_t base = sb + (kb % 3) * STG;
        #pragma unroll
        for (int kk = 0; kk < 2; kk++) {
            uint32_t af[2][4][4];
            #pragma unroll
            for (int s = 0; s < 2; s++)
                #pragma unroll
                for (int mt = 0; mt < 4; mt++) {
                    uint32_t ad = base + s * A_MAT + a_off + kk * 32 + mt * 16 * SK * 2;
                    LDSM_X4(af[s][mt][0], af[s][mt][1], af[s][mt][2], af[s][mt][3], ad);
                }
            uint32_t bf[2][2][4];
            #pragma unroll
            for (int s = 0; s < 2; s++) {
                uint32_t bd = base + 2 * A_MAT + s * B_MAT + b_off + kk * 32;
                LDSM_X4(bf[0][s][0], bf[0][s][1], bf[0][s][2], bf[0][s][3], bd);
            }
            #pragma unroll
            for (int nt2 = 0; nt2 < 4; nt2++) {
                int cur = nt2 & 1, nxt = cur ^ 1;
                if (nt2 < 3) {
                    #pragma unroll
                    for (int s = 0; s < 2; s++) {
                        uint32_t bd = base + 2 * A_MAT + s * B_MAT + b_off + kk * 32 + (nt2 + 1) * 16 * SK * 2;
                        LDSM_X4(bf[nxt][s][0], bf[nxt][s][1], bf[nxt][s][2], bf[nxt][s][3], bd);
                    }
                }
                #pragma unroll
                for (int p = 0; p < NP; p++)
                    #pragma unroll
                    for (int mt = 0; mt < 4; mt++)
                        #pragma unroll
                        for (int half = 0; half < 2; half++)
                            MMA_BF16(c[mt][nt2 * 2 + half], af[pa[p]][mt], bf[cur][pb[p]] + half * 2);
            }
        }
        if (kb + 2 < nkb) issue_stage(kb + 2, (kb + 2) % 3);
    }

    const int grp = lane >> 2, tig = lane & 3;
    #pragma unroll
    for (int mt = 0; mt < 4; mt++) {
        #pragma unroll
        for (int nt = 0; nt < 8; nt++) {
            int col = n0 + wn * 64 + nt * 8 + tig * 2;
            float b0 = bias[col], b1 = bias[col + 1];
            #pragma unroll
            for (int hrow = 0; hrow < 2; hrow++) {
                int row = m0 + wm * 64 + mt * 16 + grp + hrow * 8;
                if (row >= M) continue;
                float vx = c[mt][nt][hrow * 2 + 0] + b0;
                float vy = c[mt][nt][hrow * 2 + 1] + b1;
                if (act == 1) {
                    vx = fmaxf(vx, 0.f); vy = fmaxf(vy, 0.f);
                } else if (act == 2) {
                    vx = 0.5f * vx * (1.f + erff(vx * 0.7071067811865475f));
                    vy = 0.5f * vy * (1.f + erff(vy * 0.7071067811865475f));
                }
                size_t off = (size_t)row * N + col;
                if (res) {
                    float2 r = *(const float2*)(res + off);
                    vx += r.x; vy += r.y;
                }
                float2 o; o.x = vx; o.y = vy;
                *(float2*)(C + off) = o;
            }
        }
    }
}

// ---- chunk mean ----
__global__ void chunk_avg_kernel(const float* __restrict__ h, const int* __restrict__ ids,
                                 float* __restrict__ avg) {
    int c = blockIdx.x, b = blockIdx.y;
    __shared__ float msk[CS_];
    __shared__ float s_cnt;
    int tid = threadIdx.x;
    if (tid < CS_) msk[tid] = (ids[b * S_ + c * CS_ + tid] != 0) ? 1.f : 0.f;
    __syncthreads();
    if (tid == 0) {
        float cn = 0.f;
        for (int p = 0; p < CS_; p++) cn += msk[p];
        s_cnt = cn;
    }
    __syncthreads();
    float inv = 1.f / (s_cnt + 1e-10f);
    for (int d = tid; d < H_; d += blockDim.x) {
        float s = 0.f;
        for (int p = 0; p < CS_; p++)
            s += h[(size_t)(b * S_ + c * CS_ + p) * H_ + d] * msk[p];
        avg[(size_t)(b * NC_ + c) * H_ + d] = s * inv;
    }
}

// ---- topk ----
__global__ void __launch_bounds__(512)
topk_kernel(const float* __restrict__ qe, const float* __restrict__ cenc,
            unsigned* __restrict__ sel) {
    int s = blockIdx.x, b = blockIdx.y;
    int tid = threadIdx.x, warp = tid >> 5, lane = tid & 31;
    __shared__ float sc[NC_];
    const float* q = qe + (size_t)(b * S_ + s) * H_;
    const float* c = cenc + (size_t)(b * NC_ + warp) * H_;
    float d = 0.f;
    for (int e = lane; e < H_; e += 32) d += q[e] * c[e];
    d = warpSum(d);
    if (lane == 0) sc[warp] = d;
    __syncthreads();
    if (tid == 0) {
        unsigned chosen = 0;
        for (int t = 0; t < TOPK_; t++) {
            float best = -INFINITY;
            int bi = 0;
            for (int cc = 0; cc < NC_; cc++)
                if (!((chosen >> cc) & 1u) && sc[cc] > best) { best = sc[cc]; bi = cc; }
            chosen |= 1u << bi;
        }
        sel[b * S_ + s] = chosen;
    }
}

// ---- LayerNorm ----
__global__ void ln_kernel(const float* __restrict__ x, const float* __restrict__ g,
                          const float* __restrict__ bt, float* __restrict__ y) {
    int r = blockIdx.x;
    int tid = threadIdx.x, warp = tid >> 5, lane = tid & 31;
    const float* xr = x + (size_t)r * H_;
    float s = 0.f, sq = 0.f;
    for (int e = tid; e < H_; e += 256) {
        float v = xr[e];
        s += v; sq += v * v;
    }
    __shared__ float rs[8], rq[8];
    __shared__ float s_mean, s_rstd;
    s = warpSum(s); sq = warpSum(sq);
    if (lane == 0) { rs[warp] = s; rq[warp] = sq; }
    __syncthreads();
    if (tid == 0) {
        float Sm = 0.f, Q = 0.f;
        for (int ww = 0; ww < 8; ww++) { Sm += rs[ww]; Q += rq[ww]; }
        float mean = Sm / (float)H_;
        float var = Q / (float)H_ - mean * mean;
        s_mean = mean;
        s_rstd = rsqrtf(var + 1e-5f);
    }
    __syncthreads();
    float mean = s_mean, rstd = s_rstd;
    float* yr = y + (size_t)r * H_;
    for (int e = tid; e < H_; e += 256)
        yr[e] = (xr[e] - mean) * rstd * g[e] + bt[e];
}

// ---- HMMA sparse chunk attention ----
// Block = (16 queries, head, b). Streams union-of-masks chunks through smem.
// Softmax computed without max subtraction (scores are tiny) -> single pass.
// All operands split-bf16 with 4 products => fp32-equivalent.
#define AST 136                    // row stride in bf16 elems (272B)
#define KOFF0 0
#define KOFF1 34816
#define VOFF0 69632
#define VOFF1 104448
#define QOFF0 139264
#define QOFF1 143616
#define NOFF  147968               // num: 16x128 fp32
#define DOFF  156160               // den: 16 fp32
#define ASMEM 156224

__global__ void __launch_bounds__(128)
attn_kernel(const __nv_bfloat16* __restrict__ gq0, const __nv_bfloat16* __restrict__ gq1,
            const __nv_bfloat16* __restrict__ gk0, const __nv_bfloat16* __restrict__ gk1,
            const __nv_bfloat16* __restrict__ gv0, const __nv_bfloat16* __restrict__ gv1,
            const unsigned* __restrict__ sel, float* __restrict__ out) {
    extern __shared__ char sm[];
    const uint32_t sb = smem_u32(sm);
    const int tid = threadIdx.x, lane = tid & 31, w = tid >> 5;
    const int head = blockIdx.y, b = blockIdx.z;
    const int s0 = blockIdx.x * 16;
    float* num = (float*)(sm + NOFF);
    float* den = (float*)(sm + DOFF);
    __shared__ unsigned smask[16];
    __shared__ unsigned s_union;

    for (int i = tid; i < 16 * 128; i += 128) num[i] = 0.f;
    if (tid < 16) { smask[tid] = sel[b * S_ + s0 + tid]; den[tid] = 0.f; }
    __syncthreads();
    if (tid == 0) {
        unsigned u = 0;
        for (int i = 0; i < 16; i++) u |= smask[i];
        s_union = u;
    }
    // load Q (16 rows x 128 dims x 2 splits)
    {
        int row = tid >> 3, sp = tid & 7;
        size_t src = ((size_t)(b * S_ + s0 + row)) * H_ + head * HD_ + sp * 16;
        uint32_t d = row * (AST * 2) + sp * 32;
        CPA(sb + QOFF0 + d,      gq0 + src);
        CPA(sb + QOFF0 + d + 16, gq0 + src + 8);
        CPA(sb + QOFF1 + d,      gq1 + src);
        CPA(sb + QOFF1 + d + 16, gq1 + src + 8);
    }
    CPA_COMMIT();
    CPA_WAIT0();
    __syncthreads();

    // preload Q A-fragments (resident)
    uint32_t qf[2][8][4];
    const uint32_t qa = (lane & 15) * (AST * 2) + ((lane >> 4) << 4);
    #pragma unroll
    for (int s = 0; s < 2; s++)
        #pragma unroll
        for (int ks = 0; ks < 8; ks++) {
            uint32_t ad = sb + (s ? QOFF1 : QOFF0) + qa + ks * 32;
            LDSM_X4(qf[s][ks][0], qf[s][ks][1], qf[s][ks][2], qf[s][ks][3], ad);
        }

    float oacc[16][4];
    #pragma unroll
    for (int t = 0; t < 16; t++)
        #pragma unroll
        for (int e = 0; e < 4; e++) oacc[t][e] = 0.f;

    const unsigned um = s_union;
    const int r0 = lane >> 2, r1 = r0 + 8;
    const uint32_t kb_off = (w * 32 + (lane & 7) + ((lane >> 4) << 3)) * (AST * 2) + (((lane >> 3) & 1) << 4);
    const uint32_t vb_off = (w * 32 + (lane & 15)) * (AST * 2) + ((lane >> 4) << 4);

    for (int c = 0; c < NC_; c++) {
        if (!((um >> c) & 1u)) continue;
        int j0 = c * CS_;
        // load K,V chunk (bf16 splits), row per thread
        {
            size_t src = ((size_t)(b * S_ + j0 + tid)) * H_ + head * HD_;
            uint32_t d = tid * (AST * 2);
            #pragma unroll
            for (int g = 0; g < 16; g++) {
                CPA(sb + KOFF0 + d + g * 16, gk0 + src + g * 8);
                CPA(sb + KOFF1 + d + g * 16, gk1 + src + g * 8);
                CPA(sb + VOFF0 + d + g * 16, gv0 + src + g * 8);
                CPA(sb + VOFF1 + d + g * 16, gv1 + src + g * 8);
            }
        }
        CPA_COMMIT();
        CPA_WAIT0();
        __syncthreads();

        // scores: S(16x32) per warp, 4 products
        float sc[4][4];
        #pragma unroll
        for (int t = 0; t < 4; t++)
            #pragma unroll
            for (int e = 0; e < 4; e++) sc[t][e] = 0.f;
        #pragma unroll
        for (int ks = 0; ks < 8; ks++) {
            uint32_t kfA0[4], kfA1[4], kfB0[4], kfB1[4];
            LDSM_X4(kfA0[0], kfA0[1], kfA0[2], kfA0[3], sb + KOFF0 + kb_off + ks * 32);
            LDSM_X4(kfB0[0], kfB0[1], kfB0[2], kfB0[3], sb + KOFF0 + kb_off + 16 * AST * 2 + ks * 32);
            LDSM_X4(kfA1[0], kfA1[1], kfA1[2], kfA1[3], sb + KOFF1 + kb_off + ks * 32);
            LDSM_X4(kfB1[0], kfB1[1], kfB1[2], kfB1[3], sb + KOFF1 + kb_off + 16 * AST * 2 + ks * 32);
            #pragma unroll
            for (int qs = 0; qs < 2; qs++) {
                uint32_t* a = qf[qs][ks];
                MMA_BF16(sc[0], a, kfA0 + 0); MMA_BF16(sc[1], a, kfA0 + 2);
                MMA_BF16(sc[2], a, kfB0 + 0); MMA_BF16(sc[3], a, kfB0 + 2);
                MMA_BF16(sc[0], a, kfA1 + 0); MMA_BF16(sc[1], a, kfA1 + 2);
                MMA_BF16(sc[2], a, kfB1 + 0); MMA_BF16(sc[3], a, kfB1 + 2);
            }
        }
        // mask + exp + den + pack P (split)
        bool m0 = (smask[r0] >> c) & 1u, m1 = (smask[r1] >> c) & 1u;
        float d0 = 0.f, d1 = 0.f;
        uint32_t pf[2][2][4];   // [k16 group][split][frag]
        #pragma unroll
        for (int t = 0; t < 4; t++) {
            float e0 = m0 ? expf(sc[t][0] * SCALE_) : 0.f;
            float e1 = m0 ? expf(sc[t][1] * SCALE_) : 0.f;
            float e2 = m1 ? expf(sc[t][2] * SCALE_) : 0.f;
            float e3 = m1 ? expf(sc[t][3] * SCALE_) : 0.f;
            d0 += e0 + e1; d1 += e2 + e3;
            float h0 = __bfloat162float(__float2bfloat16_rn(e0));
            float h1 = __bfloat162float(__float2bfloat16_rn(e1));
            float h2 = __bfloat162float(__float2bfloat16_rn(e2));
            float h3 = __bfloat162float(__float2bfloat16_rn(e3));
            int g = t >> 1, o = (t & 1) * 2;
            pf[g][0][o + 0] = packbf(h0, h1);
            pf[g][0][o + 1] = packbf(h2, h3);
            pf[g][1][o + 0] = packbf(e0 - h0, e1 - h1);
            pf[g][1][o + 1] = packbf(e2 - h2, e3 - h3);
        }
        d0 += __shfl_xor_sync(0xffffffffu, d0, 1);
        d0 += __shfl_xor_sync(0xffffffffu, d0, 2);
        d1 += __shfl_xor_sync(0xffffffffu, d1, 1);
        d1 += __shfl_xor_sync(0xffffffffu, d1, 2);
        if ((lane & 3) == 0) {
            atomicAdd(&den[r0], d0);
            atomicAdd(&den[r1], d1);
        }
        // PV: out(16x128) partial over this warp's 32 keys, 4 products
        #pragma unroll
        for (int dg = 0; dg < 8; dg++) {
            #pragma unroll
            for (int kg = 0; kg < 2; kg++) {
                uint32_t vf0[4], vf1[4];
                LDSM_X4T(vf0[0], vf0[1], vf0[2], vf0[3], sb + VOFF0 + vb_off + kg * 16 * AST * 2 + dg * 32);
                LDSM_X4T(vf1[0], vf1[1], vf1[2], vf1[3], sb + VOFF1 + vb_off + kg * 16 * AST * 2 + dg * 32);
                #pragma unroll
                for (int ps = 0; ps < 2; ps++) {
                    uint32_t* a = pf[kg][ps];
                    MMA_BF16(oacc[2 * dg + 0], a, vf0 + 0);
                    MMA_BF16(oacc[2 * dg + 1], a, vf0 + 2);
                    MMA_BF16(oacc[2 * dg + 0], a, vf1 + 0);
                    MMA_BF16(oacc[2 * dg + 1], a, vf1 + 2);
                }
            }
        }
        __syncthreads();
    }

    // cross-warp reduce num
    for (int ww = 0; ww < 4; ww++) {
        if (w == ww) {
            #pragma unroll
            for (int t = 0; t < 16; t++) {
                int dbase = 8 * t + 2 * (lane & 3);
                num[r0 * 128 + dbase + 0] += oacc[t][0];
                num[r0 * 128 + dbase + 1] += oacc[t][1];
                num[r1 * 128 + dbase + 0] += oacc[t][2];
                num[r1 * 128 + dbase + 1] += oacc[t][3];
            }
        }
        __syncthreads();
    }
    // write out
    for (int r = 0; r < 16; r++) {
        float dv = den[r];
        out[((size_t)(b * S_ + s0 + r)) * H_ + head * HD_ + tid] = num[r * 128 + tid] / dv;
    }
}

// ---- host ----
static __nv_bfloat16 *s_A0, *s_A1, *s_W0, *s_W1, *s_at0, *s_at1;

static inline void cvtA(const float* A, int n) {
    cvt_split2_kernel<<<(n / 4 + 255) / 256, 256>>>(A, s_A0, s_A1, n);
}
static inline void run_gemm(const float* W, const float* bias, const float* res,
                            float* C, int M, int K, int N, int act, int hi) {
    cvt_t2_kernel<<<dim3(N / 32, K / 32), dim3(32, 8)>>>(W, s_W0, s_W1, K, N);
    dim3 grid(N / 256, (M + 127) / 128);
    if (hi)
        gemm_tc_kernel<4><<<grid, 256, GSMEM>>>(s_A0, s_A1, s_W0, s_W1, bias, res, C, M, K, N, act);
    else
        gemm_tc_kernel<3><<<grid, 256, GSMEM>>>(s_A0, s_A1, s_W0, s_W1, bias, res, C, M, K, N, act);
}

extern "C" void kernel_launch(void* const* d_in, const int* in_sizes, int n_in,
                              void* d_out, int out_size) {
    const int*   ids     = (const int*)  d_in[0];
    const float* tok_emb = (const float*)d_in[1];
    const float* pos_emb = (const float*)d_in[2];
    const float* in_w    = (const float*)d_in[3];
    const float* in_b    = (const float*)d_in[4];
    const float* ch_w1   = (const float*)d_in[5];
    const float* ch_b1   = (const float*)d_in[6];
    const float* ch_w2   = (const float*)d_in[7];
    const float* ch_b2   = (const float*)d_in[8];
    const float* qe_w1   = (const float*)d_in[9];
    const float* qe_b1   = (const float*)d_in[10];
    const float* qe_w2   = (const float*)d_in[11];
    const float* qe_b2   = (const float*)d_in[12];
    const float* q_w     = (const float*)d_in[13];
    const float* q_b     = (const float*)d_in[14];
    const float* k_w     = (const float*)d_in[15];
    const float* k_b     = (const float*)d_in[16];
    const float* v_w     = (const float*)d_in[17];
    const float* v_b     = (const float*)d_in[18];
    const float* o_w     = (const float*)d_in[19];
    const float* o_b     = (const float*)d_in[20];
    const float* f_w1    = (const float*)d_in[21];
    const float* f_b1    = (const float*)d_in[22];
    const float* f_w2    = (const float*)d_in[23];
    const float* f_b2    = (const float*)d_in[24];
    const float* ln1_g   = (const float*)d_in[25];
    const float* ln1_b   = (const float*)d_in[26];
    const float* ln2_g   = (const float*)d_in[27];
    const float* ln2_b   = (const float*)d_in[28];
    const float* out_w   = (const float*)d_in[29];
    const float* out_b   = (const float*)d_in[30];
    float* logits = (float*)d_out;

    cudaFuncSetAttribute(gemm_tc_kernel<4>, cudaFuncAttributeMaxDynamicSharedMemorySize, GSMEM);
    cudaFuncSetAttribute(gemm_tc_kernel<3>, cudaFuncAttributeMaxDynamicSharedMemorySize, GSMEM);
    cudaFuncSetAttribute(attn_kernel, cudaFuncAttributeMaxDynamicSharedMemorySize, ASMEM);

    float *h, *x, *q, *k, *v, *ao, *mid, *avg, *cmid, *cenc;
    unsigned* sel;
    cudaGetSymbolAddress((void**)&h,    g_h);
    cudaGetSymbolAddress((void**)&x,    g_x);
    cudaGetSymbolAddress((void**)&q,    g_q);
    cudaGetSymbolAddress((void**)&k,    g_k);
    cudaGetSymbolAddress((void**)&v,    g_v);
    cudaGetSymbolAddress((void**)&ao,   g_ao);
    cudaGetSymbolAddress((void**)&mid,  g_mid);
    cudaGetSymbolAddress((void**)&avg,  g_avg);
    cudaGetSymbolAddress((void**)&cmid, g_cmid);
    cudaGetSymbolAddress((void**)&cenc, g_cenc);
    cudaGetSymbolAddress((void**)&sel,  g_sel);
    cudaGetSymbolAddress((void**)&s_A0, g_A0);
    cudaGetSymbolAddress((void**)&s_A1, g_A1);
    cudaGetSymbolAddress((void**)&s_W0, g_W0);
    cudaGetSymbolAddress((void**)&s_W1, g_W1);
    cudaGetSymbolAddress((void**)&s_at0, g_at0);
    cudaGetSymbolAddress((void**)&s_at1, g_at1);

    embed_kernel<<<R_, 256>>>(ids, tok_emb, pos_emb, x);
    cvtA(x, R_ * E_);
    run_gemm(in_w, in_b, nullptr, h, R_, E_, H_, 0, 1);

    chunk_avg_kernel<<<dim3(NC_, B_), 256>>>(h, ids, avg);
    cvtA(avg, B_ * NC_ * H_);
    run_gemm(ch_w1, ch_b1, nullptr, cmid, B_ * NC_, H_, HH_, 1, 1);
    cvtA(cmid, B_ * NC_ * HH_);
    run_gemm(ch_w2, ch_b2, nullptr, cenc, B_ * NC_, HH_, H_, 0, 1);

    for (int i = 0; i < L_; i++) {
        cvtA(h, R_ * H_);
        run_gemm(qe_w1, qe_b1, nullptr, mid, R_, H_, HH_, 1, 1);
        cvtA(mid, R_ * HH_);
        run_gemm(qe_w2, qe_b2, nullptr, x, R_, HH_, H_, 0, 1);
        topk_kernel<<<dim3(S_, B_), 512>>>(x, cenc, sel);

        int hi = (i == 0) ? 1 : 0;
        ln_kernel<<<R_, 256>>>(h, ln1_g + i * H_, ln1_b + i * H_, x);
        cvtA(x, R_ * H_);
        run_gemm(q_w + (size_t)i * H_ * H_, q_b + i * H_, nullptr, q, R_, H_, H_, 0, hi);
        run_gemm(k_w + (size_t)i * H_ * H_, k_b + i * H_, nullptr, k, R_, H_, H_, 0, hi);
        run_gemm(v_w + (size_t)i * H_ * H_, v_b + i * H_, nullptr, v, R_, H_, H_, 0, hi);

        cvt_split2_kernel<<<(R_ * H_ / 4 + 255) / 256, 256>>>(q, s_at0,             s_at1,             R_ * H_);
        cvt_split2_kernel<<<(R_ * H_ / 4 + 255) / 256, 256>>>(k, s_at0 + R_ * H_,   s_at1 + R_ * H_,   R_ * H_);
        cvt_split2_kernel<<<(R_ * H_ / 4 + 255) / 256, 256>>>(v, s_at0 + 2 * R_ * H_, s_at1 + 2 * R_ * H_, R_ * H_);
        attn_kernel<<<dim3(S_ / 16, NH_, B_), 128, ASMEM>>>(
            s_at0, s_at1,
            s_at0 + R_ * H_, s_at1 + R_ * H_,
            s_at0 + 2 * R_ * H_, s_at1 + 2 * R_ * H_,
            sel, ao);

        cvtA(ao, R_ * H_);
        run_gemm(o_w + (size_t)i * H_ * H_, o_b + i * H_, h, h, R_, H_, H_, 0, hi);

        ln_kernel<<<R_, 256>>>(h, ln2_g + i * H_, ln2_b + i * H_, x);
        cvtA(x, R_ * H_);
        run_gemm(f_w1 + (size_t)i * H_ * FF_, f_b1 + i * FF_, nullptr, mid, R_, H_, FF_, 2, hi);
        cvtA(mid, R_ * FF_);
        run_gemm(f_w2 + (size_t)i * FF_ * H_, f_b2 + i * H_, h, h, R_, FF_, H_, 0, hi);
    }

    cvtA(h, R_ * H_);
    run_gemm(out_w, out_b, nullptr, logits, R_, H_, V_, 0, 0);
}

// round 9
// speedup vs baseline: 2.1276x; 1.0850x over previous
#include <cuda_runtime.h>
#include <cuda_bf16.h>
#include <math.h>
#include <stdint.h>

#define B_  2
#define S_  2048
#define E_  1024
#define H_  1024
#define NH_ 8
#define HD_ 128
#define L_  2
#define V_  32000
#define CS_ 128
#define NC_ 16
#define TOPK_ 8
#define R_  (B_ * S_)
#define FF_ (4 * H_)
#define HH_ (H_ / 2)
#define SCALE_ 0.08838834764831843f

// ---- scratch ----
__device__ __align__(16) float g_h  [R_ * H_];
__device__ __align__(16) float g_x  [R_ * H_];
__device__ __align__(16) float g_ao [R_ * H_];
__device__ __align__(16) float g_avg [B_ * NC_ * H_];
__device__ __align__(16) float g_cenc[B_ * NC_ * H_];
__device__ unsigned g_sel[R_];
__device__ __align__(16) __nv_bfloat16 g_A0[R_ * FF_];   // split pair A
__device__ __align__(16) __nv_bfloat16 g_A1[R_ * FF_];
__device__ __align__(16) __nv_bfloat16 g_B0[R_ * FF_];   // split pair B
__device__ __align__(16) __nv_bfloat16 g_B1[R_ * FF_];
__device__ __align__(16) __nv_bfloat16 g_W0[32000 * 1024];
__device__ __align__(16) __nv_bfloat16 g_W1[32000 * 1024];
__device__ __align__(16) __nv_bfloat16 g_at0[3 * R_ * H_];
__device__ __align__(16) __nv_bfloat16 g_at1[3 * R_ * H_];

// ---- helpers ----
__device__ __forceinline__ float warpSum(float v) {
    #pragma unroll
    for (int o = 16; o > 0; o >>= 1) v += __shfl_xor_sync(0xffffffffu, v, o);
    return v;
}
__device__ __forceinline__ uint32_t smem_u32(const void* p) {
    uint32_t a;
    asm("{ .reg .u64 t; cvta.to.shared.u64 t, %1; cvt.u32.u64 %0, t; }" : "=r"(a) : "l"(p));
    return a;
}
#define CPA(d, s) asm volatile("cp.async.cg.shared.global [%0], [%1], 16;" :: "r"(d), "l"(s))
#define CPA_COMMIT() asm volatile("cp.async.commit_group;" ::: "memory")
#define CPA_WAIT0()  asm volatile("cp.async.wait_group 0;" ::: "memory")
#define CPA_WAIT1()  asm volatile("cp.async.wait_group 1;" ::: "memory")

#define LDSM_X4(r0, r1, r2, r3, a) \
    asm volatile("ldmatrix.sync.aligned.m8n8.x4.shared.b16 {%0,%1,%2,%3}, [%4];" \
        : "=r"(r0), "=r"(r1), "=r"(r2), "=r"(r3) : "r"(a))
#define LDSM_X4T(r0, r1, r2, r3, a) \
    asm volatile("ldmatrix.sync.aligned.m8n8.x4.trans.shared.b16 {%0,%1,%2,%3}, [%4];" \
        : "=r"(r0), "=r"(r1), "=r"(r2), "=r"(r3) : "r"(a))

#define MMA_BF16(c, a, b) \
    asm volatile("mma.sync.aligned.m16n8k16.row.col.f32.bf16.bf16.f32 " \
        "{%0,%1,%2,%3}, {%4,%5,%6,%7}, {%8,%9}, {%0,%1,%2,%3};" \
        : "+f"((c)[0]), "+f"((c)[1]), "+f"((c)[2]), "+f"((c)[3]) \
        : "r"((a)[0]), "r"((a)[1]), "r"((a)[2]), "r"((a)[3]), "r"((b)[0]), "r"((b)[1]))

__device__ __forceinline__ uint32_t packbf(float lo, float hi) {
    __nv_bfloat162 t = __floats2bfloat162_rn(lo, hi);
    return *(uint32_t*)&t;
}

// ---- embedding ----
__global__ void embed_kernel(const int* __restrict__ ids, const float* __restrict__ tok,
                             const float* __restrict__ pos, float* __restrict__ out) {
    int r = blockIdx.x;
    int id = ids[r];
    const float* t = tok + (size_t)id * E_;
    const float* p = pos + (size_t)(r % S_) * E_;
    float* o = out + (size_t)r * E_;
    for (int e = threadIdx.x; e < E_; e += blockDim.x) o[e] = t[e] + p[e];
}

// ---- fp32 -> 2-way bf16 split ----
__global__ void cvt_split2_kernel(const float* __restrict__ a, __nv_bfloat16* __restrict__ o0,
                                  __nv_bfloat16* __restrict__ o1, int n) {
    int i = (blockIdx.x * blockDim.x + threadIdx.x) * 4;
    if (i >= n) return;
    float4 v = *(const float4*)(a + i);
    union { __nv_bfloat16 b[4]; uint2 u; } U0, U1;
    float f[4] = {v.x, v.y, v.z, v.w};
    #pragma unroll
    for (int j = 0; j < 4; j++) {
        __nv_bfloat16 b0 = __float2bfloat16_rn(f[j]);
        U0.b[j] = b0;
        U1.b[j] = __float2bfloat16_rn(f[j] - __bfloat162float(b0));
    }
    *(uint2*)(o0 + i) = U0.u;
    *(uint2*)(o1 + i) = U1.u;
}

// ---- fp32 W[K,N] -> 2-way split W^T[N,K] ----
__global__ void cvt_t2_kernel(const float* __restrict__ w, __nv_bfloat16* __restrict__ o0,
                              __nv_bfloat16* __restrict__ o1, int Kd, int Nd) {
    __shared__ float t[32][33];
    int n0 = blockIdx.x * 32, k0 = blockIdx.y * 32;
    int tx = threadIdx.x, ty = threadIdx.y;
    #pragma unroll
    for (int i = 0; i < 32; i += 8)
        t[ty + i][tx] = w[(size_t)(k0 + ty + i) * Nd + n0 + tx];
    __syncthreads();
    #pragma unroll
    for (int i = 0; i < 32; i += 8) {
        float v = t[tx][ty + i];
        __nv_bfloat16 b0 = __float2bfloat16_rn(v);
        size_t o = (size_t)(n0 + ty + i) * Kd + k0 + tx;
        o0[o] = b0;
        o1[o] = __float2bfloat16_rn(v - __bfloat162float(b0));
    }
}

// ---- HMMA split-bf16 GEMM (3-stage, 512 threads, warp tile 32x64) ----
// If o0 != null: write split-bf16 output (o0,o1) instead of fp32 C.
#define SK 40
#define A_MAT (128 * SK * 2)
#define B_MAT (256 * SK * 2)
#define STG (2 * A_MAT + 2 * B_MAT)
#define GSMEM (3 * STG)     // 184320

template<int NP>
__global__ void __launch_bounds__(512)
gemm_tc_kernel(const __nv_bfloat16* __restrict__ A0, const __nv_bfloat16* __restrict__ A1,
               const __nv_bfloat16* __restrict__ B0, const __nv_bfloat16* __restrict__ B1,
               const float* __restrict__ bias, const float* __restrict__ res,
               float* __restrict__ C, __nv_bfloat16* __restrict__ o0,
               __nv_bfloat16* __restrict__ o1, int M, int K, int N, int act) {
    extern __shared__ char smem[];
    const uint32_t sb = smem_u32(smem);
    const int tid = threadIdx.x, lane = tid & 31;
    const int w = tid >> 5, wm = w >> 2, wn = w & 3;   // 4x4 warp grid
    const int m0 = blockIdx.y * 128, n0 = blockIdx.x * 256;

    float c[2][8][4];
    #pragma unroll
    for (int i = 0; i < 2; i++)
        #pragma unroll
        for (int j = 0; j < 8; j++)
            #pragma unroll
            for (int e = 0; e < 4; e++) c[i][j][e] = 0.f;

    const int arow = tid >> 2, aseg = tid & 3;
    const int agrow = (m0 + arow < M) ? (m0 + arow) : (M - 1);

    auto issue_stage = [&](int kb, int st) {
        size_t gk = (size_t)kb * 32;
        uint32_t stb = sb + st * STG;
        {
            uint32_t d = stb + (arow * SK + aseg * 8) * 2;
            size_t o = (size_t)agrow * K + gk + aseg * 8;
            CPA(d, A0 + o);
            CPA(d + A_MAT, A1 + o);
        }
        #pragma unroll
        for (int i = 0; i < 2; i++) {
            int idx = tid + i * 512;
            int r = idx >> 2, sg = idx & 3;
            uint32_t d = stb + 2 * A_MAT + (r * SK + sg * 8) * 2;
            size_t o = (size_t)(n0 + r) * K + gk + sg * 8;
            CPA(d, B0 + o);
            CPA(d + B_MAT, B1 + o);
        }
        CPA_COMMIT();
    };

    const int nkb = K >> 5;
    issue_stage(0, 0);
    if (nkb > 1) issue_stage(1, 1);

    const uint32_t a_off = ((wm * 32 + (lane & 15)) * SK + ((lane >> 4) << 3)) * 2;
    const uint32_t b_off = ((wn * 64 + (lane & 7) + ((lane >> 4) << 3)) * SK + (((lane >> 3) & 1) << 3)) * 2;
    const int pa[4] = {0, 0, 1, 1};
    const int pb[4] = {0, 1, 0, 1};

    for (int kb = 0; kb < nkb; kb++) {
        if (kb + 1 < nkb) CPA_WAIT1(); else CPA_WAIT0();
        __syncthreads();
        uint32_t base = sb + (kb % 3) * STG;
        #pragma unroll
        for (int kk = 0; kk < 2; kk++) {
            uint32_t af[2][2][4];
            #pragma unroll
            for (int s = 0; s < 2; s++)
                #pragma unroll
                for (int mt = 0; mt < 2; mt++) {
                    uint32_t ad = base + s * A_MAT + a_off + kk * 32 + mt * 16 * SK * 2;
                    LDSM_X4(af[s][mt][0], af[s][mt][1], af[s][mt][2], af[s][mt][3], ad);
                }
            uint32_t bf[2][2][4];
            #pragma unroll
            for (int s = 0; s < 2; s++) {
                uint32_t bd = base + 2 * A_MAT + s * B_MAT + b_off + kk * 32;
                LDSM_X4(bf[0][s][0], bf[0][s][1], bf[0][s][2], bf[0][s][3], bd);
            }
            #pragma unroll
            for (int nt2 = 0; nt2 < 4; nt2++) {
                int cur = nt2 & 1, nxt = cur ^ 1;
                if (nt2 < 3) {
                    #pragma unroll
                    for (int s = 0; s < 2; s++) {
                        uint32_t bd = base + 2 * A_MAT + s * B_MAT + b_off + kk * 32 + (nt2 + 1) * 16 * SK * 2;
                        LDSM_X4(bf[nxt][s][0], bf[nxt][s][1], bf[nxt][s][2], bf[nxt][s][3], bd);
                    }
                }
                #pragma unroll
                for (int p = 0; p < NP; p++)
                    #pragma unroll
                    for (int mt = 0; mt < 2; mt++)
                        #pragma unroll
                        for (int half = 0; half < 2; half++)
                            MMA_BF16(c[mt][nt2 * 2 + half], af[pa[p]][mt], bf[cur][pb[p]] + half * 2);
            }
        }
        if (kb + 2 < nkb) issue_stage(kb + 2, (kb + 2) % 3);
    }

    const int grp = lane >> 2, tig = lane & 3;
    #pragma unroll
    for (int mt = 0; mt < 2; mt++) {
        #pragma unroll
        for (int nt = 0; nt < 8; nt++) {
            int col = n0 + wn * 64 + nt * 8 + tig * 2;
            float b0 = bias[col], b1 = bias[col + 1];
            #pragma unroll
            for (int hrow = 0; hrow < 2; hrow++) {
                int row = m0 + wm * 32 + mt * 16 + grp + hrow * 8;
                if (row >= M) continue;
                float vx = c[mt][nt][hrow * 2 + 0] + b0;
                float vy = c[mt][nt][hrow * 2 + 1] + b1;
                if (act == 1) {
                    vx = fmaxf(vx, 0.f); vy = fmaxf(vy, 0.f);
                } else if (act == 2) {
                    vx = 0.5f * vx * (1.f + erff(vx * 0.7071067811865475f));
                    vy = 0.5f * vy * (1.f + erff(vy * 0.7071067811865475f));
                }
                size_t off = (size_t)row * N + col;
                if (o0) {
                    float hx = __bfloat162float(__float2bfloat16_rn(vx));
                    float hy = __bfloat162float(__float2bfloat16_rn(vy));
                    *(uint32_t*)(o0 + off) = packbf(hx, hy);
                    *(uint32_t*)(o1 + off) = packbf(vx - hx, vy - hy);
                } else {
                    if (res) {
                        float2 r = *(const float2*)(res + off);
                        vx += r.x; vy += r.y;
                    }
                    float2 o; o.x = vx; o.y = vy;
                    *(float2*)(C + off) = o;
                }
            }
        }
    }
}

// ---- chunk mean ----
__global__ void chunk_avg_kernel(const float* __restrict__ h, const int* __restrict__ ids,
                                 float* __restrict__ avg) {
    int c = blockIdx.x, b = blockIdx.y;
    __shared__ float msk[CS_];
    __shared__ float s_cnt;
    int tid = threadIdx.x;
    if (tid < CS_) msk[tid] = (ids[b * S_ + c * CS_ + tid] != 0) ? 1.f : 0.f;
    __syncthreads();
    if (tid == 0) {
        float cn = 0.f;
        for (int p = 0; p < CS_; p++) cn += msk[p];
        s_cnt = cn;
    }
    __syncthreads();
    float inv = 1.f / (s_cnt + 1e-10f);
    for (int d = tid; d < H_; d += blockDim.x) {
        float s = 0.f;
        for (int p = 0; p < CS_; p++)
            s += h[(size_t)(b * S_ + c * CS_ + p) * H_ + d] * msk[p];
        avg[(size_t)(b * NC_ + c) * H_ + d] = s * inv;
    }
}

// ---- topk ----
__global__ void __launch_bounds__(512)
topk_kernel(const float* __restrict__ qe, const float* __restrict__ cenc,
            unsigned* __restrict__ sel) {
    int s = blockIdx.x, b = blockIdx.y;
    int tid = threadIdx.x, warp = tid >> 5, lane = tid & 31;
    __shared__ float sc[NC_];
    const float* q = qe + (size_t)(b * S_ + s) * H_;
    const float* c = cenc + (size_t)(b * NC_ + warp) * H_;
    float d = 0.f;
    for (int e = lane; e < H_; e += 32) d += q[e] * c[e];
    d = warpSum(d);
    if (lane == 0) sc[warp] = d;
    __syncthreads();
    if (tid == 0) {
        unsigned chosen = 0;
        for (int t = 0; t < TOPK_; t++) {
            float best = -INFINITY;
            int bi = 0;
            for (int cc = 0; cc < NC_; cc++)
                if (!((chosen >> cc) & 1u) && sc[cc] > best) { best = sc[cc]; bi = cc; }
            chosen |= 1u << bi;
        }
        sel[b * S_ + s] = chosen;
    }
}

// ---- LayerNorm ----
__global__ void ln_kernel(const float* __restrict__ x, const float* __restrict__ g,
                          const float* __restrict__ bt, float* __restrict__ y) {
    int r = blockIdx.x;
    int tid = threadIdx.x, warp = tid >> 5, lane = tid & 31;
    const float* xr = x + (size_t)r * H_;
    float s = 0.f, sq = 0.f;
    for (int e = tid; e < H_; e += 256) {
        float v = xr[e];
        s += v; sq += v * v;
    }
    __shared__ float rs[8], rq[8];
    __shared__ float s_mean, s_rstd;
    s = warpSum(s); sq = warpSum(sq);
    if (lane == 0) { rs[warp] = s; rq[warp] = sq; }
    __syncthreads();
    if (tid == 0) {
        float Sm = 0.f, Q = 0.f;
        for (int ww = 0; ww < 8; ww++) { Sm += rs[ww]; Q += rq[ww]; }
        float mean = Sm / (float)H_;
        float var = Q / (float)H_ - mean * mean;
        s_mean = mean;
        s_rstd = rsqrtf(var + 1e-5f);
    }
    __syncthreads();
    float mean = s_mean, rstd = s_rstd;
    float* yr = y + (size_t)r * H_;
    for (int e = tid; e < 256 * ((H_ + 255) / 256); e += 256)
        if (e < H_) yr[e] = (xr[e] - mean) * rstd * g[e] + bt[e];
}

// ---- HMMA sparse chunk attention ----
#define AST 136
#define KOFF0 0
#define KOFF1 34816
#define VOFF0 69632
#define VOFF1 104448
#define QOFF0 139264
#define QOFF1 143616
#define NOFF  147968
#define DOFF  156160
#define ASMEM 156224

__global__ void __launch_bounds__(128)
attn_kernel(const __nv_bfloat16* __restrict__ gq0, const __nv_bfloat16* __restrict__ gq1,
            const __nv_bfloat16* __restrict__ gk0, const __nv_bfloat16* __restrict__ gk1,
            const __nv_bfloat16* __restrict__ gv0, const __nv_bfloat16* __restrict__ gv1,
            const unsigned* __restrict__ sel, float* __restrict__ out) {
    extern __shared__ char sm[];
    const uint32_t sb = smem_u32(sm);
    const int tid = threadIdx.x, lane = tid & 31, w = tid >> 5;
    const int head = blockIdx.y, b = blockIdx.z;
    const int s0 = blockIdx.x * 16;
    float* num = (float*)(sm + NOFF);
    float* den = (float*)(sm + DOFF);
    __shared__ unsigned smask[16];
    __shared__ unsigned s_union;

    for (int i = tid; i < 16 * 128; i += 128) num[i] = 0.f;
    if (tid < 16) { smask[tid] = sel[b * S_ + s0 + tid]; den[tid] = 0.f; }
    __syncthreads();
    if (tid == 0) {
        unsigned u = 0;
        for (int i = 0; i < 16; i++) u |= smask[i];
        s_union = u;
    }
    {
        int row = tid >> 3, sp = tid & 7;
        size_t src = ((size_t)(b * S_ + s0 + row)) * H_ + head * HD_ + sp * 16;
        uint32_t d = row * (AST * 2) + sp * 32;
        CPA(sb + QOFF0 + d,      gq0 + src);
        CPA(sb + QOFF0 + d + 16, gq0 + src + 8);
        CPA(sb + QOFF1 + d,      gq1 + src);
        CPA(sb + QOFF1 + d + 16, gq1 + src + 8);
    }
    CPA_COMMIT();
    CPA_WAIT0();
    __syncthreads();

    uint32_t qf[2][8][4];
    const uint32_t qa = (lane & 15) * (AST * 2) + ((lane >> 4) << 4);
    #pragma unroll
    for (int s = 0; s < 2; s++)
        #pragma unroll
        for (int ks = 0; ks < 8; ks++) {
            uint32_t ad = sb + (s ? QOFF1 : QOFF0) + qa + ks * 32;
            LDSM_X4(qf[s][ks][0], qf[s][ks][1], qf[s][ks][2], qf[s][ks][3], ad);
        }

    float oacc[16][4];
    #pragma unroll
    for (int t = 0; t < 16; t++)
        #pragma unroll
        for (int e = 0; e < 4; e++) oacc[t][e] = 0.f;

    const unsigned um = s_union;
    const int r0 = lane >> 2, r1 = r0 + 8;
    const uint32_t kb_off = (w * 32 + (lane & 7) + ((lane >> 4) << 3)) * (AST * 2) + (((lane >> 3) & 1) << 4);
    const uint32_t vb_off = (w * 32 + (lane & 15)) * (AST * 2) + ((lane >> 4) << 4);

    for (int c = 0; c < NC_; c++) {
        if (!((um >> c) & 1u)) continue;
        int j0 = c * CS_;
        {
            size_t src = ((size_t)(b * S_ + j0 + tid)) * H_ + head * HD_;
            uint32_t d = tid * (AST * 2);
            #pragma unroll
            for (int g = 0; g < 16; g++) {
                CPA(sb + KOFF0 + d + g * 16, gk0 + src + g * 8);
                CPA(sb + KOFF1 + d + g * 16, gk1 + src + g * 8);
                CPA(sb + VOFF0 + d + g * 16, gv0 + src + g * 8);
                CPA(sb + VOFF1 + d + g * 16, gv1 + src + g * 8);
            }
        }
        CPA_COMMIT();
        CPA_WAIT0();
        __syncthreads();

        float sc[4][4];
        #pragma unroll
        for (int t = 0; t < 4; t++)
            #pragma unroll
            for (int e = 0; e < 4; e++) sc[t][e] = 0.f;
        #pragma unroll
        for (int ks = 0; ks < 8; ks++) {
            uint32_t kfA0[4], kfA1[4], kfB0[4], kfB1[4];
            LDSM_X4(kfA0[0], kfA0[1], kfA0[2], kfA0[3], sb + KOFF0 + kb_off + ks * 32);
            LDSM_X4(kfB0[0], kfB0[1], kfB0[2], kfB0[3], sb + KOFF0 + kb_off + 16 * AST * 2 + ks * 32);
            LDSM_X4(kfA1[0], kfA1[1], kfA1[2], kfA1[3], sb + KOFF1 + kb_off + ks * 32);
            LDSM_X4(kfB1[0], kfB1[1], kfB1[2], kfB1[3], sb + KOFF1 + kb_off + 16 * AST * 2 + ks * 32);
            #pragma unroll
            for (int qs = 0; qs < 2; qs++) {
                uint32_t* a = qf[qs][ks];
                MMA_BF16(sc[0], a, kfA0 + 0); MMA_BF16(sc[1], a, kfA0 + 2);
                MMA_BF16(sc[2], a, kfB0 + 0); MMA_BF16(sc[3], a, kfB0 + 2);
                MMA_BF16(sc[0], a, kfA1 + 0); MMA_BF16(sc[1], a, kfA1 + 2);
                MMA_BF16(sc[2], a, kfB1 + 0); MMA_BF16(sc[3], a, kfB1 + 2);
            }
        }
        bool m0 = (smask[r0] >> c) & 1u, m1 = (smask[r1] >> c) & 1u;
        float d0 = 0.f, d1 = 0.f;
        uint32_t pf[2][2][4];
        #pragma unroll
        for (int t = 0; t < 4; t++) {
            float e0 = m0 ? expf(sc[t][0] * SCALE_) : 0.f;
            float e1 = m0 ? expf(sc[t][1] * SCALE_) : 0.f;
            float e2 = m1 ? expf(sc[t][2] * SCALE_) : 0.f;
            float e3 = m1 ? expf(sc[t][3] * SCALE_) : 0.f;
            d0 += e0 + e1; d1 += e2 + e3;
            float h0 = __bfloat162float(__float2bfloat16_rn(e0));
            float h1 = __bfloat162float(__float2bfloat16_rn(e1));
            float h2 = __bfloat162float(__float2bfloat16_rn(e2));
            float h3 = __bfloat162float(__float2bfloat16_rn(e3));
            int g = t >> 1, o = (t & 1) * 2;
            pf[g][0][o + 0] = packbf(h0, h1);
            pf[g][0][o + 1] = packbf(h2, h3);
            pf[g][1][o + 0] = packbf(e0 - h0, e1 - h1);
            pf[g][1][o + 1] = packbf(e2 - h2, e3 - h3);
        }
        d0 += __shfl_xor_sync(0xffffffffu, d0, 1);
        d0 += __shfl_xor_sync(0xffffffffu, d0, 2);
        d1 += __shfl_xor_sync(0xffffffffu, d1, 1);
        d1 += __shfl_xor_sync(0xffffffffu, d1, 2);
        if ((lane & 3) == 0) {
            atomicAdd(&den[r0], d0);
            atomicAdd(&den[r1], d1);
        }
        #pragma unroll
        for (int dg = 0; dg < 8; dg++) {
            #pragma unroll
            for (int kg = 0; kg < 2; kg++) {
                uint32_t vf0[4], vf1[4];
                LDSM_X4T(vf0[0], vf0[1], vf0[2], vf0[3], sb + VOFF0 + vb_off + kg * 16 * AST * 2 + dg * 32);
                LDSM_X4T(vf1[0], vf1[1], vf1[2], vf1[3], sb + VOFF1 + vb_off + kg * 16 * AST * 2 + dg * 32);
                #pragma unroll
                for (int ps = 0; ps < 2; ps++) {
                    uint32_t* a = pf[kg][ps];
                    MMA_BF16(oacc[2 * dg + 0], a, vf0 + 0);
                    MMA_BF16(oacc[2 * dg + 1], a, vf0 + 2);
                    MMA_BF16(oacc[2 * dg + 0], a, vf1 + 0);
                    MMA_BF16(oacc[2 * dg + 1], a, vf1 + 2);
                }
            }
        }
        __syncthreads();
    }

    for (int ww = 0; ww < 4; ww++) {
        if (w == ww) {
            #pragma unroll
            for (int t = 0; t < 16; t++) {
                int dbase = 8 * t + 2 * (lane & 3);
                num[r0 * 128 + dbase + 0] += oacc[t][0];
                num[r0 * 128 + dbase + 1] += oacc[t][1];
                num[r1 * 128 + dbase + 0] += oacc[t][2];
                num[r1 * 128 + dbase + 1] += oacc[t][3];
            }
        }
        __syncthreads();
    }
    for (int r = 0; r < 16; r++) {
        float dv = den[r];
        out[((size_t)(b * S_ + s0 + r)) * H_ + head * HD_ + tid] = num[r * 128 + tid] / dv;
    }
}

// ---- host ----
static __nv_bfloat16 *s_A0, *s_A1, *s_B0, *s_B1, *s_W0, *s_W1, *s_at0, *s_at1;

static inline void cvt2(const float* A, __nv_bfloat16* d0, __nv_bfloat16* d1, int n) {
    cvt_split2_kernel<<<(n / 4 + 255) / 256, 256>>>(A, d0, d1, n);
}
static inline void run_gemm(const __nv_bfloat16* A0, const __nv_bfloat16* A1,
                            const float* W, const float* bias, const float* res,
                            float* C, __nv_bfloat16* o0, __nv_bfloat16* o1,
                            int M, int K, int N, int act, int hi) {
    cvt_t2_kernel<<<dim3(N / 32, K / 32), dim3(32, 8)>>>(W, s_W0, s_W1, K, N);
    dim3 grid(N / 256, (M + 127) / 128);
    if (hi)
        gemm_tc_kernel<4><<<grid, 512, GSMEM>>>(A0, A1, s_W0, s_W1, bias, res, C, o0, o1, M, K, N, act);
    else
        gemm_tc_kernel<3><<<grid, 512, GSMEM>>>(A0, A1, s_W0, s_W1, bias, res, C, o0, o1, M, K, N, act);
}

extern "C" void kernel_launch(void* const* d_in, const int* in_sizes, int n_in,
                              void* d_out, int out_size) {
    const int*   ids     = (const int*)  d_in[0];
    const float* tok_emb = (const float*)d_in[1];
    const float* pos_emb = (const float*)d_in[2];
    const float* in_w    = (const float*)d_in[3];
    const float* in_b    = (const float*)d_in[4];
    const float* ch_w1   = (const float*)d_in[5];
    const float* ch_b1   = (const float*)d_in[6];
    const float* ch_w2   = (const float*)d_in[7];
    const float* ch_b2   = (const float*)d_in[8];
    const float* qe_w1   = (const float*)d_in[9];
    const float* qe_b1   = (const float*)d_in[10];
    const float* qe_w2   = (const float*)d_in[11];
    const float* qe_b2   = (const float*)d_in[12];
    const float* q_w     = (const float*)d_in[13];
    const float* q_b     = (const float*)d_in[14];
    const float* k_w     = (const float*)d_in[15];
    const float* k_b     = (const float*)d_in[16];
    const float* v_w     = (const float*)d_in[17];
    const float* v_b     = (const float*)d_in[18];
    const float* o_w     = (const float*)d_in[19];
    const float* o_b     = (const float*)d_in[20];
    const float* f_w1    = (const float*)d_in[21];
    const float* f_b1    = (const float*)d_in[22];
    const float* f_w2    = (const float*)d_in[23];
    const float* f_b2    = (const float*)d_in[24];
    const float* ln1_g   = (const float*)d_in[25];
    const float* ln1_b   = (const float*)d_in[26];
    const float* ln2_g   = (const float*)d_in[27];
    const float* ln2_b   = (const float*)d_in[28];
    const float* out_w   = (const float*)d_in[29];
    const float* out_b   = (const float*)d_in[30];
    float* logits = (float*)d_out;

    cudaFuncSetAttribute(gemm_tc_kernel<4>, cudaFuncAttributeMaxDynamicSharedMemorySize, GSMEM);
    cudaFuncSetAttribute(gemm_tc_kernel<3>, cudaFuncAttributeMaxDynamicSharedMemorySize, GSMEM);
    cudaFuncSetAttribute(attn_kernel, cudaFuncAttributeMaxDynamicSharedMemorySize, ASMEM);

    float *h, *x, *ao, *avg, *cenc;
    unsigned* sel;
    cudaGetSymbolAddress((void**)&h,    g_h);
    cudaGetSymbolAddress((void**)&x,    g_x);
    cudaGetSymbolAddress((void**)&ao,   g_ao);
    cudaGetSymbolAddress((void**)&avg,  g_avg);
    cudaGetSymbolAddress((void**)&cenc, g_cenc);
    cudaGetSymbolAddress((void**)&sel,  g_sel);
    cudaGetSymbolAddress((void**)&s_A0, g_A0);
    cudaGetSymbolAddress((void**)&s_A1, g_A1);
    cudaGetSymbolAddress((void**)&s_B0, g_B0);
    cudaGetSymbolAddress((void**)&s_B1, g_B1);
    cudaGetSymbolAddress((void**)&s_W0, g_W0);
    cudaGetSymbolAddress((void**)&s_W1, g_W1);
    cudaGetSymbolAddress((void**)&s_at0, g_at0);
    cudaGetSymbolAddress((void**)&s_at1, g_at1);

    // embeddings -> x ; input projection -> h (fp32)
    embed_kernel<<<R_, 256>>>(ids, tok_emb, pos_emb, x);
    cvt2(x, s_A0, s_A1, R_ * E_);
    run_gemm(s_A0, s_A1, in_w, in_b, nullptr, h, nullptr, nullptr, R_, E_, H_, 0, 1);

    // chunk encodings (split-output chain)
    chunk_avg_kernel<<<dim3(NC_, B_), 256>>>(h, ids, avg);
    cvt2(avg, s_A0, s_A1, B_ * NC_ * H_);
    run_gemm(s_A0, s_A1, ch_w1, ch_b1, nullptr, nullptr, s_B0, s_B1, B_ * NC_, H_, HH_, 1, 1);
    run_gemm(s_B0, s_B1, ch_w2, ch_b2, nullptr, cenc, nullptr, nullptr, B_ * NC_, HH_, H_, 0, 1);

    for (int i = 0; i < L_; i++) {
        // selection path (hi precision)
        cvt2(h, s_A0, s_A1, R_ * H_);
        run_gemm(s_A0, s_A1, qe_w1, qe_b1, nullptr, nullptr, s_B0, s_B1, R_, H_, HH_, 1, 1);
        run_gemm(s_B0, s_B1, qe_w2, qe_b2, nullptr, x, nullptr, nullptr, R_, HH_, H_, 0, 1);
        topk_kernel<<<dim3(S_, B_), 512>>>(x, cenc, sel);

        int hi = (i == 0) ? 1 : 0;
        ln_kernel<<<R_, 256>>>(h, ln1_g + i * H_, ln1_b + i * H_, x);
        cvt2(x, s_A0, s_A1, R_ * H_);
        // q/k/v: split-bf16 direct to attention buffers
        run_gemm(s_A0, s_A1, q_w + (size_t)i * H_ * H_, q_b + i * H_, nullptr, nullptr,
                 s_at0,              s_at1,              R_, H_, H_, 0, hi);
        run_gemm(s_A0, s_A1, k_w + (size_t)i * H_ * H_, k_b + i * H_, nullptr, nullptr,
                 s_at0 + R_ * H_,    s_at1 + R_ * H_,    R_, H_, H_, 0, hi);
        run_gemm(s_A0, s_A1, v_w + (size_t)i * H_ * H_, v_b + i * H_, nullptr, nullptr,
                 s_at0 + 2 * R_ * H_, s_at1 + 2 * R_ * H_, R_, H_, H_, 0, hi);
        attn_kernel<<<dim3(S_ / 16, NH_, B_), 128, ASMEM>>>(
            s_at0, s_at1, s_at0 + R_ * H_, s_at1 + R_ * H_,
            s_at0 + 2 * R_ * H_, s_at1 + 2 * R_ * H_, sel, ao);

        cvt2(ao, s_B0, s_B1, R_ * H_);
        run_gemm(s_B0, s_B1, o_w + (size_t)i * H_ * H_, o_b + i * H_, h, h, nullptr, nullptr,
                 R_, H_, H_, 0, hi);

        ln_kernel<<<R_, 256>>>(h, ln2_g + i * H_, ln2_b + i * H_, x);
        cvt2(x, s_A0, s_A1, R_ * H_);
        run_gemm(s_A0, s_A1, f_w1 + (size_t)i * H_ * FF_, f_b1 + i * FF_, nullptr, nullptr,
                 s_B0, s_B1, R_, H_, FF_, 2, hi);
        run_gemm(s_B0, s_B1, f_w2 + (size_t)i * FF_ * H_, f_b2 + i * H_, h, h, nullptr, nullptr,
                 R_, FF_, H_, 0, hi);
    }

    cvt2(h, s_A0, s_A1, R_ * H_);
    run_gemm(s_A0, s_A1, out_w, out_b, nullptr, logits, nullptr, nullptr, R_, H_, V_, 0, 0);
}

// round 10
// speedup vs baseline: 2.1378x; 1.0048x over previous
#include <cuda_runtime.h>
#include <cuda_bf16.h>
#include <math.h>
#include <stdint.h>

#define B_  2
#define S_  2048
#define E_  1024
#define H_  1024
#define NH_ 8
#define HD_ 128
#define L_  2
#define V_  32000
#define CS_ 128
#define NC_ 16
#define TOPK_ 8
#define R_  (B_ * S_)
#define FF_ (4 * H_)
#define HH_ (H_ / 2)
#define SCALE_ 0.08838834764831843f

// ---- scratch ----
__device__ __align__(16) float g_h  [R_ * H_];
__device__ __align__(16) float g_x  [R_ * H_];
__device__ __align__(16) float g_avg [B_ * NC_ * H_];
__device__ __align__(16) float g_cenc[B_ * NC_ * H_];
__device__ unsigned g_sel[R_];
__device__ __align__(16) __nv_bfloat16 g_A0[R_ * FF_];
__device__ __align__(16) __nv_bfloat16 g_A1[R_ * FF_];
__device__ __align__(16) __nv_bfloat16 g_B0[R_ * FF_];
__device__ __align__(16) __nv_bfloat16 g_B1[R_ * FF_];
__device__ __align__(16) __nv_bfloat16 g_W0[32000 * 1024];
__device__ __align__(16) __nv_bfloat16 g_W1[32000 * 1024];
__device__ __align__(16) __nv_bfloat16 g_at0[3 * R_ * H_];
__device__ __align__(16) __nv_bfloat16 g_at1[3 * R_ * H_];

// ---- helpers ----
__device__ __forceinline__ float warpSum(float v) {
    #pragma unroll
    for (int o = 16; o > 0; o >>= 1) v += __shfl_xor_sync(0xffffffffu, v, o);
    return v;
}
__device__ __forceinline__ uint32_t smem_u32(const void* p) {
    uint32_t a;
    asm("{ .reg .u64 t; cvta.to.shared.u64 t, %1; cvt.u32.u64 %0, t; }" : "=r"(a) : "l"(p));
    return a;
}
#define CPA(d, s) asm volatile("cp.async.cg.shared.global [%0], [%1], 16;" :: "r"(d), "l"(s))
#define CPA_COMMIT() asm volatile("cp.async.commit_group;" ::: "memory")
#define CPA_WAIT0()  asm volatile("cp.async.wait_group 0;" ::: "memory")

#define LDSM_X4(r0, r1, r2, r3, a) \
    asm volatile("ldmatrix.sync.aligned.m8n8.x4.shared.b16 {%0,%1,%2,%3}, [%4];" \
        : "=r"(r0), "=r"(r1), "=r"(r2), "=r"(r3) : "r"(a))
#define LDSM_X4T(r0, r1, r2, r3, a) \
    asm volatile("ldmatrix.sync.aligned.m8n8.x4.trans.shared.b16 {%0,%1,%2,%3}, [%4];" \
        : "=r"(r0), "=r"(r1), "=r"(r2), "=r"(r3) : "r"(a))

#define MMA_BF16(c, a, b) \
    asm volatile("mma.sync.aligned.m16n8k16.row.col.f32.bf16.bf16.f32 " \
        "{%0,%1,%2,%3}, {%4,%5,%6,%7}, {%8,%9}, {%0,%1,%2,%3};" \
        : "+f"((c)[0]), "+f"((c)[1]), "+f"((c)[2]), "+f"((c)[3]) \
        : "r"((a)[0]), "r"((a)[1]), "r"((a)[2]), "r"((a)[3]), "r"((b)[0]), "r"((b)[1]))

__device__ __forceinline__ uint32_t packbf(float lo, float hi) {
    __nv_bfloat162 t = __floats2bfloat162_rn(lo, hi);
    return *(uint32_t*)&t;
}
__device__ __forceinline__ void split_store(__nv_bfloat16* o0, __nv_bfloat16* o1,
                                            size_t off, float vx, float vy) {
    float hx = __bfloat162float(__float2bfloat16_rn(vx));
    float hy = __bfloat162float(__float2bfloat16_rn(vy));
    *(uint32_t*)(o0 + off) = packbf(hx, hy);
    *(uint32_t*)(o1 + off) = packbf(vx - hx, vy - hy);
}

// ---- embedding (fused split output) ----
__global__ void embed_kernel(const int* __restrict__ ids, const float* __restrict__ tok,
                             const float* __restrict__ pos,
                             __nv_bfloat16* __restrict__ o0, __nv_bfloat16* __restrict__ o1) {
    int r = blockIdx.x;
    int id = ids[r];
    const float* t = tok + (size_t)id * E_;
    const float* p = pos + (size_t)(r % S_) * E_;
    size_t base = (size_t)r * E_;
    for (int e = threadIdx.x * 2; e < E_; e += blockDim.x * 2) {
        float vx = t[e] + p[e];
        float vy = t[e + 1] + p[e + 1];
        split_store(o0, o1, base + e, vx, vy);
    }
}

// ---- fp32 -> 2-way bf16 split ----
__global__ void cvt_split2_kernel(const float* __restrict__ a, __nv_bfloat16* __restrict__ o0,
                                  __nv_bfloat16* __restrict__ o1, int n) {
    int i = (blockIdx.x * blockDim.x + threadIdx.x) * 4;
    if (i >= n) return;
    float4 v = *(const float4*)(a + i);
    union { __nv_bfloat16 b[4]; uint2 u; } U0, U1;
    float f[4] = {v.x, v.y, v.z, v.w};
    #pragma unroll
    for (int j = 0; j < 4; j++) {
        __nv_bfloat16 b0 = __float2bfloat16_rn(f[j]);
        U0.b[j] = b0;
        U1.b[j] = __float2bfloat16_rn(f[j] - __bfloat162float(b0));
    }
    *(uint2*)(o0 + i) = U0.u;
    *(uint2*)(o1 + i) = U1.u;
}

// ---- fp32 W[K,N] -> 2-way split W^T[N,K] ----
__global__ void cvt_t2_kernel(const float* __restrict__ w, __nv_bfloat16* __restrict__ o0,
                              __nv_bfloat16* __restrict__ o1, int Kd, int Nd) {
    __shared__ float t[32][33];
    int n0 = blockIdx.x * 32, k0 = blockIdx.y * 32;
    int tx = threadIdx.x, ty = threadIdx.y;
    #pragma unroll
    for (int i = 0; i < 32; i += 8)
        t[ty + i][tx] = w[(size_t)(k0 + ty + i) * Nd + n0 + tx];
    __syncthreads();
    #pragma unroll
    for (int i = 0; i < 32; i += 8) {
        float v = t[tx][ty + i];
        __nv_bfloat16 b0 = __float2bfloat16_rn(v);
        size_t o = (size_t)(n0 + ty + i) * Kd + k0 + tx;
        o0[o] = b0;
        o1[o] = __float2bfloat16_rn(v - __bfloat162float(b0));
    }
}

// ---- HMMA split-bf16 GEMM (BK=64, 2-stage, 512 threads, warp tile 32x64) ----
#define SK 72
#define A_MAT (128 * SK * 2)   // 18432
#define B_MAT (256 * SK * 2)   // 36864
#define STG (2 * A_MAT + 2 * B_MAT)   // 110592
#define GSMEM (2 * STG)               // 221184

template<int NP>
__global__ void __launch_bounds__(512)
gemm_tc_kernel(const __nv_bfloat16* __restrict__ A0, const __nv_bfloat16* __restrict__ A1,
               const __nv_bfloat16* __restrict__ B0, const __nv_bfloat16* __restrict__ B1,
               const float* __restrict__ bias, const float* __restrict__ res,
               float* __restrict__ C, __nv_bfloat16* __restrict__ o0,
               __nv_bfloat16* __restrict__ o1, int M, int K, int N, int act) {
    extern __shared__ char smem[];
    const uint32_t sb = smem_u32(smem);
    const int tid = threadIdx.x, lane = tid & 31;
    const int w = tid >> 5, wm = w >> 2, wn = w & 3;
    const int m0 = blockIdx.y * 128, n0 = blockIdx.x * 256;

    float c[2][8][4];
    #pragma unroll
    for (int i = 0; i < 2; i++)
        #pragma unroll
        for (int j = 0; j < 8; j++)
            #pragma unroll
            for (int e = 0; e < 4; e++) c[i][j][e] = 0.f;

    const int arow = tid >> 3, aseg = tid & 7;
    int agrow_t = (m0 + arow < M) ? (m0 + arow) : (M - 1);
    const int arow2 = (tid + 512) >> 3, aseg2 = (tid + 512) & 7;
    int agrow2_t = (m0 + arow2 < M) ? (m0 + arow2) : (M - 1);

    auto issue_stage = [&](int kb, int st) {
        size_t gk = (size_t)kb * 64;
        uint32_t stb = sb + st * STG;
        {
            uint32_t d = stb + (arow * SK + aseg * 8) * 2;
            size_t o = (size_t)agrow_t * K + gk + aseg * 8;
            CPA(d, A0 + o);
            CPA(d + A_MAT, A1 + o);
            uint32_t d2 = stb + (arow2 * SK + aseg2 * 8) * 2;
            size_t o2 = (size_t)agrow2_t * K + gk + aseg2 * 8;
            CPA(d2, A0 + o2);
            CPA(d2 + A_MAT, A1 + o2);
        }
        #pragma unroll
        for (int i = 0; i < 4; i++) {
            int idx = tid + i * 512;
            int r = idx >> 3, sg = idx & 7;
            uint32_t d = stb + 2 * A_MAT + (r * SK + sg * 8) * 2;
            size_t o = (size_t)(n0 + r) * K + gk + sg * 8;
            CPA(d, B0 + o);
            CPA(d + B_MAT, B1 + o);
        }
        CPA_COMMIT();
    };

    const int nkb = K >> 6;
    issue_stage(0, 0);

    const uint32_t a_off = ((wm * 32 + (lane & 15)) * SK + ((lane >> 4) << 3)) * 2;
    const uint32_t b_off = ((wn * 64 + (lane & 7) + ((lane >> 4) << 3)) * SK + (((lane >> 3) & 1) << 3)) * 2;
    const int pa[4] = {0, 0, 1, 1};
    const int pb[4] = {0, 1, 0, 1};

    for (int kb = 0; kb < nkb; kb++) {
        CPA_WAIT0();
        __syncthreads();
        if (kb + 1 < nkb) issue_stage(kb + 1, (kb + 1) & 1);
        uint32_t base = sb + (kb & 1) * STG;
        #pragma unroll
        for (int kk = 0; kk < 4; kk++) {
            uint32_t af[2][2][4];
            #pragma unroll
            for (int s = 0; s < 2; s++)
                #pragma unroll
                for (int mt = 0; mt < 2; mt++) {
                    uint32_t ad = base + s * A_MAT + a_off + kk * 32 + mt * 16 * SK * 2;
                    LDSM_X4(af[s][mt][0], af[s][mt][1], af[s][mt][2], af[s][mt][3], ad);
                }
            uint32_t bf[2][2][4];
            #pragma unroll
            for (int s = 0; s < 2; s++) {
                uint32_t bd = base + 2 * A_MAT + s * B_MAT + b_off + kk * 32;
                LDSM_X4(bf[0][s][0], bf[0][s][1], bf[0][s][2], bf[0][s][3], bd);
            }
            #pragma unroll
            for (int nt2 = 0; nt2 < 4; nt2++) {
                int cur = nt2 & 1, nxt = cur ^ 1;
                if (nt2 < 3) {
                    #pragma unroll
                    for (int s = 0; s < 2; s++) {
                        uint32_t bd = base + 2 * A_MAT + s * B_MAT + b_off + kk * 32 + (nt2 + 1) * 16 * SK * 2;
                        LDSM_X4(bf[nxt][s][0], bf[nxt][s][1], bf[nxt][s][2], bf[nxt][s][3], bd);
                    }
                }
                #pragma unroll
                for (int p = 0; p < NP; p++)
                    #pragma unroll
                    for (int mt = 0; mt < 2; mt++)
                        #pragma unroll
                        for (int half = 0; half < 2; half++)
                            MMA_BF16(c[mt][nt2 * 2 + half], af[pa[p]][mt], bf[cur][pb[p]] + half * 2);
            }
        }
    }

    const int grp = lane >> 2, tig = lane & 3;
    #pragma unroll
    for (int mt = 0; mt < 2; mt++) {
        #pragma unroll
        for (int nt = 0; nt < 8; nt++) {
            int col = n0 + wn * 64 + nt * 8 + tig * 2;
            float b0 = bias[col], b1 = bias[col + 1];
            #pragma unroll
            for (int hrow = 0; hrow < 2; hrow++) {
                int row = m0 + wm * 32 + mt * 16 + grp + hrow * 8;
                if (row >= M) continue;
                float vx = c[mt][nt][hrow * 2 + 0] + b0;
                float vy = c[mt][nt][hrow * 2 + 1] + b1;
                if (act == 1) {
                    vx = fmaxf(vx, 0.f); vy = fmaxf(vy, 0.f);
                } else if (act == 2) {
                    vx = 0.5f * vx * (1.f + erff(vx * 0.7071067811865475f));
                    vy = 0.5f * vy * (1.f + erff(vy * 0.7071067811865475f));
                }
                size_t off = (size_t)row * N + col;
                if (o0) {
                    split_store(o0, o1, off, vx, vy);
                } else {
                    if (res) {
                        float2 r = *(const float2*)(res + off);
                        vx += r.x; vy += r.y;
                    }
                    float2 o; o.x = vx; o.y = vy;
                    *(float2*)(C + off) = o;
                }
            }
        }
    }
}

// ---- chunk mean ----
__global__ void chunk_avg_kernel(const float* __restrict__ h, const int* __restrict__ ids,
                                 float* __restrict__ avg) {
    int c = blockIdx.x, b = blockIdx.y;
    __shared__ float msk[CS_];
    __shared__ float s_cnt;
    int tid = threadIdx.x;
    if (tid < CS_) msk[tid] = (ids[b * S_ + c * CS_ + tid] != 0) ? 1.f : 0.f;
    __syncthreads();
    if (tid == 0) {
        float cn = 0.f;
        for (int p = 0; p < CS_; p++) cn += msk[p];
        s_cnt = cn;
    }
    __syncthreads();
    float inv = 1.f / (s_cnt + 1e-10f);
    for (int d = tid; d < H_; d += blockDim.x) {
        float s = 0.f;
        for (int p = 0; p < CS_; p++)
            s += h[(size_t)(b * S_ + c * CS_ + p) * H_ + d] * msk[p];
        avg[(size_t)(b * NC_ + c) * H_ + d] = s * inv;
    }
}

// ---- topk ----
__global__ void __launch_bounds__(512)
topk_kernel(const float* __restrict__ qe, const float* __restrict__ cenc,
            unsigned* __restrict__ sel) {
    int s = blockIdx.x, b = blockIdx.y;
    int tid = threadIdx.x, warp = tid >> 5, lane = tid & 31;
    __shared__ float sc[NC_];
    const float* q = qe + (size_t)(b * S_ + s) * H_;
    const float* c = cenc + (size_t)(b * NC_ + warp) * H_;
    float d = 0.f;
    for (int e = lane; e < H_; e += 32) d += q[e] * c[e];
    d = warpSum(d);
    if (lane == 0) sc[warp] = d;
    __syncthreads();
    if (tid == 0) {
        unsigned chosen = 0;
        for (int t = 0; t < TOPK_; t++) {
            float best = -INFINITY;
            int bi = 0;
            for (int cc = 0; cc < NC_; cc++)
                if (!((chosen >> cc) & 1u) && sc[cc] > best) { best = sc[cc]; bi = cc; }
            chosen |= 1u << bi;
        }
        sel[b * S_ + s] = chosen;
    }
}

// ---- LayerNorm (fused split output) ----
__global__ void ln_kernel(const float* __restrict__ x, const float* __restrict__ g,
                          const float* __restrict__ bt,
                          __nv_bfloat16* __restrict__ o0, __nv_bfloat16* __restrict__ o1) {
    int r = blockIdx.x;
    int tid = threadIdx.x, warp = tid >> 5, lane = tid & 31;
    const float* xr = x + (size_t)r * H_;
    float s = 0.f, sq = 0.f;
    for (int e = tid; e < H_; e += 256) {
        float v = xr[e];
        s += v; sq += v * v;
    }
    __shared__ float rs[8], rq[8];
    __shared__ float s_mean, s_rstd;
    s = warpSum(s); sq = warpSum(sq);
    if (lane == 0) { rs[warp] = s; rq[warp] = sq; }
    __syncthreads();
    if (tid == 0) {
        float Sm = 0.f, Q = 0.f;
        for (int ww = 0; ww < 8; ww++) { Sm += rs[ww]; Q += rq[ww]; }
        float mean = Sm / (float)H_;
        float var = Q / (float)H_ - mean * mean;
        s_mean = mean;
        s_rstd = rsqrtf(var + 1e-5f);
    }
    __syncthreads();
    float mean = s_mean, rstd = s_rstd;
    size_t base = (size_t)r * H_;
    for (int e = tid * 2; e < H_; e += 512) {
        float vx = (xr[e] - mean) * rstd * g[e] + bt[e];
        float vy = (xr[e + 1] - mean) * rstd * g[e + 1] + bt[e + 1];
        split_store(o0, o1, base + e, vx, vy);
    }
}

// ---- HMMA sparse chunk attention (split output) ----
#define AST 136
#define KOFF0 0
#define KOFF1 34816
#define VOFF0 69632
#define VOFF1 104448
#define QOFF0 139264
#define QOFF1 143616
#define NOFF  147968
#define DOFF  156160
#define ASMEM 156224

__global__ void __launch_bounds__(128)
attn_kernel(const __nv_bfloat16* __restrict__ gq0, const __nv_bfloat16* __restrict__ gq1,
            const __nv_bfloat16* __restrict__ gk0, const __nv_bfloat16* __restrict__ gk1,
            const __nv_bfloat16* __restrict__ gv0, const __nv_bfloat16* __restrict__ gv1,
            const unsigned* __restrict__ sel,
            __nv_bfloat16* __restrict__ out0, __nv_bfloat16* __restrict__ out1) {
    extern __shared__ char sm[];
    const uint32_t sb = smem_u32(sm);
    const int tid = threadIdx.x, lane = tid & 31, w = tid >> 5;
    const int head = blockIdx.y, b = blockIdx.z;
    const int s0 = blockIdx.x * 16;
    float* num = (float*)(sm + NOFF);
    float* den = (float*)(sm + DOFF);
    __shared__ unsigned smask[16];
    __shared__ unsigned s_union;

    for (int i = tid; i < 16 * 128; i += 128) num[i] = 0.f;
    if (tid < 16) { smask[tid] = sel[b * S_ + s0 + tid]; den[tid] = 0.f; }
    __syncthreads();
    if (tid == 0) {
        unsigned u = 0;
        for (int i = 0; i < 16; i++) u |= smask[i];
        s_union = u;
    }
    {
        int row = tid >> 3, sp = tid & 7;
        size_t src = ((size_t)(b * S_ + s0 + row)) * H_ + head * HD_ + sp * 16;
        uint32_t d = row * (AST * 2) + sp * 32;
        CPA(sb + QOFF0 + d,      gq0 + src);
        CPA(sb + QOFF0 + d + 16, gq0 + src + 8);
        CPA(sb + QOFF1 + d,      gq1 + src);
        CPA(sb + QOFF1 + d + 16, gq1 + src + 8);
    }
    CPA_COMMIT();
    CPA_WAIT0();
    __syncthreads();

    uint32_t qf[2][8][4];
    const uint32_t qa = (lane & 15) * (AST * 2) + ((lane >> 4) << 4);
    #pragma unroll
    for (int s = 0; s < 2; s++)
        #pragma unroll
        for (int ks = 0; ks < 8; ks++) {
            uint32_t ad = sb + (s ? QOFF1 : QOFF0) + qa + ks * 32;
            LDSM_X4(qf[s][ks][0], qf[s][ks][1], qf[s][ks][2], qf[s][ks][3], ad);
        }

    float oacc[16][4];
    #pragma unroll
    for (int t = 0; t < 16; t++)
        #pragma unroll
        for (int e = 0; e < 4; e++) oacc[t][e] = 0.f;

    const unsigned um = s_union;
    const int r0 = lane >> 2, r1 = r0 + 8;
    const uint32_t kb_off = (w * 32 + (lane & 7) + ((lane >> 4) << 3)) * (AST * 2) + (((lane >> 3) & 1) << 4);
    const uint32_t vb_off = (w * 32 + (lane & 15)) * (AST * 2) + ((lane >> 4) << 4);

    for (int c = 0; c < NC_; c++) {
        if (!((um >> c) & 1u)) continue;
        int j0 = c * CS_;
        {
            size_t src = ((size_t)(b * S_ + j0 + tid)) * H_ + head * HD_;
            uint32_t d = tid * (AST * 2);
            #pragma unroll
            for (int g = 0; g < 16; g++) {
                CPA(sb + KOFF0 + d + g * 16, gk0 + src + g * 8);
                CPA(sb + KOFF1 + d + g * 16, gk1 + src + g * 8);
                CPA(sb + VOFF0 + d + g * 16, gv0 + src + g * 8);
                CPA(sb + VOFF1 + d + g * 16, gv1 + src + g * 8);
            }
        }
        CPA_COMMIT();
        CPA_WAIT0();
        __syncthreads();

        float sc[4][4];
        #pragma unroll
        for (int t = 0; t < 4; t++)
            #pragma unroll
            for (int e = 0; e < 4; e++) sc[t][e] = 0.f;
        #pragma unroll
        for (int ks = 0; ks < 8; ks++) {
            uint32_t kfA0[4], kfA1[4], kfB0[4], kfB1[4];
            LDSM_X4(kfA0[0], kfA0[1], kfA0[2], kfA0[3], sb + KOFF0 + kb_off + ks * 32);
            LDSM_X4(kfB0[0], kfB0[1], kfB0[2], kfB0[3], sb + KOFF0 + kb_off + 16 * AST * 2 + ks * 32);
            LDSM_X4(kfA1[0], kfA1[1], kfA1[2], kfA1[3], sb + KOFF1 + kb_off + ks * 32);
            LDSM_X4(kfB1[0], kfB1[1], kfB1[2], kfB1[3], sb + KOFF1 + kb_off + 16 * AST * 2 + ks * 32);
            #pragma unroll
            for (int qs = 0; qs < 2; qs++) {
                uint32_t* a = qf[qs][ks];
                MMA_BF16(sc[0], a, kfA0 + 0); MMA_BF16(sc[1], a, kfA0 + 2);
                MMA_BF16(sc[2], a, kfB0 + 0); MMA_BF16(sc[3], a, kfB0 + 2);
                MMA_BF16(sc[0], a, kfA1 + 0); MMA_BF16(sc[1], a, kfA1 + 2);
                MMA_BF16(sc[2], a, kfB1 + 0); MMA_BF16(sc[3], a, kfB1 + 2);
            }
        }
        bool m0 = (smask[r0] >> c) & 1u, m1 = (smask[r1] >> c) & 1u;
        float d0 = 0.f, d1 = 0.f;
        uint32_t pf[2][2][4];
        #pragma unroll
        for (int t = 0; t < 4; t++) {
            float e0 = m0 ? expf(sc[t][0] * SCALE_) : 0.f;
            float e1 = m0 ? expf(sc[t][1] * SCALE_) : 0.f;
            float e2 = m1 ? expf(sc[t][2] * SCALE_) : 0.f;
            float e3 = m1 ? expf(sc[t][3] * SCALE_) : 0.f;
            d0 += e0 + e1; d1 += e2 + e3;
            float h0 = __bfloat162float(__float2bfloat16_rn(e0));
            float h1 = __bfloat162float(__float2bfloat16_rn(e1));
            float h2 = __bfloat162float(__float2bfloat16_rn(e2));
            float h3 = __bfloat162float(__float2bfloat16_rn(e3));
            int g = t >> 1, o = (t & 1) * 2;
            pf[g][0][o + 0] = packbf(h0, h1);
            pf[g][0][o + 1] = packbf(h2, h3);
            pf[g][1][o + 0] = packbf(e0 - h0, e1 - h1);
            pf[g][1][o + 1] = packbf(e2 - h2, e3 - h3);
        }
        d0 += __shfl_xor_sync(0xffffffffu, d0, 1);
        d0 += __shfl_xor_sync(0xffffffffu, d0, 2);
        d1 += __shfl_xor_sync(0xffffffffu, d1, 1);
        d1 += __shfl_xor_sync(0xffffffffu, d1, 2);
        if ((lane & 3) == 0) {
            atomicAdd(&den[r0], d0);
            atomicAdd(&den[r1], d1);
        }
        #pragma unroll
        for (int dg = 0; dg < 8; dg++) {
            #pragma unroll
            for (int kg = 0; kg < 2; kg++) {
                uint32_t vf0[4], vf1[4];
                LDSM_X4T(vf0[0], vf0[1], vf0[2], vf0[3], sb + VOFF0 + vb_off + kg * 16 * AST * 2 + dg * 32);
                LDSM_X4T(vf1[0], vf1[1], vf1[2], vf1[3], sb + VOFF1 + vb_off + kg * 16 * AST * 2 + dg * 32);
                #pragma unroll
                for (int ps = 0; ps < 2; ps++) {
                    uint32_t* a = pf[kg][ps];
                    MMA_BF16(oacc[2 * dg + 0], a, vf0 + 0);
                    MMA_BF16(oacc[2 * dg + 1], a, vf0 + 2);
                    MMA_BF16(oacc[2 * dg + 0], a, vf1 + 0);
                    MMA_BF16(oacc[2 * dg + 1], a, vf1 + 2);
                }
            }
        }
        __syncthreads();
    }

    for (int ww = 0; ww < 4; ww++) {
        if (w == ww) {
            #pragma unroll
            for (int t = 0; t < 16; t++) {
                int dbase = 8 * t + 2 * (lane & 3);
                num[r0 * 128 + dbase + 0] += oacc[t][0];
                num[r0 * 128 + dbase + 1] += oacc[t][1];
                num[r1 * 128 + dbase + 0] += oacc[t][2];
                num[r1 * 128 + dbase + 1] += oacc[t][3];
            }
        }
        __syncthreads();
    }
    for (int r = 0; r < 16; r += 2) {
        int rr = r + (tid >> 6);
        int e = (tid & 63) * 2;
        float dv = den[rr];
        float vx = num[rr * 128 + e] / dv;
        float vy = num[rr * 128 + e + 1] / dv;
        split_store(out0, out1, ((size_t)(b * S_ + s0 + rr)) * H_ + head * HD_ + e, vx, vy);
    }
}

// ---- host ----
static __nv_bfloat16 *s_A0, *s_A1, *s_B0, *s_B1, *s_W0, *s_W1, *s_at0, *s_at1;

static inline void cvt2(const float* A, __nv_bfloat16* d0, __nv_bfloat16* d1, int n) {
    cvt_split2_kernel<<<(n / 4 + 255) / 256, 256>>>(A, d0, d1, n);
}
static inline void run_gemm(const __nv_bfloat16* A0, const __nv_bfloat16* A1,
                            const float* W, const float* bias, const float* res,
                            float* C, __nv_bfloat16* o0, __nv_bfloat16* o1,
                            int M, int K, int N, int act, int hi) {
    cvt_t2_kernel<<<dim3(N / 32, K / 32), dim3(32, 8)>>>(W, s_W0, s_W1, K, N);
    dim3 grid(N / 256, (M + 127) / 128);
    if (hi)
        gemm_tc_kernel<4><<<grid, 512, GSMEM>>>(A0, A1, s_W0, s_W1, bias, res, C, o0, o1, M, K, N, act);
    else
        gemm_tc_kernel<3><<<grid, 512, GSMEM>>>(A0, A1, s_W0, s_W1, bias, res, C, o0, o1, M, K, N, act);
}

extern "C" void kernel_launch(void* const* d_in, const int* in_sizes, int n_in,
                              void* d_out, int out_size) {
    const int*   ids     = (const int*)  d_in[0];
    const float* tok_emb = (const float*)d_in[1];
    const float* pos_emb = (const float*)d_in[2];
    const float* in_w    = (const float*)d_in[3];
    const float* in_b    = (const float*)d_in[4];
    const float* ch_w1   = (const float*)d_in[5];
    const float* ch_b1   = (const float*)d_in[6];
    const float* ch_w2   = (const float*)d_in[7];
    const float* ch_b2   = (const float*)d_in[8];
    const float* qe_w1   = (const float*)d_in[9];
    const float* qe_b1   = (const float*)d_in[10];
    const float* qe_w2   = (const float*)d_in[11];
    const float* qe_b2   = (const float*)d_in[12];
    const float* q_w     = (const float*)d_in[13];
    const float* q_b     = (const float*)d_in[14];
    const float* k_w     = (const float*)d_in[15];
    const float* k_b     = (const float*)d_in[16];
    const float* v_w     = (const float*)d_in[17];
    const float* v_b     = (const float*)d_in[18];
    const float* o_w     = (const float*)d_in[19];
    const float* o_b     = (const float*)d_in[20];
    const float* f_w1    = (const float*)d_in[21];
    const float* f_b1    = (const float*)d_in[22];
    const float* f_w2    = (const float*)d_in[23];
    const float* f_b2    = (const float*)d_in[24];
    const float* ln1_g   = (const float*)d_in[25];
    const float* ln1_b   = (const float*)d_in[26];
    const float* ln2_g   = (const float*)d_in[27];
    const float* ln2_b   = (const float*)d_in[28];
    const float* out_w   = (const float*)d_in[29];
    const float* out_b   = (const float*)d_in[30];
    float* logits = (float*)d_out;

    cudaFuncSetAttribute(gemm_tc_kernel<4>, cudaFuncAttributeMaxDynamicSharedMemorySize, GSMEM);
    cudaFuncSetAttribute(gemm_tc_kernel<3>, cudaFuncAttributeMaxDynamicSharedMemorySize, GSMEM);
    cudaFuncSetAttribute(attn_kernel, cudaFuncAttributeMaxDynamicSharedMemorySize, ASMEM);

    float *h, *x, *avg, *cenc;
    unsigned* sel;
    cudaGetSymbolAddress((void**)&h,    g_h);
    cudaGetSymbolAddress((void**)&x,    g_x);
    cudaGetSymbolAddress((void**)&avg,  g_avg);
    cudaGetSymbolAddress((void**)&cenc, g_cenc);
    cudaGetSymbolAddress((void**)&sel,  g_sel);
    cudaGetSymbolAddress((void**)&s_A0, g_A0);
    cudaGetSymbolAddress((void**)&s_A1, g_A1);
    cudaGetSymbolAddress((void**)&s_B0, g_B0);
    cudaGetSymbolAddress((void**)&s_B1, g_B1);
    cudaGetSymbolAddress((void**)&s_W0, g_W0);
    cudaGetSymbolAddress((void**)&s_W1, g_W1);
    cudaGetSymbolAddress((void**)&s_at0, g_at0);
    cudaGetSymbolAddress((void**)&s_at1, g_at1);

    // embeddings (split) -> in-proj -> h (fp32)
    embed_kernel<<<R_, 256>>>(ids, tok_emb, pos_emb, s_A0, s_A1);
    run_gemm(s_A0, s_A1, in_w, in_b, nullptr, h, nullptr, nullptr, R_, E_, H_, 0, 1);

    // chunk encodings
    chunk_avg_kernel<<<dim3(NC_, B_), 256>>>(h, ids, avg);
    cvt2(avg, s_A0, s_A1, B_ * NC_ * H_);
    run_gemm(s_A0, s_A1, ch_w1, ch_b1, nullptr, nullptr, s_B0, s_B1, B_ * NC_, H_, HH_, 1, 1);
    run_gemm(s_B0, s_B1, ch_w2, ch_b2, nullptr, cenc, nullptr, nullptr, B_ * NC_, HH_, H_, 0, 1);

    for (int i = 0; i < L_; i++) {
        // selection path (hi precision)
        cvt2(h, s_A0, s_A1, R_ * H_);
        run_gemm(s_A0, s_A1, qe_w1, qe_b1, nullptr, nullptr, s_B0, s_B1, R_, H_, HH_, 1, 1);
        run_gemm(s_B0, s_B1, qe_w2, qe_b2, nullptr, x, nullptr, nullptr, R_, HH_, H_, 0, 1);
        topk_kernel<<<dim3(S_, B_), 512>>>(x, cenc, sel);

        int hi = (i == 0) ? 1 : 0;
        ln_kernel<<<R_, 256>>>(h, ln1_g + i * H_, ln1_b + i * H_, s_A0, s_A1);
        run_gemm(s_A0, s_A1, q_w + (size_t)i * H_ * H_, q_b + i * H_, nullptr, nullptr,
                 s_at0,               s_at1,               R_, H_, H_, 0, hi);
        run_gemm(s_A0, s_A1, k_w + (size_t)i * H_ * H_, k_b + i * H_, nullptr, nullptr,
                 s_at0 + R_ * H_,     s_at1 + R_ * H_,     R_, H_, H_, 0, hi);
        run_gemm(s_A0, s_A1, v_w + (size_t)i * H_ * H_, v_b + i * H_, nullptr, nullptr,
                 s_at0 + 2 * R_ * H_, s_at1 + 2 * R_ * H_, R_, H_, H_, 0, hi);
        attn_kernel<<<dim3(S_ / 16, NH_, B_), 128, ASMEM>>>(
            s_at0, s_at1, s_at0 + R_ * H_, s_at1 + R_ * H_,
            s_at0 + 2 * R_ * H_, s_at1 + 2 * R_ * H_, sel, s_B0, s_B1);
        run_gemm(s_B0, s_B1, o_w + (size_t)i * H_ * H_, o_b + i * H_, h, h, nullptr, nullptr,
                 R_, H_, H_, 0, hi);

        ln_kernel<<<R_, 256>>>(h, ln2_g + i * H_, ln2_b + i * H_, s_A0, s_A1);
        run_gemm(s_A0, s_A1, f_w1 + (size_t)i * H_ * FF_, f_b1 + i * FF_, nullptr, nullptr,
                 s_B0, s_B1, R_, H_, FF_, 2, hi);
        run_gemm(s_B0, s_B1, f_w2 + (size_t)i * FF_ * H_, f_b2 + i * H_, h, h, nullptr, nullptr,
                 R_, FF_, H_, 0, hi);
    }

    cvt2(h, s_A0, s_A1, R_ * H_);
    run_gemm(s_A0, s_A1, out_w, out_b, nullptr, logits, nullptr, nullptr, R_, H_, V_, 0, 0);
}

// round 11
// speedup vs baseline: 2.5554x; 1.1953x over previous
#include <cuda_runtime.h>
#include <cuda_bf16.h>
#include <math.h>
#include <stdint.h>

#define B_  2
#define S_  2048
#define E_  1024
#define H_  1024
#define NH_ 8
#define HD_ 128
#define L_  2
#define V_  32000
#define CS_ 128
#define NC_ 16
#define TOPK_ 8
#define R_  (B_ * S_)
#define FF_ (4 * H_)
#define HH_ (H_ / 2)
#define HS_ 3072
#define SCALE_ 0.08838834764831843f

// ---- scratch ----
__device__ __align__(16) float g_h  [R_ * H_];
__device__ __align__(16) float g_x  [R_ * H_];
__device__ __align__(16) float g_avg [B_ * NC_ * H_];
__device__ __align__(16) float g_cenc[B_ * NC_ * H_];
__device__ __align__(16) float g_qkvb[HS_];
__device__ unsigned g_sel[R_];
__device__ __align__(16) __nv_bfloat16 g_A0[R_ * FF_];
__device__ __align__(16) __nv_bfloat16 g_A1[R_ * FF_];
__device__ __align__(16) __nv_bfloat16 g_B0[R_ * FF_];
__device__ __align__(16) __nv_bfloat16 g_B1[R_ * FF_];
__device__ __align__(16) __nv_bfloat16 g_W0[32000 * 1024];
__device__ __align__(16) __nv_bfloat16 g_W1[32000 * 1024];
__device__ __align__(16) __nv_bfloat16 g_at0[R_ * HS_];
__device__ __align__(16) __nv_bfloat16 g_at1[R_ * HS_];

// ---- helpers ----
__device__ __forceinline__ float warpSum(float v) {
    #pragma unroll
    for (int o = 16; o > 0; o >>= 1) v += __shfl_xor_sync(0xffffffffu, v, o);
    return v;
}
__device__ __forceinline__ uint32_t smem_u32(const void* p) {
    uint32_t a;
    asm("{ .reg .u64 t; cvta.to.shared.u64 t, %1; cvt.u32.u64 %0, t; }" : "=r"(a) : "l"(p));
    return a;
}
#define CPA(d, s) asm volatile("cp.async.cg.shared.global [%0], [%1], 16;" :: "r"(d), "l"(s))
#define CPA_COMMIT() asm volatile("cp.async.commit_group;" ::: "memory")
#define CPA_WAIT0()  asm volatile("cp.async.wait_group 0;" ::: "memory")

#define LDSM_X4(r0, r1, r2, r3, a) \
    asm volatile("ldmatrix.sync.aligned.m8n8.x4.shared.b16 {%0,%1,%2,%3}, [%4];" \
        : "=r"(r0), "=r"(r1), "=r"(r2), "=r"(r3) : "r"(a))
#define LDSM_X4T(r0, r1, r2, r3, a) \
    asm volatile("ldmatrix.sync.aligned.m8n8.x4.trans.shared.b16 {%0,%1,%2,%3}, [%4];" \
        : "=r"(r0), "=r"(r1), "=r"(r2), "=r"(r3) : "r"(a))

#define MMA_BF16(c, a, b) \
    asm volatile("mma.sync.aligned.m16n8k16.row.col.f32.bf16.bf16.f32 " \
        "{%0,%1,%2,%3}, {%4,%5,%6,%7}, {%8,%9}, {%0,%1,%2,%3};" \
        : "+f"((c)[0]), "+f"((c)[1]), "+f"((c)[2]), "+f"((c)[3]) \
        : "r"((a)[0]), "r"((a)[1]), "r"((a)[2]), "r"((a)[3]), "r"((b)[0]), "r"((b)[1]))

__device__ __forceinline__ uint32_t packbf(float lo, float hi) {
    __nv_bfloat162 t = __floats2bfloat162_rn(lo, hi);
    return *(uint32_t*)&t;
}
__device__ __forceinline__ void split_store(__nv_bfloat16* o0, __nv_bfloat16* o1,
                                            size_t off, float vx, float vy) {
    float hx = __bfloat162float(__float2bfloat16_rn(vx));
    float hy = __bfloat162float(__float2bfloat16_rn(vy));
    *(uint32_t*)(o0 + off) = packbf(hx, hy);
    *(uint32_t*)(o1 + off) = packbf(vx - hx, vy - hy);
}

// ---- embedding (fused split output) ----
__global__ void embed_kernel(const int* __restrict__ ids, const float* __restrict__ tok,
                             const float* __restrict__ pos,
                             __nv_bfloat16* __restrict__ o0, __nv_bfloat16* __restrict__ o1) {
    int r = blockIdx.x;
    int id = ids[r];
    const float* t = tok + (size_t)id * E_;
    const float* p = pos + (size_t)(r % S_) * E_;
    size_t base = (size_t)r * E_;
    for (int e = threadIdx.x * 2; e < E_; e += blockDim.x * 2) {
        float vx = t[e] + p[e];
        float vy = t[e + 1] + p[e + 1];
        split_store(o0, o1, base + e, vx, vy);
    }
}

// ---- fp32 -> 2-way bf16 split ----
__global__ void cvt_split2_kernel(const float* __restrict__ a, __nv_bfloat16* __restrict__ o0,
                                  __nv_bfloat16* __restrict__ o1, int n) {
    int i = (blockIdx.x * blockDim.x + threadIdx.x) * 4;
    if (i >= n) return;
    float4 v = *(const float4*)(a + i);
    union { __nv_bfloat16 b[4]; uint2 u; } U0, U1;
    float f[4] = {v.x, v.y, v.z, v.w};
    #pragma unroll
    for (int j = 0; j < 4; j++) {
        __nv_bfloat16 b0 = __float2bfloat16_rn(f[j]);
        U0.b[j] = b0;
        U1.b[j] = __float2bfloat16_rn(f[j] - __bfloat162float(b0));
    }
    *(uint2*)(o0 + i) = U0.u;
    *(uint2*)(o1 + i) = U1.u;
}

// ---- fp32 W[K,N] -> 2-way split W^T[N,K] ----
__global__ void cvt_t2_kernel(const float* __restrict__ w, __nv_bfloat16* __restrict__ o0,
                              __nv_bfloat16* __restrict__ o1, int Kd, int Nd) {
    __shared__ float t[32][33];
    int n0 = blockIdx.x * 32, k0 = blockIdx.y * 32;
    int tx = threadIdx.x, ty = threadIdx.y;
    #pragma unroll
    for (int i = 0; i < 32; i += 8)
        t[ty + i][tx] = w[(size_t)(k0 + ty + i) * Nd + n0 + tx];
    __syncthreads();
    #pragma unroll
    for (int i = 0; i < 32; i += 8) {
        float v = t[tx][ty + i];
        __nv_bfloat16 b0 = __float2bfloat16_rn(v);
        size_t o = (size_t)(n0 + ty + i) * Kd + k0 + tx;
        o0[o] = b0;
        o1[o] = __float2bfloat16_rn(v - __bfloat162float(b0));
    }
}

// ---- HMMA split-bf16 GEMM (BK=64, 2-stage, 512 threads, warp tile 32x64) ----
#define SK 72
#define A_MAT (128 * SK * 2)
#define B_MAT (256 * SK * 2)
#define STG (2 * A_MAT + 2 * B_MAT)
#define GSMEM (2 * STG)

template<int NP>
__global__ void __launch_bounds__(512)
gemm_tc_kernel(const __nv_bfloat16* __restrict__ A0, const __nv_bfloat16* __restrict__ A1,
               const __nv_bfloat16* __restrict__ B0, const __nv_bfloat16* __restrict__ B1,
               const float* __restrict__ bias, const float* __restrict__ res,
               float* __restrict__ C, __nv_bfloat16* __restrict__ o0,
               __nv_bfloat16* __restrict__ o1, int M, int K, int N, int act) {
    extern __shared__ char smem[];
    const uint32_t sb = smem_u32(smem);
    const int tid = threadIdx.x, lane = tid & 31;
    const int w = tid >> 5, wm = w >> 2, wn = w & 3;
    const int m0 = blockIdx.y * 128, n0 = blockIdx.x * 256;

    float c[2][8][4];
    #pragma unroll
    for (int i = 0; i < 2; i++)
        #pragma unroll
        for (int j = 0; j < 8; j++)
            #pragma unroll
            for (int e = 0; e < 4; e++) c[i][j][e] = 0.f;

    const int arow = tid >> 3, aseg = tid & 7;
    int agrow_t = (m0 + arow < M) ? (m0 + arow) : (M - 1);
    const int arow2 = (tid + 512) >> 3, aseg2 = (tid + 512) & 7;
    int agrow2_t = (m0 + arow2 < M) ? (m0 + arow2) : (M - 1);

    auto issue_stage = [&](int kb, int st) {
        size_t gk = (size_t)kb * 64;
        uint32_t stb = sb + st * STG;
        {
            uint32_t d = stb + (arow * SK + aseg * 8) * 2;
            size_t o = (size_t)agrow_t * K + gk + aseg * 8;
            CPA(d, A0 + o);
            CPA(d + A_MAT, A1 + o);
            uint32_t d2 = stb + (arow2 * SK + aseg2 * 8) * 2;
            size_t o2 = (size_t)agrow2_t * K + gk + aseg2 * 8;
            CPA(d2, A0 + o2);
            CPA(d2 + A_MAT, A1 + o2);
        }
        #pragma unroll
        for (int i = 0; i < 4; i++) {
            int idx = tid + i * 512;
            int r = idx >> 3, sg = idx & 7;
            uint32_t d = stb + 2 * A_MAT + (r * SK + sg * 8) * 2;
            size_t o = (size_t)(n0 + r) * K + gk + sg * 8;
            CPA(d, B0 + o);
            CPA(d + B_MAT, B1 + o);
        }
        CPA_COMMIT();
    };

    const int nkb = K >> 6;
    issue_stage(0, 0);

    const uint32_t a_off = ((wm * 32 + (lane & 15)) * SK + ((lane >> 4) << 3)) * 2;
    const uint32_t b_off = ((wn * 64 + (lane & 7) + ((lane >> 4) << 3)) * SK + (((lane >> 3) & 1) << 3)) * 2;
    const int pa[4] = {0, 0, 1, 1};
    const int pb[4] = {0, 1, 0, 1};

    for (int kb = 0; kb < nkb; kb++) {
        CPA_WAIT0();
        __syncthreads();
        if (kb + 1 < nkb) issue_stage(kb + 1, (kb + 1) & 1);
        uint32_t base = sb + (kb & 1) * STG;
        #pragma unroll
        for (int kk = 0; kk < 4; kk++) {
            uint32_t af[2][2][4];
            #pragma unroll
            for (int s = 0; s < 2; s++)
                #pragma unroll
                for (int mt = 0; mt < 2; mt++) {
                    uint32_t ad = base + s * A_MAT + a_off + kk * 32 + mt * 16 * SK * 2;
                    LDSM_X4(af[s][mt][0], af[s][mt][1], af[s][mt][2], af[s][mt][3], ad);
                }
            uint32_t bf[2][2][4];
            #pragma unroll
            for (int s = 0; s < 2; s++) {
                uint32_t bd = base + 2 * A_MAT + s * B_MAT + b_off + kk * 32;
                LDSM_X4(bf[0][s][0], bf[0][s][1], bf[0][s][2], bf[0][s][3], bd);
            }
            #pragma unroll
            for (int nt2 = 0; nt2 < 4; nt2++) {
                int cur = nt2 & 1, nxt = cur ^ 1;
                if (nt2 < 3) {
                    #pragma unroll
                    for (int s = 0; s < 2; s++) {
                        uint32_t bd = base + 2 * A_MAT + s * B_MAT + b_off + kk * 32 + (nt2 + 1) * 16 * SK * 2;
                        LDSM_X4(bf[nxt][s][0], bf[nxt][s][1], bf[nxt][s][2], bf[nxt][s][3], bd);
                    }
                }
                #pragma unroll
                for (int p = 0; p < NP; p++)
                    #pragma unroll
                    for (int mt = 0; mt < 2; mt++)
                        #pragma unroll
                        for (int half = 0; half < 2; half++)
                            MMA_BF16(c[mt][nt2 * 2 + half], af[pa[p]][mt], bf[cur][pb[p]] + half * 2);
            }
        }
    }

    const int grp = lane >> 2, tig = lane & 3;
    #pragma unroll
    for (int mt = 0; mt < 2; mt++) {
        #pragma unroll
        for (int nt = 0; nt < 8; nt++) {
            int col = n0 + wn * 64 + nt * 8 + tig * 2;
            float b0 = bias[col], b1 = bias[col + 1];
            #pragma unroll
            for (int hrow = 0; hrow < 2; hrow++) {
                int row = m0 + wm * 32 + mt * 16 + grp + hrow * 8;
                if (row >= M) continue;
                float vx = c[mt][nt][hrow * 2 + 0] + b0;
                float vy = c[mt][nt][hrow * 2 + 1] + b1;
                if (act == 1) {
                    vx = fmaxf(vx, 0.f); vy = fmaxf(vy, 0.f);
                } else if (act == 2) {
                    vx = 0.5f * vx * (1.f + erff(vx * 0.7071067811865475f));
                    vy = 0.5f * vy * (1.f + erff(vy * 0.7071067811865475f));
                }
                size_t off = (size_t)row * N + col;
                if (o0) {
                    split_store(o0, o1, off, vx, vy);
                } else {
                    if (res) {
                        float2 r = *(const float2*)(res + off);
                        vx += r.x; vy += r.y;
                    }
                    float2 o; o.x = vx; o.y = vy;
                    *(float2*)(C + off) = o;
                }
            }
        }
    }
}

// ---- chunk mean (parallel over 4 dim groups) ----
__global__ void chunk_avg_kernel(const float* __restrict__ h, const int* __restrict__ ids,
                                 float* __restrict__ avg) {
    int c = blockIdx.x, b = blockIdx.y, dg = blockIdx.z;
    __shared__ float msk[CS_];
    __shared__ float s_cnt;
    int tid = threadIdx.x;
    if (tid < CS_) msk[tid] = (ids[b * S_ + c * CS_ + tid] != 0) ? 1.f : 0.f;
    __syncthreads();
    if (tid == 0) {
        float cn = 0.f;
        for (int p = 0; p < CS_; p++) cn += msk[p];
        s_cnt = cn;
    }
    __syncthreads();
    float inv = 1.f / (s_cnt + 1e-10f);
    int d = dg * 256 + tid;
    float s = 0.f;
    for (int p = 0; p < CS_; p++)
        s += h[(size_t)(b * S_ + c * CS_ + p) * H_ + d] * msk[p];
    avg[(size_t)(b * NC_ + c) * H_ + d] = s * inv;
}

// ---- topk ----
__global__ void __launch_bounds__(512)
topk_kernel(const float* __restrict__ qe, const float* __restrict__ cenc,
            unsigned* __restrict__ sel) {
    int s = blockIdx.x, b = blockIdx.y;
    int tid = threadIdx.x, warp = tid >> 5, lane = tid & 31;
    __shared__ float sc[NC_];
    const float* q = qe + (size_t)(b * S_ + s) * H_;
    const float* c = cenc + (size_t)(b * NC_ + warp) * H_;
    float d = 0.f;
    for (int e = lane; e < H_; e += 32) d += q[e] * c[e];
    d = warpSum(d);
    if (lane == 0) sc[warp] = d;
    __syncthreads();
    if (tid == 0) {
        unsigned chosen = 0;
        for (int t = 0; t < TOPK_; t++) {
            float best = -INFINITY;
            int bi = 0;
            for (int cc = 0; cc < NC_; cc++)
                if (!((chosen >> cc) & 1u) && sc[cc] > best) { best = sc[cc]; bi = cc; }
            chosen |= 1u << bi;
        }
        sel[b * S_ + s] = chosen;
    }
}

// ---- LayerNorm (fused split output) ----
__global__ void ln_kernel(const float* __restrict__ x, const float* __restrict__ g,
                          const float* __restrict__ bt,
                          __nv_bfloat16* __restrict__ o0, __nv_bfloat16* __restrict__ o1) {
    int r = blockIdx.x;
    int tid = threadIdx.x, warp = tid >> 5, lane = tid & 31;
    const float* xr = x + (size_t)r * H_;
    float s = 0.f, sq = 0.f;
    for (int e = tid; e < H_; e += 256) {
        float v = xr[e];
        s += v; sq += v * v;
    }
    __shared__ float rs[8], rq[8];
    __shared__ float s_mean, s_rstd;
    s = warpSum(s); sq = warpSum(sq);
    if (lane == 0) { rs[warp] = s; rq[warp] = sq; }
    __syncthreads();
    if (tid == 0) {
        float Sm = 0.f, Q = 0.f;
        for (int ww = 0; ww < 8; ww++) { Sm += rs[ww]; Q += rq[ww]; }
        float mean = Sm / (float)H_;
        float var = Q / (float)H_ - mean * mean;
        s_mean = mean;
        s_rstd = rsqrtf(var + 1e-5f);
    }
    __syncthreads();
    float mean = s_mean, rstd = s_rstd;
    size_t base = (size_t)r * H_;
    for (int e = tid * 2; e < H_; e += 512) {
        float vx = (xr[e] - mean) * rstd * g[e] + bt[e];
        float vy = (xr[e + 1] - mean) * rstd * g[e + 1] + bt[e + 1];
        split_store(o0, o1, base + e, vx, vy);
    }
}

// ---- HMMA sparse chunk attention: 32 queries/block (2x16 groups share K/V) ----
#define AST 136
#define KOFF0 0
#define KOFF1 34816
#define VOFF0 69632
#define VOFF1 104448
#define QOFF0 139264      // 2 groups x 4352
#define QOFF1 147968
#define NOFF  156672      // 32 x 128 fp32
#define DOFF  173056      // 32 fp32
#define ASMEM 173184

__global__ void __launch_bounds__(256)
attn_kernel(const __nv_bfloat16* __restrict__ qkv0, const __nv_bfloat16* __restrict__ qkv1,
            const unsigned* __restrict__ sel,
            __nv_bfloat16* __restrict__ out0, __nv_bfloat16* __restrict__ out1) {
    extern __shared__ char sm[];
    const uint32_t sb = smem_u32(sm);
    const int tid = threadIdx.x, lane = tid & 31;
    const int w = tid >> 5, gq = w >> 2, wq = w & 3;   // group (0/1), warp-in-group
    const int g_tid = tid & 127;
    const int head = blockIdx.y, b = blockIdx.z;
    const int s0 = blockIdx.x * 32;
    float* num = (float*)(sm + NOFF);
    float* den = (float*)(sm + DOFF);
    __shared__ unsigned smask[32];
    __shared__ unsigned s_union;

    for (int i = tid; i < 32 * 128; i += 256) num[i] = 0.f;
    if (tid < 32) { smask[tid] = sel[b * S_ + s0 + tid]; den[tid] = 0.f; }
    __syncthreads();
    if (tid == 0) {
        unsigned u = 0;
        for (int i = 0; i < 32; i++) u |= smask[i];
        s_union = u;
    }
    // load Q: 32 rows x 128 dims x 2 splits (q at col offset 0 of qkv)
    {
        int row = tid >> 3, sp = tid & 7;   // 16 dims per thread
        size_t src = ((size_t)(b * S_ + s0 + row)) * HS_ + head * HD_ + sp * 16;
        int gg = row >> 4, lrow = row & 15;
        uint32_t d = gg * 4352 + lrow * (AST * 2) + sp * 32;
        CPA(sb + QOFF0 + d,      qkv0 + src);
        CPA(sb + QOFF0 + d + 16, qkv0 + src + 8);
        CPA(sb + QOFF1 + d,      qkv1 + src);
        CPA(sb + QOFF1 + d + 16, qkv1 + src + 8);
    }
    CPA_COMMIT();
    CPA_WAIT0();
    __syncthreads();

    // resident Q fragments (per group's Q tile)
    uint32_t qf[2][8][4];
    const uint32_t qa = gq * 4352 + (lane & 15) * (AST * 2) + ((lane >> 4) << 4);
    #pragma unroll
    for (int s = 0; s < 2; s++)
        #pragma unroll
        for (int ks = 0; ks < 8; ks++) {
            uint32_t ad = sb + (s ? QOFF1 : QOFF0) + qa + ks * 32;
            LDSM_X4(qf[s][ks][0], qf[s][ks][1], qf[s][ks][2], qf[s][ks][3], ad);
        }

    float oacc[16][4];
    #pragma unroll
    for (int t = 0; t < 16; t++)
        #pragma unroll
        for (int e = 0; e < 4; e++) oacc[t][e] = 0.f;

    const unsigned um = s_union;
    const int r0 = lane >> 2, r1 = r0 + 8;
    const uint32_t kb_off = (wq * 32 + (lane & 7) + ((lane >> 4) << 3)) * (AST * 2) + (((lane >> 3) & 1) << 4);
    const uint32_t vb_off = (wq * 32 + (lane & 15)) * (AST * 2) + ((lane >> 4) << 4);

    for (int c = 0; c < NC_; c++) {
        if (!((um >> c) & 1u)) continue;
        int j0 = c * CS_;
        // K/V chunk load: 256 threads, 2 threads per row (64 dims each)
        {
            int row = tid >> 1, hf = tid & 1;
            size_t src = ((size_t)(b * S_ + j0 + row)) * HS_ + head * HD_ + hf * 64;
            uint32_t d = row * (AST * 2) + hf * 128;
            const __nv_bfloat16* k0p = qkv0 + 1024;
            const __nv_bfloat16* k1p = qkv1 + 1024;
            const __nv_bfloat16* v0p = qkv0 + 2048;
            const __nv_bfloat16* v1p = qkv1 + 2048;
            #pragma unroll
            for (int g = 0; g < 8; g++) {
                CPA(sb + KOFF0 + d + g * 16, k0p + src + g * 8);
                CPA(sb + KOFF1 + d + g * 16, k1p + src + g * 8);
                CPA(sb + VOFF0 + d + g * 16, v0p + src + g * 8);
                CPA(sb + VOFF1 + d + g * 16, v1p + src + g * 8);
            }
        }
        CPA_COMMIT();
        CPA_WAIT0();
        __syncthreads();

        float sc[4][4];
        #pragma unroll
        for (int t = 0; t < 4; t++)
            #pragma unroll
            for (int e = 0; e < 4; e++) sc[t][e] = 0.f;
        #pragma unroll
        for (int ks = 0; ks < 8; ks++) {
            uint32_t kfA0[4], kfA1[4], kfB0[4], kfB1[4];
            LDSM_X4(kfA0[0], kfA0[1], kfA0[2], kfA0[3], sb + KOFF0 + kb_off + ks * 32);
            LDSM_X4(kfB0[0], kfB0[1], kfB0[2], kfB0[3], sb + KOFF0 + kb_off + 16 * AST * 2 + ks * 32);
            LDSM_X4(kfA1[0], kfA1[1], kfA1[2], kfA1[3], sb + KOFF1 + kb_off + ks * 32);
            LDSM_X4(kfB1[0], kfB1[1], kfB1[2], kfB1[3], sb + KOFF1 + kb_off + 16 * AST * 2 + ks * 32);
            #pragma unroll
            for (int qs = 0; qs < 2; qs++) {
                uint32_t* a = qf[qs][ks];
                MMA_BF16(sc[0], a, kfA0 + 0); MMA_BF16(sc[1], a, kfA0 + 2);
                MMA_BF16(sc[2], a, kfB0 + 0); MMA_BF16(sc[3], a, kfB0 + 2);
                MMA_BF16(sc[0], a, kfA1 + 0); MMA_BF16(sc[1], a, kfA1 + 2);
                MMA_BF16(sc[2], a, kfB1 + 0); MMA_BF16(sc[3], a, kfB1 + 2);
            }
        }
        bool m0 = (smask[gq * 16 + r0] >> c) & 1u, m1 = (smask[gq * 16 + r1] >> c) & 1u;
        float d0 = 0.f, d1 = 0.f;
        uint32_t pf[2][2][4];
        #pragma unroll
        for (int t = 0; t < 4; t++) {
            float e0 = m0 ? expf(sc[t][0] * SCALE_) : 0.f;
            float e1 = m0 ? expf(sc[t][1] * SCALE_) : 0.f;
            float e2 = m1 ? expf(sc[t][2] * SCALE_) : 0.f;
            float e3 = m1 ? expf(sc[t][3] * SCALE_) : 0.f;
            d0 += e0 + e1; d1 += e2 + e3;
            float h0 = __bfloat162float(__float2bfloat16_rn(e0));
            float h1 = __bfloat162float(__float2bfloat16_rn(e1));
            float h2 = __bfloat162float(__float2bfloat16_rn(e2));
            float h3 = __bfloat162float(__float2bfloat16_rn(e3));
            int g = t >> 1, o = (t & 1) * 2;
            pf[g][0][o + 0] = packbf(h0, h1);
            pf[g][0][o + 1] = packbf(h2, h3);
            pf[g][1][o + 0] = packbf(e0 - h0, e1 - h1);
            pf[g][1][o + 1] = packbf(e2 - h2, e3 - h3);
        }
        d0 += __shfl_xor_sync(0xffffffffu, d0, 1);
        d0 += __shfl_xor_sync(0xffffffffu, d0, 2);
        d1 += __shfl_xor_sync(0xffffffffu, d1, 1);
        d1 += __shfl_xor_sync(0xffffffffu, d1, 2);
        if ((lane & 3) == 0) {
            atomicAdd(&den[gq * 16 + r0], d0);
            atomicAdd(&den[gq * 16 + r1], d1);
        }
        #pragma unroll
        for (int dg = 0; dg < 8; dg++) {
            #pragma unroll
            for (int kg = 0; kg < 2; kg++) {
                uint32_t vf0[4], vf1[4];
                LDSM_X4T(vf0[0], vf0[1], vf0[2], vf0[3], sb + VOFF0 + vb_off + kg * 16 * AST * 2 + dg * 32);
                LDSM_X4T(vf1[0], vf1[1], vf1[2], vf1[3], sb + VOFF1 + vb_off + kg * 16 * AST * 2 + dg * 32);
                #pragma unroll
                for (int ps = 0; ps < 2; ps++) {
                    uint32_t* a = pf[kg][ps];
                    MMA_BF16(oacc[2 * dg + 0], a, vf0 + 0);
                    MMA_BF16(oacc[2 * dg + 1], a, vf0 + 2);
                    MMA_BF16(oacc[2 * dg + 0], a, vf1 + 0);
                    MMA_BF16(oacc[2 * dg + 1], a, vf1 + 2);
                }
            }
        }
        __syncthreads();
    }

    // cross-warp reduce into num (both groups in lockstep on wq)
    for (int ww = 0; ww < 4; ww++) {
        if (wq == ww) {
            #pragma unroll
            for (int t = 0; t < 16; t++) {
                int dbase = 8 * t + 2 * (lane & 3);
                int rb = gq * 16;
                num[(rb + r0) * 128 + dbase + 0] += oacc[t][0];
                num[(rb + r0) * 128 + dbase + 1] += oacc[t][1];
                num[(rb + r1) * 128 + dbase + 0] += oacc[t][2];
                num[(rb + r1) * 128 + dbase + 1] += oacc[t][3];
            }
        }
        __syncthreads();
    }
    for (int r = 0; r < 16; r += 2) {
        int rr = r + (g_tid >> 6);
        int e = (g_tid & 63) * 2;
        int qrow = gq * 16 + rr;
        float dv = den[qrow];
        float vx = num[qrow * 128 + e] / dv;
        float vy = num[qrow * 128 + e + 1] / dv;
        split_store(out0, out1, ((size_t)(b * S_ + s0 + qrow)) * H_ + head * HD_ + e, vx, vy);
    }
}

// ---- host ----
static __nv_bfloat16 *s_A0, *s_A1, *s_B0, *s_B1, *s_W0, *s_W1, *s_at0, *s_at1;
static float* s_qkvb;

static inline void cvt2(const float* A, __nv_bfloat16* d0, __nv_bfloat16* d1, int n) {
    cvt_split2_kernel<<<(n / 4 + 255) / 256, 256>>>(A, d0, d1, n);
}
static inline void gemm_go(const __nv_bfloat16* A0, const __nv_bfloat16* A1,
                           const float* bias, const float* res,
                           float* C, __nv_bfloat16* o0, __nv_bfloat16* o1,
                           int M, int K, int N, int act, int hi) {
    dim3 grid(N / 256, (M + 127) / 128);
    if (hi)
        gemm_tc_kernel<4><<<grid, 512, GSMEM>>>(A0, A1, s_W0, s_W1, bias, res, C, o0, o1, M, K, N, act);
    else
        gemm_tc_kernel<3><<<grid, 512, GSMEM>>>(A0, A1, s_W0, s_W1, bias, res, C, o0, o1, M, K, N, act);
}
static inline void run_gemm(const __nv_bfloat16* A0, const __nv_bfloat16* A1,
                            const float* W, const float* bias, const float* res,
                            float* C, __nv_bfloat16* o0, __nv_bfloat16* o1,
                            int M, int K, int N, int act, int hi) {
    cvt_t2_kernel<<<dim3(N / 32, K / 32), dim3(32, 8)>>>(W, s_W0, s_W1, K, N);
    gemm_go(A0, A1, bias, res, C, o0, o1, M, K, N, act, hi);
}

extern "C" void kernel_launch(void* const* d_in, const int* in_sizes, int n_in,
                              void* d_out, int out_size) {
    const int*   ids     = (const int*)  d_in[0];
    const float* tok_emb = (const float*)d_in[1];
    const float* pos_emb = (const float*)d_in[2];
    const float* in_w    = (const float*)d_in[3];
    const float* in_b    = (const float*)d_in[4];
    const float* ch_w1   = (const float*)d_in[5];
    const float* ch_b1   = (const float*)d_in[6];
    const float* ch_w2   = (const float*)d_in[7];
    const float* ch_b2   = (const float*)d_in[8];
    const float* qe_w1   = (const float*)d_in[9];
    const float* qe_b1   = (const float*)d_in[10];
    const float* qe_w2   = (const float*)d_in[11];
    const float* qe_b2   = (const float*)d_in[12];
    const float* q_w     = (const float*)d_in[13];
    const float* q_b     = (const float*)d_in[14];
    const float* k_w     = (const float*)d_in[15];
    const float* k_b     = (const float*)d_in[16];
    const float* v_w     = (const float*)d_in[17];
    const float* v_b     = (const float*)d_in[18];
    const float* o_w     = (const float*)d_in[19];
    const float* o_b     = (const float*)d_in[20];
    const float* f_w1    = (const float*)d_in[21];
    const float* f_b1    = (const float*)d_in[22];
    const float* f_w2    = (const float*)d_in[23];
    const float* f_b2    = (const float*)d_in[24];
    const float* ln1_g   = (const float*)d_in[25];
    const float* ln1_b   = (const float*)d_in[26];
    const float* ln2_g   = (const float*)d_in[27];
    const float* ln2_b   = (const float*)d_in[28];
    const float* out_w   = (const float*)d_in[29];
    const float* out_b   = (const float*)d_in[30];
    float* logits = (float*)d_out;

    cudaFuncSetAttribute(gemm_tc_kernel<4>, cudaFuncAttributeMaxDynamicSharedMemorySize, GSMEM);
    cudaFuncSetAttribute(gemm_tc_kernel<3>, cudaFuncAttributeMaxDynamicSharedMemorySize, GSMEM);
    cudaFuncSetAttribute(attn_kernel, cudaFuncAttributeMaxDynamicSharedMemorySize, ASMEM);

    float *h, *x, *avg, *cenc;
    unsigned* sel;
    cudaGetSymbolAddress((void**)&h,    g_h);
    cudaGetSymbolAddress((void**)&x,    g_x);
    cudaGetSymbolAddress((void**)&avg,  g_avg);
    cudaGetSymbolAddress((void**)&cenc, g_cenc);
    cudaGetSymbolAddress((void**)&sel,  g_sel);
    cudaGetSymbolAddress((void**)&s_A0, g_A0);
    cudaGetSymbolAddress((void**)&s_A1, g_A1);
    cudaGetSymbolAddress((void**)&s_B0, g_B0);
    cudaGetSymbolAddress((void**)&s_B1, g_B1);
    cudaGetSymbolAddress((void**)&s_W0, g_W0);
    cudaGetSymbolAddress((void**)&s_W1, g_W1);
    cudaGetSymbolAddress((void**)&s_at0, g_at0);
    cudaGetSymbolAddress((void**)&s_at1, g_at1);
    cudaGetSymbolAddress((void**)&s_qkvb, g_qkvb);

    // embeddings (split) -> in-proj -> h (fp32)
    embed_kernel<<<R_, 256>>>(ids, tok_emb, pos_emb, s_A0, s_A1);
    run_gemm(s_A0, s_A1, in_w, in_b, nullptr, h, nullptr, nullptr, R_, E_, H_, 0, 1);

    // chunk encodings
    chunk_avg_kernel<<<dim3(NC_, B_, 4), 256>>>(h, ids, avg);
    cvt2(avg, s_A0, s_A1, B_ * NC_ * H_);
    run_gemm(s_A0, s_A1, ch_w1, ch_b1, nullptr, nullptr, s_B0, s_B1, B_ * NC_, H_, HH_, 1, 1);
    run_gemm(s_B0, s_B1, ch_w2, ch_b2, nullptr, cenc, nullptr, nullptr, B_ * NC_, HH_, H_, 0, 1);

    for (int i = 0; i < L_; i++) {
        // selection path (hi precision)
        cvt2(h, s_A0, s_A1, R_ * H_);
        run_gemm(s_A0, s_A1, qe_w1, qe_b1, nullptr, nullptr, s_B0, s_B1, R_, H_, HH_, 1, 1);
        run_gemm(s_B0, s_B1, qe_w2, qe_b2, nullptr, x, nullptr, nullptr, R_, HH_, H_, 0, 1);
        topk_kernel<<<dim3(S_, B_), 512>>>(x, cenc, sel);

        int hi = (i == 0) ? 1 : 0;
        ln_kernel<<<R_, 256>>>(h, ln1_g + i * H_, ln1_b + i * H_, s_A0, s_A1);
        // merged qkv: W^T rows [q | k | v], bias concatenated
        cvt_t2_kernel<<<dim3(32, 32), dim3(32, 8)>>>(q_w + (size_t)i * H_ * H_, s_W0, s_W1, H_, H_);
        cvt_t2_kernel<<<dim3(32, 32), dim3(32, 8)>>>(k_w + (size_t)i * H_ * H_,
            s_W0 + (size_t)H_ * H_, s_W1 + (size_t)H_ * H_, H_, H_);
        cvt_t2_kernel<<<dim3(32, 32), dim3(32, 8)>>>(v_w + (size_t)i * H_ * H_,
            s_W0 + (size_t)2 * H_ * H_, s_W1 + (size_t)2 * H_ * H_, H_, H_);
        cudaMemcpyAsync(s_qkvb,        q_b + i * H_, H_ * 4, cudaMemcpyDeviceToDevice);
        cudaMemcpyAsync(s_qkvb + H_,   k_b + i * H_, H_ * 4, cudaMemcpyDeviceToDevice);
        cudaMemcpyAsync(s_qkvb + 2*H_, v_b + i * H_, H_ * 4, cudaMemcpyDeviceToDevice);
        gemm_go(s_A0, s_A1, s_qkvb, nullptr, nullptr, s_at0, s_at1, R_, H_, HS_, 0, hi);

        attn_kernel<<<dim3(S_ / 32, NH_, B_), 256, ASMEM>>>(s_at0, s_at1, sel, s_B0, s_B1);
        run_gemm(s_B0, s_B1, o_w + (size_t)i * H_ * H_, o_b + i * H_, h, h, nullptr, nullptr,
                 R_, H_, H_, 0, hi);

        ln_kernel<<<R_, 256>>>(h, ln2_g + i * H_, ln2_b + i * H_, s_A0, s_A1);
        run_gemm(s_A0, s_A1, f_w1 + (size_t)i * H_ * FF_, f_b1 + i * FF_, nullptr, nullptr,
                 s_B0, s_B1, R_, H_, FF_, 2, hi);
        run_gemm(s_B0, s_B1, f_w2 + (size_t)i * FF_ * H_, f_b2 + i * H_, h, h, nullptr, nullptr,
                 R_, FF_, H_, 0, hi);
    }

    cvt2(h, s_A0, s_A1, R_ * H_);
    run_gemm(s_A0, s_A1, out_w, out_b, nullptr, logits, nullptr, nullptr, R_, H_, V_, 0, 0);
}